// round 2
// baseline (speedup 1.0000x reference)
#include <cuda_runtime.h>
#include <cuda_bf16.h>
#include <cstdint>
#include <cstddef>

// ---------------------------------------------------------------------------
// Problem constants
// ---------------------------------------------------------------------------
#define B_TOT   2048
#define SEQ_N   98
#define CH      256
#define HEADS   8
#define DH      32
#define NW      64
#define M_TOT   (B_TOT * SEQ_N)        // 200704
#define BH_TOT  (B_TOT * HEADS)        // 16384
#define HS      (SEQ_N * DH)           // 3136 floats per (b,h) per tensor
#define QKV_ONE ((size_t)BH_TOT * HS)  // 51380224
#define SCALE   0.17677669529663687f   // 1/sqrt(32)

// ---------------------------------------------------------------------------
// Device-global scratch (static: no runtime allocation allowed)
// ---------------------------------------------------------------------------
__device__ float g_qkv[3ull * QKV_ONE];           // [which][b*H+h][n][d]  ~617MB
__device__ float g_attnout[(size_t)M_TOT * CH];   // [b][n][c]             ~205MB
__device__ float g_bm[(size_t)NW * HEADS * SEQ_N * SEQ_N];  // bias+mask    ~19.7MB

// ---------------------------------------------------------------------------
// Kernel 0: precompute bias(rel-pos) + mask  ->  g_bm[wi][h][n][m]
// ---------------------------------------------------------------------------
__global__ void bm_kernel(const float* __restrict__ mask,
                          const float* __restrict__ table) {
    int i = blockIdx.x * 256 + threadIdx.x;
    const int TOT = NW * HEADS * SEQ_N * SEQ_N;   // 4917248
    if (i >= TOT) return;
    int m  = i % SEQ_N;
    int r  = i / SEQ_N;
    int n  = r % SEQ_N;  r /= SEQ_N;
    int h  = r & 7;
    int wi = r >> 3;
    // window (2,7,7): n -> (dn,hn,wn)
    int dn = n / 49, hn = (n % 49) / 7, wn = n % 7;
    int dm = m / 49, hm = (m % 49) / 7, wm = m % 7;
    int rid = (dn - dm + 1) * 169 + (hn - hm + 6) * 13 + (wn - wm + 6);
    g_bm[i] = table[rid * HEADS + h] + mask[(size_t)wi * SEQ_N * SEQ_N + n * SEQ_N + m];
}

// ---------------------------------------------------------------------------
// Tiled SGEMM, 128x128 tile, BK=16, 256 threads, 8x8 microtile
// ---------------------------------------------------------------------------
#define GBM 128
#define GBN 128
#define GBK 16
#define LDT 132   // padded smem row stride (keeps float4 alignment, kills conflicts)

// GEMM 1: qkv = X[200704,256] @ W[256,768], scattered to g_qkv layout
__global__ __launch_bounds__(256, 2)
void gemm_qkv(const float* __restrict__ X, const float* __restrict__ W) {
    __shared__ float As[GBK * LDT];
    __shared__ float Bs[GBK * LDT];
    int tid = threadIdx.x;
    int tx = tid & 15, ty = tid >> 4;
    int rowBase = blockIdx.y * GBM;
    int colBase = blockIdx.x * GBN;

    float acc[8][8];
#pragma unroll
    for (int i = 0; i < 8; i++)
#pragma unroll
        for (int j = 0; j < 8; j++) acc[i][j] = 0.f;

    int a_r  = tid >> 2;          // 0..63
    int a_k4 = (tid & 3) * 4;     // 0,4,8,12
    int b_n4 = (tid & 31) * 4;    // 0..124
    int b_k  = tid >> 5;          // 0..7

    for (int kt = 0; kt < 256; kt += GBK) {
#pragma unroll
        for (int i = 0; i < 2; i++) {
            int r = a_r + 64 * i;
            float4 v = *(const float4*)&X[(size_t)(rowBase + r) * 256 + kt + a_k4];
            As[(a_k4 + 0) * LDT + r] = v.x;
            As[(a_k4 + 1) * LDT + r] = v.y;
            As[(a_k4 + 2) * LDT + r] = v.z;
            As[(a_k4 + 3) * LDT + r] = v.w;
        }
#pragma unroll
        for (int i = 0; i < 2; i++) {
            int k = b_k + 8 * i;
            float4 v = *(const float4*)&W[(size_t)(kt + k) * 768 + colBase + b_n4];
            *(float4*)&Bs[k * LDT + b_n4] = v;
        }
        __syncthreads();
#pragma unroll
        for (int k = 0; k < GBK; k++) {
            float a[8], b[8];
            *(float4*)&a[0] = *(float4*)&As[k * LDT + ty * 8];
            *(float4*)&a[4] = *(float4*)&As[k * LDT + ty * 8 + 4];
            *(float4*)&b[0] = *(float4*)&Bs[k * LDT + tx * 8];
            *(float4*)&b[4] = *(float4*)&Bs[k * LDT + tx * 8 + 4];
#pragma unroll
            for (int i = 0; i < 8; i++)
#pragma unroll
                for (int j = 0; j < 8; j++) acc[i][j] += a[i] * b[j];
        }
        __syncthreads();
    }

    // Epilogue: scatter into g_qkv[which][b*8+h][n][d]
    int jbase = colBase + tx * 8;           // 8-aligned -> all 8 cols same which,h
    int which = jbase >> 8;
    int h     = (jbase >> 5) & 7;
    int d0    = jbase & 31;
#pragma unroll
    for (int i = 0; i < 8; i++) {
        int gm = rowBase + ty * 8 + i;
        int bb = gm / SEQ_N, n = gm % SEQ_N;
        size_t base = ((size_t)which * BH_TOT + bb * HEADS + h) * HS + (size_t)n * DH + d0;
        *(float4*)&g_qkv[base]     = make_float4(acc[i][0], acc[i][1], acc[i][2], acc[i][3]);
        *(float4*)&g_qkv[base + 4] = make_float4(acc[i][4], acc[i][5], acc[i][6], acc[i][7]);
    }
}

// GEMM 2: out = g_attnout[200704,256] @ proj_w[256,256] + proj_b
__global__ __launch_bounds__(256, 2)
void gemm_proj(const float* __restrict__ W, const float* __restrict__ bias,
               float* __restrict__ Out) {
    __shared__ float As[GBK * LDT];
    __shared__ float Bs[GBK * LDT];
    int tid = threadIdx.x;
    int tx = tid & 15, ty = tid >> 4;
    int rowBase = blockIdx.y * GBM;
    int colBase = blockIdx.x * GBN;
    const float* X = g_attnout;

    float acc[8][8];
#pragma unroll
    for (int i = 0; i < 8; i++)
#pragma unroll
        for (int j = 0; j < 8; j++) acc[i][j] = 0.f;

    int a_r  = tid >> 2;
    int a_k4 = (tid & 3) * 4;
    int b_n4 = (tid & 31) * 4;
    int b_k  = tid >> 5;

    for (int kt = 0; kt < 256; kt += GBK) {
#pragma unroll
        for (int i = 0; i < 2; i++) {
            int r = a_r + 64 * i;
            float4 v = *(const float4*)&X[(size_t)(rowBase + r) * 256 + kt + a_k4];
            As[(a_k4 + 0) * LDT + r] = v.x;
            As[(a_k4 + 1) * LDT + r] = v.y;
            As[(a_k4 + 2) * LDT + r] = v.z;
            As[(a_k4 + 3) * LDT + r] = v.w;
        }
#pragma unroll
        for (int i = 0; i < 2; i++) {
            int k = b_k + 8 * i;
            float4 v = *(const float4*)&W[(size_t)(kt + k) * 256 + colBase + b_n4];
            *(float4*)&Bs[k * LDT + b_n4] = v;
        }
        __syncthreads();
#pragma unroll
        for (int k = 0; k < GBK; k++) {
            float a[8], b[8];
            *(float4*)&a[0] = *(float4*)&As[k * LDT + ty * 8];
            *(float4*)&a[4] = *(float4*)&As[k * LDT + ty * 8 + 4];
            *(float4*)&b[0] = *(float4*)&Bs[k * LDT + tx * 8];
            *(float4*)&b[4] = *(float4*)&Bs[k * LDT + tx * 8 + 4];
#pragma unroll
            for (int i = 0; i < 8; i++)
#pragma unroll
                for (int j = 0; j < 8; j++) acc[i][j] += a[i] * b[j];
        }
        __syncthreads();
    }

    int jbase = colBase + tx * 8;
    float pb[8];
#pragma unroll
    for (int j = 0; j < 8; j++) pb[j] = bias[jbase + j];
#pragma unroll
    for (int i = 0; i < 8; i++) {
        int gm = rowBase + ty * 8 + i;
        size_t base = (size_t)gm * 256 + jbase;
        *(float4*)&Out[base]     = make_float4(acc[i][0] + pb[0], acc[i][1] + pb[1],
                                               acc[i][2] + pb[2], acc[i][3] + pb[3]);
        *(float4*)&Out[base + 4] = make_float4(acc[i][4] + pb[4], acc[i][5] + pb[5],
                                               acc[i][6] + pb[6], acc[i][7] + pb[7]);
    }
}

// ---------------------------------------------------------------------------
// Kernel: fused attention per (b,h).  S = (q*scale)k^T + bm; softmax; O = P v
// smem: sq[100][32] | skT[32][128] | sv[100][32] | sS[98][100]  = 81184 B
// ---------------------------------------------------------------------------
#define ATTN_SMEM_FLOATS (3200 + 4096 + 3200 + 9800)
#define ATTN_SMEM_BYTES  (ATTN_SMEM_FLOATS * 4)

__global__ __launch_bounds__(256, 2)
void attn_kernel() {
    extern __shared__ float sm[];
    float* sq  = sm;              // 100*32
    float* skT = sm + 3200;       // 32*128 (cols 98..127 zero)
    float* sv  = sm + 7296;       // 100*32 (rows 98,99 zero)
    float* sS  = sm + 10496;      // 98*100 (cols 98,99 zero)

    int tid  = threadIdx.x;
    int bh   = blockIdx.x;
    int b    = bh >> 3;
    int h    = bh & 7;
    size_t qoff = (size_t)bh * HS;
    const float* gq = g_qkv + qoff;
    const float* gk = g_qkv + QKV_ONE + qoff;
    const float* gv = g_qkv + 2 * QKV_ONE + qoff;

    for (int i = tid; i < HS; i += 256) sq[i] = gq[i] * SCALE;
    if (tid < 64) sq[HS + tid] = 0.f;
    for (int i = tid; i < 960; i += 256) { int d = i / 30, c = i % 30; skT[d * 128 + 98 + c] = 0.f; }
    for (int i = tid; i < HS; i += 256) { int n = i >> 5, d = i & 31; skT[d * 128 + n] = gk[i]; }
    for (int i = tid; i < HS; i += 256) sv[i] = gv[i];
    if (tid < 64) sv[HS + tid] = 0.f;
    if (tid < 196) sS[(tid >> 1) * 100 + 98 + (tid & 1)] = 0.f;
    __syncthreads();

    int warp = tid >> 5, lane = tid & 31;
    size_t bmbase = ((size_t)(b & (NW - 1)) * HEADS + h) * (SEQ_N * SEQ_N);

    // ---- S + softmax: warp handles 4 rows, lane handles m = lane+32*sl ----
    for (int g = warp; g < 25; g += 8) {
        int n0 = g * 4;
        float s[4][4];
#pragma unroll
        for (int i = 0; i < 4; i++)
#pragma unroll
            for (int sl = 0; sl < 4; sl++) s[i][sl] = 0.f;

#pragma unroll
        for (int d4 = 0; d4 < 32; d4 += 4) {
            float4 q4[4];
#pragma unroll
            for (int i = 0; i < 4; i++)
                q4[i] = *(float4*)&sq[(n0 + i) * 32 + d4];
#pragma unroll
            for (int dd = 0; dd < 4; dd++) {
                int d = d4 + dd;
                float kv0 = skT[d * 128 + lane];
                float kv1 = skT[d * 128 + lane + 32];
                float kv2 = skT[d * 128 + lane + 64];
                float kv3 = skT[d * 128 + lane + 96];
#pragma unroll
                for (int i = 0; i < 4; i++) {
                    float qv = (dd == 0) ? q4[i].x : (dd == 1) ? q4[i].y
                             : (dd == 2) ? q4[i].z : q4[i].w;
                    s[i][0] += qv * kv0;
                    s[i][1] += qv * kv1;
                    s[i][2] += qv * kv2;
                    s[i][3] += qv * kv3;
                }
            }
        }

        // bias+mask, validity, softmax
#pragma unroll
        for (int i = 0; i < 4; i++) {
            int n = n0 + i;
            bool rowok = (n < SEQ_N);
#pragma unroll
            for (int sl = 0; sl < 4; sl++) {
                int m = lane + 32 * sl;
                if (rowok && m < SEQ_N)
                    s[i][sl] += g_bm[bmbase + (size_t)n * SEQ_N + m];
                else
                    s[i][sl] = -1e30f;
            }
            float mx = fmaxf(fmaxf(s[i][0], s[i][1]), fmaxf(s[i][2], s[i][3]));
#pragma unroll
            for (int off = 16; off > 0; off >>= 1)
                mx = fmaxf(mx, __shfl_xor_sync(0xffffffffu, mx, off));
            float e0 = __expf(s[i][0] - mx);
            float e1 = __expf(s[i][1] - mx);
            float e2 = __expf(s[i][2] - mx);
            float e3 = __expf(s[i][3] - mx);
            float sum = e0 + e1 + e2 + e3;
#pragma unroll
            for (int off = 16; off > 0; off >>= 1)
                sum += __shfl_xor_sync(0xffffffffu, sum, off);
            float inv = 1.0f / sum;
            if (rowok) {
                sS[n * 100 + lane]      = e0 * inv;
                sS[n * 100 + lane + 32] = e1 * inv;
                sS[n * 100 + lane + 64] = e2 * inv;
                if (lane < 2) sS[n * 100 + lane + 96] = e3 * inv;
            }
        }
    }
    __syncthreads();

    // ---- O = P @ v : lane = d, warp handles 4 rows ----
    for (int g = warp; g < 25; g += 8) {
        int n0 = g * 4;
        float o[4] = {0.f, 0.f, 0.f, 0.f};
#pragma unroll 5
        for (int m4 = 0; m4 < 100; m4 += 4) {
            float v0 = sv[(m4 + 0) * 32 + lane];
            float v1 = sv[(m4 + 1) * 32 + lane];
            float v2 = sv[(m4 + 2) * 32 + lane];
            float v3 = sv[(m4 + 3) * 32 + lane];
#pragma unroll
            for (int i = 0; i < 4; i++) {
                int n = n0 + i;
                if (n < SEQ_N) {
                    float4 p = *(float4*)&sS[n * 100 + m4];
                    o[i] += p.x * v0 + p.y * v1 + p.z * v2 + p.w * v3;
                }
            }
        }
#pragma unroll
        for (int i = 0; i < 4; i++) {
            int n = n0 + i;
            if (n < SEQ_N)
                g_attnout[((size_t)b * SEQ_N + n) * CH + h * DH + lane] = o[i];
        }
    }
}

// ---------------------------------------------------------------------------
// Launch
// ---------------------------------------------------------------------------
extern "C" void kernel_launch(void* const* d_in, const int* in_sizes, int n_in,
                              void* d_out, int out_size) {
    const float* x       = (const float*)d_in[0];
    const float* mask    = (const float*)d_in[1];
    const float* qkv_w   = (const float*)d_in[2];
    const float* proj_w  = (const float*)d_in[3];
    const float* proj_b  = (const float*)d_in[4];
    const float* table   = (const float*)d_in[5];
    float* out           = (float*)d_out;

    static bool attr_done = false;
    if (!attr_done) {
        cudaFuncSetAttribute(attn_kernel, cudaFuncAttributeMaxDynamicSharedMemorySize,
                             ATTN_SMEM_BYTES);
        attr_done = true;
    }

    // 0) bias+mask precompute
    {
        int tot = NW * HEADS * SEQ_N * SEQ_N;
        bm_kernel<<<(tot + 255) / 256, 256>>>(mask, table);
    }
    // 1) qkv GEMM  (M=200704, N=768, K=256)
    gemm_qkv<<<dim3(768 / GBN, M_TOT / GBM), 256>>>(x, qkv_w);
    // 2) attention per (b,h)
    attn_kernel<<<BH_TOT, 256, ATTN_SMEM_BYTES>>>();
    // 3) proj GEMM + bias  (M=200704, N=256, K=256)
    gemm_proj<<<dim3(256 / GBN, M_TOT / GBM), 256>>>(proj_w, proj_b, out);
}

// round 3
// speedup vs baseline: 1.4431x; 1.4431x over previous
#include <cuda_runtime.h>
#include <cuda_bf16.h>
#include <cstdint>
#include <cstddef>

// ---------------------------------------------------------------------------
// Problem constants
// ---------------------------------------------------------------------------
#define B_TOT   2048
#define SEQ_N   98
#define CH      256
#define HEADS   8
#define DH      32
#define NW      64
#define M_TOT   (B_TOT * SEQ_N)        // 200704
#define BH_TOT  (B_TOT * HEADS)        // 16384
#define HS      (SEQ_N * DH)           // 3136 floats per (b,h) per tensor
#define QKV_ONE ((size_t)BH_TOT * HS)  // 51380224
#define SCALE   0.17677669529663687f   // 1/sqrt(32)

// ---------------------------------------------------------------------------
// Device-global scratch
// ---------------------------------------------------------------------------
__device__ float g_qkv[3ull * QKV_ONE];           // [which][b*H+h][n][d]
__device__ float g_attnout[(size_t)M_TOT * CH];   // [b][n][c]
__device__ float g_bm[(size_t)NW * HEADS * SEQ_N * SEQ_N];  // bias+mask

// ---------------------------------------------------------------------------
// Kernel 0: precompute bias(rel-pos) + mask  ->  g_bm[wi][h][n][m]
// ---------------------------------------------------------------------------
__global__ void bm_kernel(const float* __restrict__ mask,
                          const float* __restrict__ table) {
    int i = blockIdx.x * 256 + threadIdx.x;
    const int TOT = NW * HEADS * SEQ_N * SEQ_N;
    if (i >= TOT) return;
    int m  = i % SEQ_N;
    int r  = i / SEQ_N;
    int n  = r % SEQ_N;  r /= SEQ_N;
    int h  = r & 7;
    int wi = r >> 3;
    int dn = n / 49, hn = (n % 49) / 7, wn = n % 7;
    int dm = m / 49, hm = (m % 49) / 7, wm = m % 7;
    int rid = (dn - dm + 1) * 169 + (hn - hm + 6) * 13 + (wn - wm + 6);
    g_bm[i] = table[rid * HEADS + h] + mask[(size_t)wi * SEQ_N * SEQ_N + n * SEQ_N + m];
}

// ---------------------------------------------------------------------------
// tf32 helpers
// ---------------------------------------------------------------------------
__device__ __forceinline__ uint32_t f2tf(float v) {
    uint32_t r;
    asm("cvt.rna.tf32.f32 %0, %1;" : "=r"(r) : "f"(v));
    return r;
}

__device__ __forceinline__ void mma_tf32(float* c, const uint32_t* a, const uint32_t* b) {
    asm volatile(
        "mma.sync.aligned.m16n8k8.row.col.f32.tf32.tf32.f32 "
        "{%0,%1,%2,%3}, {%4,%5,%6,%7}, {%8,%9}, {%0,%1,%2,%3};\n"
        : "+f"(c[0]), "+f"(c[1]), "+f"(c[2]), "+f"(c[3])
        : "r"(a[0]), "r"(a[1]), "r"(a[2]), "r"(a[3]),
          "r"(b[0]), "r"(b[1]));
}

// ---------------------------------------------------------------------------
// tf32 tensor-core GEMM: block 128x128, BK=32, 8 warps (2x4), warp tile 64x32
// A smem [m][k] LDA=36 (conflict-free frag loads), B smem [k][n] LDB=136
// ---------------------------------------------------------------------------
#define TBK  32
#define LDA2 36
#define LDB2 136

// Mainloop producing 4x4 m16n8 accum tiles per warp. NLD = gmem row stride of B/X cols.
struct GemmCtx {
    int rowBase, colBase;
    int lane, warp, g, tg, wm, wn;
};

__device__ __forceinline__ void gemm_mainloop(
    const float* __restrict__ X, const float* __restrict__ W, int NLD,
    uint32_t* As, uint32_t* Bs, const GemmCtx& cx, float c[4][4][4]) {
    int tid = threadIdx.x;
    int ar  = tid >> 3, ac4 = (tid & 7) * 4;   // A: 32 rows/step x 8 f4 cols
    int br  = tid >> 5, bc4 = (tid & 31) * 4;  // B: 8 rows/step x 32 f4 cols

    for (int kt = 0; kt < 256; kt += TBK) {
#pragma unroll
        for (int i = 0; i < 4; i++) {
            int r = ar + 32 * i;
            float4 v = *(const float4*)&X[(size_t)(cx.rowBase + r) * 256 + kt + ac4];
            As[r * LDA2 + ac4 + 0] = f2tf(v.x);
            As[r * LDA2 + ac4 + 1] = f2tf(v.y);
            As[r * LDA2 + ac4 + 2] = f2tf(v.z);
            As[r * LDA2 + ac4 + 3] = f2tf(v.w);
        }
#pragma unroll
        for (int i = 0; i < 4; i++) {
            int r = br + 8 * i;
            float4 v = *(const float4*)&W[(size_t)(kt + r) * NLD + cx.colBase + bc4];
            Bs[r * LDB2 + bc4 + 0] = f2tf(v.x);
            Bs[r * LDB2 + bc4 + 1] = f2tf(v.y);
            Bs[r * LDB2 + bc4 + 2] = f2tf(v.z);
            Bs[r * LDB2 + bc4 + 3] = f2tf(v.w);
        }
        __syncthreads();
#pragma unroll
        for (int kk = 0; kk < TBK; kk += 8) {
            uint32_t a[4][4], b[4][2];
#pragma unroll
            for (int mi = 0; mi < 4; mi++) {
                int r0 = (cx.wm + mi * 16 + cx.g) * LDA2 + kk + cx.tg;
                a[mi][0] = As[r0];
                a[mi][1] = As[r0 + 8 * LDA2];
                a[mi][2] = As[r0 + 4];
                a[mi][3] = As[r0 + 8 * LDA2 + 4];
            }
#pragma unroll
            for (int ni = 0; ni < 4; ni++) {
                int n = cx.wn + ni * 8 + cx.g;
                b[ni][0] = Bs[(kk + cx.tg) * LDB2 + n];
                b[ni][1] = Bs[(kk + cx.tg + 4) * LDB2 + n];
            }
#pragma unroll
            for (int mi = 0; mi < 4; mi++)
#pragma unroll
                for (int ni = 0; ni < 4; ni++)
                    mma_tf32(c[mi][ni], a[mi], b[ni]);
        }
        __syncthreads();
    }
}

// GEMM 1: qkv = X[200704,256] @ W[256,768], scatter into g_qkv[which][b*8+h][n][d]
__global__ __launch_bounds__(256, 2)
void gemm_qkv_tc(const float* __restrict__ X, const float* __restrict__ W) {
    __shared__ uint32_t As[128 * LDA2];
    __shared__ uint32_t Bs[TBK * LDB2];
    int tid = threadIdx.x;
    GemmCtx cx;
    cx.lane = tid & 31; cx.warp = tid >> 5;
    cx.g = cx.lane >> 2; cx.tg = cx.lane & 3;
    cx.wm = (cx.warp >> 2) * 64; cx.wn = (cx.warp & 3) * 32;
    cx.rowBase = blockIdx.y * 128; cx.colBase = blockIdx.x * 128;

    float c[4][4][4];
#pragma unroll
    for (int mi = 0; mi < 4; mi++)
#pragma unroll
        for (int ni = 0; ni < 4; ni++)
#pragma unroll
            for (int r = 0; r < 4; r++) c[mi][ni][r] = 0.f;

    gemm_mainloop(X, W, 768, As, Bs, cx, c);

#pragma unroll
    for (int mi = 0; mi < 4; mi++) {
        int r0 = cx.rowBase + cx.wm + mi * 16 + cx.g;
        int r1 = r0 + 8;
        int b0 = r0 / SEQ_N, n0 = r0 - b0 * SEQ_N;
        int b1 = r1 / SEQ_N, n1 = r1 - b1 * SEQ_N;
#pragma unroll
        for (int ni = 0; ni < 4; ni++) {
            int col   = cx.colBase + cx.wn + ni * 8 + 2 * cx.tg;
            int which = col >> 8;
            int h     = (col >> 5) & 7;
            int d0    = col & 31;
            size_t base0 = ((size_t)which * BH_TOT + b0 * HEADS + h) * HS + (size_t)n0 * DH + d0;
            size_t base1 = ((size_t)which * BH_TOT + b1 * HEADS + h) * HS + (size_t)n1 * DH + d0;
            *(float2*)&g_qkv[base0] = make_float2(c[mi][ni][0], c[mi][ni][1]);
            *(float2*)&g_qkv[base1] = make_float2(c[mi][ni][2], c[mi][ni][3]);
        }
    }
}

// GEMM 2: out = g_attnout[200704,256] @ proj_w[256,256] + proj_b
__global__ __launch_bounds__(256, 2)
void gemm_proj_tc(const float* __restrict__ W, const float* __restrict__ bias,
                  float* __restrict__ Out) {
    __shared__ uint32_t As[128 * LDA2];
    __shared__ uint32_t Bs[TBK * LDB2];
    int tid = threadIdx.x;
    GemmCtx cx;
    cx.lane = tid & 31; cx.warp = tid >> 5;
    cx.g = cx.lane >> 2; cx.tg = cx.lane & 3;
    cx.wm = (cx.warp >> 2) * 64; cx.wn = (cx.warp & 3) * 32;
    cx.rowBase = blockIdx.y * 128; cx.colBase = blockIdx.x * 128;

    float c[4][4][4];
#pragma unroll
    for (int mi = 0; mi < 4; mi++)
#pragma unroll
        for (int ni = 0; ni < 4; ni++)
#pragma unroll
            for (int r = 0; r < 4; r++) c[mi][ni][r] = 0.f;

    gemm_mainloop(g_attnout, W, 256, As, Bs, cx, c);

#pragma unroll
    for (int mi = 0; mi < 4; mi++) {
        int r0 = cx.rowBase + cx.wm + mi * 16 + cx.g;
        int r1 = r0 + 8;
#pragma unroll
        for (int ni = 0; ni < 4; ni++) {
            int col = cx.colBase + cx.wn + ni * 8 + 2 * cx.tg;
            float bx = bias[col], by = bias[col + 1];
            *(float2*)&Out[(size_t)r0 * 256 + col] =
                make_float2(c[mi][ni][0] + bx, c[mi][ni][1] + by);
            *(float2*)&Out[(size_t)r1 * 256 + col] =
                make_float2(c[mi][ni][2] + bx, c[mi][ni][3] + by);
        }
    }
}

// ---------------------------------------------------------------------------
// Kernel: fused attention per (b,h).  S = (q*scale)k^T + bm; softmax; O = P v
// smem: sq[100][32] | skT[32][128] | sv[100][32] | sS[98][100]  = 81184 B
// ---------------------------------------------------------------------------
#define ATTN_SMEM_FLOATS (3200 + 4096 + 3200 + 9800)
#define ATTN_SMEM_BYTES  (ATTN_SMEM_FLOATS * 4)

__global__ __launch_bounds__(256, 2)
void attn_kernel() {
    extern __shared__ float sm[];
    float* sq  = sm;              // 100*32
    float* skT = sm + 3200;       // 32*128 (cols 98..127 zero)
    float* sv  = sm + 7296;       // 100*32 (rows 98,99 zero)
    float* sS  = sm + 10496;      // 98*100 (cols 98,99 zero)

    int tid  = threadIdx.x;
    int bh   = blockIdx.x;
    int b    = bh >> 3;
    int h    = bh & 7;
    size_t qoff = (size_t)bh * HS;
    const float* gq = g_qkv + qoff;
    const float* gk = g_qkv + QKV_ONE + qoff;
    const float* gv = g_qkv + 2 * QKV_ONE + qoff;

    for (int i = tid; i < HS; i += 256) sq[i] = gq[i] * SCALE;
    if (tid < 64) sq[HS + tid] = 0.f;
    for (int i = tid; i < 960; i += 256) { int d = i / 30, c = i % 30; skT[d * 128 + 98 + c] = 0.f; }
    for (int i = tid; i < HS; i += 256) { int n = i >> 5, d = i & 31; skT[d * 128 + n] = gk[i]; }
    for (int i = tid; i < HS; i += 256) sv[i] = gv[i];
    if (tid < 64) sv[HS + tid] = 0.f;
    if (tid < 196) sS[(tid >> 1) * 100 + 98 + (tid & 1)] = 0.f;
    __syncthreads();

    int warp = tid >> 5, lane = tid & 31;
    size_t bmbase = ((size_t)(b & (NW - 1)) * HEADS + h) * (SEQ_N * SEQ_N);

    for (int g = warp; g < 25; g += 8) {
        int n0 = g * 4;
        float s[4][4];
#pragma unroll
        for (int i = 0; i < 4; i++)
#pragma unroll
            for (int sl = 0; sl < 4; sl++) s[i][sl] = 0.f;

#pragma unroll
        for (int d4 = 0; d4 < 32; d4 += 4) {
            float4 q4[4];
#pragma unroll
            for (int i = 0; i < 4; i++)
                q4[i] = *(float4*)&sq[(n0 + i) * 32 + d4];
#pragma unroll
            for (int dd = 0; dd < 4; dd++) {
                int d = d4 + dd;
                float kv0 = skT[d * 128 + lane];
                float kv1 = skT[d * 128 + lane + 32];
                float kv2 = skT[d * 128 + lane + 64];
                float kv3 = skT[d * 128 + lane + 96];
#pragma unroll
                for (int i = 0; i < 4; i++) {
                    float qv = (dd == 0) ? q4[i].x : (dd == 1) ? q4[i].y
                             : (dd == 2) ? q4[i].z : q4[i].w;
                    s[i][0] += qv * kv0;
                    s[i][1] += qv * kv1;
                    s[i][2] += qv * kv2;
                    s[i][3] += qv * kv3;
                }
            }
        }

#pragma unroll
        for (int i = 0; i < 4; i++) {
            int n = n0 + i;
            bool rowok = (n < SEQ_N);
#pragma unroll
            for (int sl = 0; sl < 4; sl++) {
                int m = lane + 32 * sl;
                if (rowok && m < SEQ_N)
                    s[i][sl] += g_bm[bmbase + (size_t)n * SEQ_N + m];
                else
                    s[i][sl] = -1e30f;
            }
            float mx = fmaxf(fmaxf(s[i][0], s[i][1]), fmaxf(s[i][2], s[i][3]));
#pragma unroll
            for (int off = 16; off > 0; off >>= 1)
                mx = fmaxf(mx, __shfl_xor_sync(0xffffffffu, mx, off));
            float e0 = __expf(s[i][0] - mx);
            float e1 = __expf(s[i][1] - mx);
            float e2 = __expf(s[i][2] - mx);
            float e3 = __expf(s[i][3] - mx);
            float sum = e0 + e1 + e2 + e3;
#pragma unroll
            for (int off = 16; off > 0; off >>= 1)
                sum += __shfl_xor_sync(0xffffffffu, sum, off);
            float inv = 1.0f / sum;
            if (rowok) {
                sS[n * 100 + lane]      = e0 * inv;
                sS[n * 100 + lane + 32] = e1 * inv;
                sS[n * 100 + lane + 64] = e2 * inv;
                if (lane < 2) sS[n * 100 + lane + 96] = e3 * inv;
            }
        }
    }
    __syncthreads();

    for (int g = warp; g < 25; g += 8) {
        int n0 = g * 4;
        float o[4] = {0.f, 0.f, 0.f, 0.f};
#pragma unroll 5
        for (int m4 = 0; m4 < 100; m4 += 4) {
            float v0 = sv[(m4 + 0) * 32 + lane];
            float v1 = sv[(m4 + 1) * 32 + lane];
            float v2 = sv[(m4 + 2) * 32 + lane];
            float v3 = sv[(m4 + 3) * 32 + lane];
#pragma unroll
            for (int i = 0; i < 4; i++) {
                int n = n0 + i;
                if (n < SEQ_N) {
                    float4 p = *(float4*)&sS[n * 100 + m4];
                    o[i] += p.x * v0 + p.y * v1 + p.z * v2 + p.w * v3;
                }
            }
        }
#pragma unroll
        for (int i = 0; i < 4; i++) {
            int n = n0 + i;
            if (n < SEQ_N)
                g_attnout[((size_t)b * SEQ_N + n) * CH + h * DH + lane] = o[i];
        }
    }
}

// ---------------------------------------------------------------------------
// Launch
// ---------------------------------------------------------------------------
extern "C" void kernel_launch(void* const* d_in, const int* in_sizes, int n_in,
                              void* d_out, int out_size) {
    const float* x       = (const float*)d_in[0];
    const float* mask    = (const float*)d_in[1];
    const float* qkv_w   = (const float*)d_in[2];
    const float* proj_w  = (const float*)d_in[3];
    const float* proj_b  = (const float*)d_in[4];
    const float* table   = (const float*)d_in[5];
    float* out           = (float*)d_out;

    static bool attr_done = false;
    if (!attr_done) {
        cudaFuncSetAttribute(attn_kernel, cudaFuncAttributeMaxDynamicSharedMemorySize,
                             ATTN_SMEM_BYTES);
        attr_done = true;
    }

    // 0) bias+mask precompute
    {
        int tot = NW * HEADS * SEQ_N * SEQ_N;
        bm_kernel<<<(tot + 255) / 256, 256>>>(mask, table);
    }
    // 1) qkv GEMM  (M=200704, N=768, K=256)  -- tf32 tensor cores
    gemm_qkv_tc<<<dim3(768 / 128, M_TOT / 128), 256>>>(x, qkv_w);
    // 2) attention per (b,h)
    attn_kernel<<<BH_TOT, 256, ATTN_SMEM_BYTES>>>();
    // 3) proj GEMM + bias  (M=200704, N=256, K=256)  -- tf32 tensor cores
    gemm_proj_tc<<<dim3(256 / 128, M_TOT / 128), 256>>>(proj_w, proj_b, out);
}

// round 4
// speedup vs baseline: 2.0025x; 1.3876x over previous
#include <cuda_runtime.h>
#include <cuda_bf16.h>
#include <cstdint>
#include <cstddef>

// ---------------------------------------------------------------------------
// Problem constants
// ---------------------------------------------------------------------------
#define B_TOT   2048
#define SEQ_N   98
#define CH      256
#define HEADS   8
#define DH      32
#define NW      64
#define M_TOT   (B_TOT * SEQ_N)        // 200704
#define BH_TOT  (B_TOT * HEADS)        // 16384
#define HS      (SEQ_N * DH)           // 3136 floats per (b,h) per tensor
#define QKV_ONE ((size_t)BH_TOT * HS)  // 51380224
#define SCALE   0.17677669529663687f   // 1/sqrt(32)

// ---------------------------------------------------------------------------
// Device-global scratch
// ---------------------------------------------------------------------------
__device__ float g_qkv[3ull * QKV_ONE];           // [which][b*H+h][n][d]
__device__ float g_attnout[(size_t)M_TOT * CH];   // [b][n][c]
__device__ float g_bm[(size_t)NW * HEADS * SEQ_N * SEQ_N];  // bias+mask

// ---------------------------------------------------------------------------
// Kernel 0: precompute bias(rel-pos) + mask  ->  g_bm[wi][h][n][m]
// ---------------------------------------------------------------------------
__global__ void bm_kernel(const float* __restrict__ mask,
                          const float* __restrict__ table) {
    int i = blockIdx.x * 256 + threadIdx.x;
    const int TOT = NW * HEADS * SEQ_N * SEQ_N;
    if (i >= TOT) return;
    int m  = i % SEQ_N;
    int r  = i / SEQ_N;
    int n  = r % SEQ_N;  r /= SEQ_N;
    int h  = r & 7;
    int wi = r >> 3;
    int dn = n / 49, hn = (n % 49) / 7, wn = n % 7;
    int dm = m / 49, hm = (m % 49) / 7, wm = m % 7;
    int rid = (dn - dm + 1) * 169 + (hn - hm + 6) * 13 + (wn - wm + 6);
    g_bm[i] = table[rid * HEADS + h] + mask[(size_t)wi * SEQ_N * SEQ_N + n * SEQ_N + m];
}

// ---------------------------------------------------------------------------
// tf32 helpers
// ---------------------------------------------------------------------------
__device__ __forceinline__ uint32_t f2tf(float v) {
    uint32_t r;
    asm("cvt.rna.tf32.f32 %0, %1;" : "=r"(r) : "f"(v));
    return r;
}

__device__ __forceinline__ void mma_tf32(float* c, const uint32_t* a, const uint32_t* b) {
    asm volatile(
        "mma.sync.aligned.m16n8k8.row.col.f32.tf32.tf32.f32 "
        "{%0,%1,%2,%3}, {%4,%5,%6,%7}, {%8,%9}, {%0,%1,%2,%3};\n"
        : "+f"(c[0]), "+f"(c[1]), "+f"(c[2]), "+f"(c[3])
        : "r"(a[0]), "r"(a[1]), "r"(a[2]), "r"(a[3]),
          "r"(b[0]), "r"(b[1]));
}

// fast exp on FMA pipe: exp(s) = 2^(s*log2e), magic-number split + deg-5 poly
__device__ __forceinline__ float fastexp(float s) {
    float t  = s * 1.4426950408889634f;
    float fr = t + 12582912.0f;            // 1.5 * 2^23
    float rn = fr - 12582912.0f;
    float f  = t - rn;
    float p  = 1.3333558146428443e-3f;
    p = fmaf(p, f, 9.618129107628477e-3f);
    p = fmaf(p, f, 5.550410866482158e-2f);
    p = fmaf(p, f, 2.402265069591007e-1f);
    p = fmaf(p, f, 6.931471805599453e-1f);
    p = fmaf(p, f, 1.0f);
    int ei = (int)((unsigned)__float_as_int(fr) << 23);
    return __int_as_float(__float_as_int(p) + ei);
}

// ---------------------------------------------------------------------------
// tf32 tensor-core GEMM: block 128x128, BK=32, 8 warps (2x4), warp tile 64x32
// ---------------------------------------------------------------------------
#define TBK  32
#define LDA2 36
#define LDB2 136

struct GemmCtx {
    int rowBase, colBase;
    int lane, warp, g, tg, wm, wn;
};

__device__ __forceinline__ void gemm_mainloop(
    const float* __restrict__ X, const float* __restrict__ W, int NLD,
    uint32_t* As, uint32_t* Bs, const GemmCtx& cx, float c[4][4][4]) {
    int tid = threadIdx.x;
    int ar  = tid >> 3, ac4 = (tid & 7) * 4;
    int br  = tid >> 5, bc4 = (tid & 31) * 4;

    for (int kt = 0; kt < 256; kt += TBK) {
#pragma unroll
        for (int i = 0; i < 4; i++) {
            int r = ar + 32 * i;
            float4 v = *(const float4*)&X[(size_t)(cx.rowBase + r) * 256 + kt + ac4];
            As[r * LDA2 + ac4 + 0] = f2tf(v.x);
            As[r * LDA2 + ac4 + 1] = f2tf(v.y);
            As[r * LDA2 + ac4 + 2] = f2tf(v.z);
            As[r * LDA2 + ac4 + 3] = f2tf(v.w);
        }
#pragma unroll
        for (int i = 0; i < 4; i++) {
            int r = br + 8 * i;
            float4 v = *(const float4*)&W[(size_t)(kt + r) * NLD + cx.colBase + bc4];
            Bs[r * LDB2 + bc4 + 0] = f2tf(v.x);
            Bs[r * LDB2 + bc4 + 1] = f2tf(v.y);
            Bs[r * LDB2 + bc4 + 2] = f2tf(v.z);
            Bs[r * LDB2 + bc4 + 3] = f2tf(v.w);
        }
        __syncthreads();
#pragma unroll
        for (int kk = 0; kk < TBK; kk += 8) {
            uint32_t a[4][4], b[4][2];
#pragma unroll
            for (int mi = 0; mi < 4; mi++) {
                int r0 = (cx.wm + mi * 16 + cx.g) * LDA2 + kk + cx.tg;
                a[mi][0] = As[r0];
                a[mi][1] = As[r0 + 8 * LDA2];
                a[mi][2] = As[r0 + 4];
                a[mi][3] = As[r0 + 8 * LDA2 + 4];
            }
#pragma unroll
            for (int ni = 0; ni < 4; ni++) {
                int n = cx.wn + ni * 8 + cx.g;
                b[ni][0] = Bs[(kk + cx.tg) * LDB2 + n];
                b[ni][1] = Bs[(kk + cx.tg + 4) * LDB2 + n];
            }
#pragma unroll
            for (int mi = 0; mi < 4; mi++)
#pragma unroll
                for (int ni = 0; ni < 4; ni++)
                    mma_tf32(c[mi][ni], a[mi], b[ni]);
        }
        __syncthreads();
    }
}

// GEMM 1: qkv = X @ W[256,768], scatter into g_qkv[which][b*8+h][n][d]
__global__ __launch_bounds__(256, 2)
void gemm_qkv_tc(const float* __restrict__ X, const float* __restrict__ W) {
    __shared__ uint32_t As[128 * LDA2];
    __shared__ uint32_t Bs[TBK * LDB2];
    int tid = threadIdx.x;
    GemmCtx cx;
    cx.lane = tid & 31; cx.warp = tid >> 5;
    cx.g = cx.lane >> 2; cx.tg = cx.lane & 3;
    cx.wm = (cx.warp >> 2) * 64; cx.wn = (cx.warp & 3) * 32;
    cx.rowBase = blockIdx.y * 128; cx.colBase = blockIdx.x * 128;

    float c[4][4][4];
#pragma unroll
    for (int mi = 0; mi < 4; mi++)
#pragma unroll
        for (int ni = 0; ni < 4; ni++)
#pragma unroll
            for (int r = 0; r < 4; r++) c[mi][ni][r] = 0.f;

    gemm_mainloop(X, W, 768, As, Bs, cx, c);

#pragma unroll
    for (int mi = 0; mi < 4; mi++) {
        int r0 = cx.rowBase + cx.wm + mi * 16 + cx.g;
        int r1 = r0 + 8;
        int b0 = r0 / SEQ_N, n0 = r0 - b0 * SEQ_N;
        int b1 = r1 / SEQ_N, n1 = r1 - b1 * SEQ_N;
#pragma unroll
        for (int ni = 0; ni < 4; ni++) {
            int col   = cx.colBase + cx.wn + ni * 8 + 2 * cx.tg;
            int which = col >> 8;
            int h     = (col >> 5) & 7;
            int d0    = col & 31;
            size_t base0 = ((size_t)which * BH_TOT + b0 * HEADS + h) * HS + (size_t)n0 * DH + d0;
            size_t base1 = ((size_t)which * BH_TOT + b1 * HEADS + h) * HS + (size_t)n1 * DH + d0;
            *(float2*)&g_qkv[base0] = make_float2(c[mi][ni][0], c[mi][ni][1]);
            *(float2*)&g_qkv[base1] = make_float2(c[mi][ni][2], c[mi][ni][3]);
        }
    }
}

// GEMM 2: out = g_attnout @ proj_w[256,256] + proj_b
__global__ __launch_bounds__(256, 2)
void gemm_proj_tc(const float* __restrict__ W, const float* __restrict__ bias,
                  float* __restrict__ Out) {
    __shared__ uint32_t As[128 * LDA2];
    __shared__ uint32_t Bs[TBK * LDB2];
    int tid = threadIdx.x;
    GemmCtx cx;
    cx.lane = tid & 31; cx.warp = tid >> 5;
    cx.g = cx.lane >> 2; cx.tg = cx.lane & 3;
    cx.wm = (cx.warp >> 2) * 64; cx.wn = (cx.warp & 3) * 32;
    cx.rowBase = blockIdx.y * 128; cx.colBase = blockIdx.x * 128;

    float c[4][4][4];
#pragma unroll
    for (int mi = 0; mi < 4; mi++)
#pragma unroll
        for (int ni = 0; ni < 4; ni++)
#pragma unroll
            for (int r = 0; r < 4; r++) c[mi][ni][r] = 0.f;

    gemm_mainloop(g_attnout, W, 256, As, Bs, cx, c);

#pragma unroll
    for (int mi = 0; mi < 4; mi++) {
        int r0 = cx.rowBase + cx.wm + mi * 16 + cx.g;
        int r1 = r0 + 8;
#pragma unroll
        for (int ni = 0; ni < 4; ni++) {
            int col = cx.colBase + cx.wn + ni * 8 + 2 * cx.tg;
            float bx = bias[col], by = bias[col + 1];
            *(float2*)&Out[(size_t)r0 * 256 + col] =
                make_float2(c[mi][ni][0] + bx, c[mi][ni][1] + by);
            *(float2*)&Out[(size_t)r1 * 256 + col] =
                make_float2(c[mi][ni][2] + bx, c[mi][ni][3] + by);
        }
    }
}

// ---------------------------------------------------------------------------
// Attention on tensor cores. One block per (b,h). 8 warps, 16-row band each.
//   S[128x112] = q[128x32] . k^T   (tf32 mma, rows/cols >=98 zero-padded)
//   P = exp(S + bias + mask)   (FMA-pipe fastexp; no max-subtract; tf32 in smem)
//   O[128x32] = P . v          (tf32 mma), scaled by 1/rowsum at store
// smem (uint32): q[128*36] k[112*36] vT[32*116] P[128*116] inv[128] = 109312 B
// ---------------------------------------------------------------------------
#define LDQ 36
#define LDK 36
#define LDV 116
#define LDP 116
#define OFF_K   (128 * LDQ)                 // 4608
#define OFF_V   (OFF_K + 112 * LDK)         // 8640
#define OFF_P   (OFF_V + 32 * LDV)          // 12352
#define OFF_INV (OFF_P + 128 * LDP)         // 27200
#define ATTN_SMEM_BYTES ((OFF_INV + 128) * 4)   // 109312

__global__ __launch_bounds__(256, 2)
void attn_tc() {
    extern __shared__ uint32_t sm[];
    uint32_t* sq  = sm;
    uint32_t* sk  = sm + OFF_K;
    uint32_t* sv  = sm + OFF_V;
    uint32_t* sP  = sm + OFF_P;
    float*    sInv = (float*)(sm + OFF_INV);

    int tid = threadIdx.x;
    int bh  = blockIdx.x;
    int b   = bh >> 3, h = bh & 7;
    const float* gq = g_qkv + (size_t)bh * HS;
    const float* gk = gq + QKV_ONE;
    const float* gv = gq + 2 * QKV_ONE;

    // ---- load tiles (tf32 in smem) ----
    for (int i = tid; i < 128 * 32; i += 256) {
        int n = i >> 5, d = i & 31;
        float v = (n < SEQ_N) ? gq[n * 32 + d] * SCALE : 0.f;
        sq[n * LDQ + d] = f2tf(v);
    }
    for (int i = tid; i < 112 * 32; i += 256) {
        int n = i >> 5, d = i & 31;
        float v = (n < SEQ_N) ? gk[n * 32 + d] : 0.f;
        sk[n * LDK + d] = f2tf(v);
    }
    for (int i = tid; i < HS; i += 256) {          // vT[d][m]
        int m = i >> 5, d = i & 31;
        sv[d * LDV + m] = f2tf(gv[i]);
    }
    for (int i = tid; i < 32 * 14; i += 256) {     // zero vT cols 98..111
        int d = i / 14, m = SEQ_N + i % 14;
        sv[d * LDV + m] = 0u;
    }
    __syncthreads();

    int lane = tid & 31, warp = tid >> 5;
    int g = lane >> 2, tg = lane & 3;
    int r0 = warp * 16 + g, r1 = r0 + 8;
    bool rv0 = (r0 < SEQ_N), rv1 = (r1 < SEQ_N);
    size_t bmbase = ((size_t)(b & (NW - 1)) * HEADS + h) * (SEQ_N * SEQ_N);

    // ---- S phase: A fragments (q rows of this warp) held in registers ----
    uint32_t aF[4][4];
#pragma unroll
    for (int kk = 0; kk < 4; kk++) {
        int base = r0 * LDQ + kk * 8 + tg;
        aF[kk][0] = sq[base];
        aF[kk][1] = sq[base + 8 * LDQ];
        aF[kk][2] = sq[base + 4];
        aF[kk][3] = sq[base + 8 * LDQ + 4];
    }

    float sum0 = 0.f, sum1 = 0.f;
#pragma unroll
    for (int ni = 0; ni < 14; ni++) {
        float acc[4] = {0.f, 0.f, 0.f, 0.f};
#pragma unroll
        for (int kk = 0; kk < 4; kk++) {
            uint32_t bF[2];
            int nr = ni * 8 + g;
            bF[0] = sk[nr * LDK + kk * 8 + tg];
            bF[1] = sk[nr * LDK + kk * 8 + tg + 4];
            mma_tf32(acc, aF[kk], bF);
        }
        // epilogue: + bias+mask, exp, tf32 -> P, rowsum
        int c0 = ni * 8 + 2 * tg;
        bool cv = (c0 < SEQ_N);        // c0 even, so c0<98 implies c0+1<=97 valid
        float e00 = 0.f, e01 = 0.f, e10 = 0.f, e11 = 0.f;
        if (cv && rv0) {
            float2 bm0 = *(const float2*)&g_bm[bmbase + (size_t)r0 * SEQ_N + c0];
            e00 = fastexp(acc[0] + bm0.x);
            e01 = fastexp(acc[1] + bm0.y);
        }
        if (cv && rv1) {
            float2 bm1 = *(const float2*)&g_bm[bmbase + (size_t)r1 * SEQ_N + c0];
            e10 = fastexp(acc[2] + bm1.x);
            e11 = fastexp(acc[3] + bm1.y);
        }
        uint32_t u00 = f2tf(e00), u01 = f2tf(e01);
        uint32_t u10 = f2tf(e10), u11 = f2tf(e11);
        sum0 += __uint_as_float(u00) + __uint_as_float(u01);
        sum1 += __uint_as_float(u10) + __uint_as_float(u11);
        *(uint2*)&sP[r0 * LDP + c0] = make_uint2(u00, u01);
        *(uint2*)&sP[r1 * LDP + c0] = make_uint2(u10, u11);
    }
    // rowsum across the 4-lane quad
    sum0 += __shfl_xor_sync(0xffffffffu, sum0, 1);
    sum0 += __shfl_xor_sync(0xffffffffu, sum0, 2);
    sum1 += __shfl_xor_sync(0xffffffffu, sum1, 1);
    sum1 += __shfl_xor_sync(0xffffffffu, sum1, 2);
    if (tg == 0) {
        sInv[r0] = rv0 ? (1.0f / sum0) : 0.f;
        sInv[r1] = rv1 ? (1.0f / sum1) : 0.f;
    }
    __syncthreads();

    // ---- O phase: O = P . v (A from sP, B from vT), scale by invsum ----
    float oacc[4][4];
#pragma unroll
    for (int ni = 0; ni < 4; ni++)
#pragma unroll
        for (int r = 0; r < 4; r++) oacc[ni][r] = 0.f;

#pragma unroll
    for (int kk = 0; kk < 14; kk++) {
        uint32_t aO[4];
        int base = r0 * LDP + kk * 8 + tg;
        aO[0] = sP[base];
        aO[1] = sP[base + 8 * LDP];
        aO[2] = sP[base + 4];
        aO[3] = sP[base + 8 * LDP + 4];
#pragma unroll
        for (int ni = 0; ni < 4; ni++) {
            uint32_t bO[2];
            int vr = ni * 8 + g;
            bO[0] = sv[vr * LDV + kk * 8 + tg];
            bO[1] = sv[vr * LDV + kk * 8 + tg + 4];
            mma_tf32(oacc[ni], aO, bO);
        }
    }

    if (rv0) {
        float inv0 = sInv[r0];
        size_t ob = ((size_t)b * SEQ_N + r0) * CH + h * DH;
#pragma unroll
        for (int ni = 0; ni < 4; ni++) {
            int d0 = ni * 8 + 2 * tg;
            *(float2*)&g_attnout[ob + d0] =
                make_float2(oacc[ni][0] * inv0, oacc[ni][1] * inv0);
        }
    }
    if (rv1) {
        float inv1 = sInv[r1];
        size_t ob = ((size_t)b * SEQ_N + r1) * CH + h * DH;
#pragma unroll
        for (int ni = 0; ni < 4; ni++) {
            int d0 = ni * 8 + 2 * tg;
            *(float2*)&g_attnout[ob + d0] =
                make_float2(oacc[ni][2] * inv1, oacc[ni][3] * inv1);
        }
    }
}

// ---------------------------------------------------------------------------
// Launch
// ---------------------------------------------------------------------------
extern "C" void kernel_launch(void* const* d_in, const int* in_sizes, int n_in,
                              void* d_out, int out_size) {
    const float* x       = (const float*)d_in[0];
    const float* mask    = (const float*)d_in[1];
    const float* qkv_w   = (const float*)d_in[2];
    const float* proj_w  = (const float*)d_in[3];
    const float* proj_b  = (const float*)d_in[4];
    const float* table   = (const float*)d_in[5];
    float* out           = (float*)d_out;

    static bool attr_done = false;
    if (!attr_done) {
        cudaFuncSetAttribute(attn_tc, cudaFuncAttributeMaxDynamicSharedMemorySize,
                             ATTN_SMEM_BYTES);
        attr_done = true;
    }

    // 0) bias+mask precompute
    {
        int tot = NW * HEADS * SEQ_N * SEQ_N;
        bm_kernel<<<(tot + 255) / 256, 256>>>(mask, table);
    }
    // 1) qkv GEMM (tf32 tensor cores)
    gemm_qkv_tc<<<dim3(768 / 128, M_TOT / 128), 256>>>(x, qkv_w);
    // 2) attention per (b,h) (tf32 tensor cores + fast exp)
    attn_tc<<<BH_TOT, 256, ATTN_SMEM_BYTES>>>();
    // 3) proj GEMM + bias (tf32 tensor cores)
    gemm_proj_tc<<<dim3(256 / 128, M_TOT / 128), 256>>>(proj_w, proj_b, out);
}

// round 6
// speedup vs baseline: 2.9528x; 1.4746x over previous
#include <cuda_runtime.h>
#include <cuda_bf16.h>
#include <cstdint>
#include <cstddef>

// ---------------------------------------------------------------------------
// Problem constants
// ---------------------------------------------------------------------------
#define B_TOT   2048
#define SEQ_N   98
#define CH      256
#define HEADS   8
#define DH      32
#define NW      64
#define M_TOT   (B_TOT * SEQ_N)        // 200704
#define BH_TOT  (B_TOT * HEADS)        // 16384
#define HS      (SEQ_N * DH)           // 3136 floats per (b,h) per tensor
#define QKV_ONE ((size_t)BH_TOT * HS)  // 51380224
#define SCALE   0.17677669529663687f   // 1/sqrt(32)

// ---------------------------------------------------------------------------
// Device-global scratch
// ---------------------------------------------------------------------------
__device__ float g_qkv[3ull * QKV_ONE];           // [which][b*H+h][n][d]
__device__ float g_attnout[(size_t)M_TOT * CH];   // [b][n][c]
__device__ float g_bm[(size_t)NW * HEADS * SEQ_N * SEQ_N];  // bias+mask

// ---------------------------------------------------------------------------
// Kernel 0: precompute bias(rel-pos) + mask  ->  g_bm[wi][h][n][m]
// ---------------------------------------------------------------------------
__global__ void bm_kernel(const float* __restrict__ mask,
                          const float* __restrict__ table) {
    int i = blockIdx.x * 256 + threadIdx.x;
    const int TOT = NW * HEADS * SEQ_N * SEQ_N;
    if (i >= TOT) return;
    int m  = i % SEQ_N;
    int r  = i / SEQ_N;
    int n  = r % SEQ_N;  r /= SEQ_N;
    int h  = r & 7;
    int wi = r >> 3;
    int dn = n / 49, hn = (n % 49) / 7, wn = n % 7;
    int dm = m / 49, hm = (m % 49) / 7, wm = m % 7;
    int rid = (dn - dm + 1) * 169 + (hn - hm + 6) * 13 + (wn - wm + 6);
    g_bm[i] = table[rid * HEADS + h] + mask[(size_t)wi * SEQ_N * SEQ_N + n * SEQ_N + m];
}

// ---------------------------------------------------------------------------
// tf32 helpers
// ---------------------------------------------------------------------------
__device__ __forceinline__ uint32_t f2tf(float v) {
    uint32_t r;
    asm("cvt.rna.tf32.f32 %0, %1;" : "=r"(r) : "f"(v));
    return r;
}

__device__ __forceinline__ void mma_tf32(float* c, const uint32_t* a, const uint32_t* b) {
    asm volatile(
        "mma.sync.aligned.m16n8k8.row.col.f32.tf32.tf32.f32 "
        "{%0,%1,%2,%3}, {%4,%5,%6,%7}, {%8,%9}, {%0,%1,%2,%3};\n"
        : "+f"(c[0]), "+f"(c[1]), "+f"(c[2]), "+f"(c[3])
        : "r"(a[0]), "r"(a[1]), "r"(a[2]), "r"(a[3]),
          "r"(b[0]), "r"(b[1]));
}

// fast exp on FMA pipe
__device__ __forceinline__ float fastexp(float s) {
    float t  = s * 1.4426950408889634f;
    float fr = t + 12582912.0f;            // 1.5 * 2^23
    float rn = fr - 12582912.0f;
    float f  = t - rn;
    float p  = 1.3333558146428443e-3f;
    p = fmaf(p, f, 9.618129107628477e-3f);
    p = fmaf(p, f, 5.550410866482158e-2f);
    p = fmaf(p, f, 2.402265069591007e-1f);
    p = fmaf(p, f, 6.931471805599453e-1f);
    p = fmaf(p, f, 1.0f);
    int ei = (int)((unsigned)__float_as_int(fr) << 23);
    return __int_as_float(__float_as_int(p) + ei);
}

// ---------------------------------------------------------------------------
// tf32 tensor-core GEMM: block 128x128, BK=32, 8 warps (2x4), warp tile 64x32
// ---------------------------------------------------------------------------
#define TBK  32
#define LDA2 36
#define LDB2 136

struct GemmCtx {
    int rowBase, colBase;
    int lane, warp, g, tg, wm, wn;
};

__device__ __forceinline__ void gemm_mainloop(
    const float* __restrict__ X, const float* __restrict__ W, int NLD,
    uint32_t* As, uint32_t* Bs, const GemmCtx& cx, float c[4][4][4]) {
    int tid = threadIdx.x;
    int ar  = tid >> 3, ac4 = (tid & 7) * 4;
    int br  = tid >> 5, bc4 = (tid & 31) * 4;

    for (int kt = 0; kt < 256; kt += TBK) {
#pragma unroll
        for (int i = 0; i < 4; i++) {
            int r = ar + 32 * i;
            float4 v = *(const float4*)&X[(size_t)(cx.rowBase + r) * 256 + kt + ac4];
            As[r * LDA2 + ac4 + 0] = f2tf(v.x);
            As[r * LDA2 + ac4 + 1] = f2tf(v.y);
            As[r * LDA2 + ac4 + 2] = f2tf(v.z);
            As[r * LDA2 + ac4 + 3] = f2tf(v.w);
        }
#pragma unroll
        for (int i = 0; i < 4; i++) {
            int r = br + 8 * i;
            float4 v = *(const float4*)&W[(size_t)(kt + r) * NLD + cx.colBase + bc4];
            Bs[r * LDB2 + bc4 + 0] = f2tf(v.x);
            Bs[r * LDB2 + bc4 + 1] = f2tf(v.y);
            Bs[r * LDB2 + bc4 + 2] = f2tf(v.z);
            Bs[r * LDB2 + bc4 + 3] = f2tf(v.w);
        }
        __syncthreads();
#pragma unroll
        for (int kk = 0; kk < TBK; kk += 8) {
            uint32_t a[4][4], b[4][2];
#pragma unroll
            for (int mi = 0; mi < 4; mi++) {
                int r0 = (cx.wm + mi * 16 + cx.g) * LDA2 + kk + cx.tg;
                a[mi][0] = As[r0];
                a[mi][1] = As[r0 + 8 * LDA2];
                a[mi][2] = As[r0 + 4];
                a[mi][3] = As[r0 + 8 * LDA2 + 4];
            }
#pragma unroll
            for (int ni = 0; ni < 4; ni++) {
                int n = cx.wn + ni * 8 + cx.g;
                b[ni][0] = Bs[(kk + cx.tg) * LDB2 + n];
                b[ni][1] = Bs[(kk + cx.tg + 4) * LDB2 + n];
            }
#pragma unroll
            for (int mi = 0; mi < 4; mi++)
#pragma unroll
                for (int ni = 0; ni < 4; ni++)
                    mma_tf32(c[mi][ni], a[mi], b[ni]);
        }
        __syncthreads();
    }
}

// GEMM 1: qkv = X @ W[256,768], scatter into g_qkv[which][b*8+h][n][d]
__global__ __launch_bounds__(256, 2)
void gemm_qkv_tc(const float* __restrict__ X, const float* __restrict__ W) {
    __shared__ uint32_t As[128 * LDA2];
    __shared__ uint32_t Bs[TBK * LDB2];
    int tid = threadIdx.x;
    GemmCtx cx;
    cx.lane = tid & 31; cx.warp = tid >> 5;
    cx.g = cx.lane >> 2; cx.tg = cx.lane & 3;
    cx.wm = (cx.warp >> 2) * 64; cx.wn = (cx.warp & 3) * 32;
    cx.rowBase = blockIdx.y * 128; cx.colBase = blockIdx.x * 128;

    float c[4][4][4];
#pragma unroll
    for (int mi = 0; mi < 4; mi++)
#pragma unroll
        for (int ni = 0; ni < 4; ni++)
#pragma unroll
            for (int r = 0; r < 4; r++) c[mi][ni][r] = 0.f;

    gemm_mainloop(X, W, 768, As, Bs, cx, c);

#pragma unroll
    for (int mi = 0; mi < 4; mi++) {
        int r0 = cx.rowBase + cx.wm + mi * 16 + cx.g;
        int r1 = r0 + 8;
        int b0 = r0 / SEQ_N, n0 = r0 - b0 * SEQ_N;
        int b1 = r1 / SEQ_N, n1 = r1 - b1 * SEQ_N;
#pragma unroll
        for (int ni = 0; ni < 4; ni++) {
            int col   = cx.colBase + cx.wn + ni * 8 + 2 * cx.tg;
            int which = col >> 8;
            int h     = (col >> 5) & 7;
            int d0    = col & 31;
            size_t base0 = ((size_t)which * BH_TOT + b0 * HEADS + h) * HS + (size_t)n0 * DH + d0;
            size_t base1 = ((size_t)which * BH_TOT + b1 * HEADS + h) * HS + (size_t)n1 * DH + d0;
            *(float2*)&g_qkv[base0] = make_float2(c[mi][ni][0], c[mi][ni][1]);
            *(float2*)&g_qkv[base1] = make_float2(c[mi][ni][2], c[mi][ni][3]);
        }
    }
}

// GEMM 2: out = g_attnout @ proj_w[256,256] + proj_b
__global__ __launch_bounds__(256, 2)
void gemm_proj_tc(const float* __restrict__ W, const float* __restrict__ bias,
                  float* __restrict__ Out) {
    __shared__ uint32_t As[128 * LDA2];
    __shared__ uint32_t Bs[TBK * LDB2];
    int tid = threadIdx.x;
    GemmCtx cx;
    cx.lane = tid & 31; cx.warp = tid >> 5;
    cx.g = cx.lane >> 2; cx.tg = cx.lane & 3;
    cx.wm = (cx.warp >> 2) * 64; cx.wn = (cx.warp & 3) * 32;
    cx.rowBase = blockIdx.y * 128; cx.colBase = blockIdx.x * 128;

    float c[4][4][4];
#pragma unroll
    for (int mi = 0; mi < 4; mi++)
#pragma unroll
        for (int ni = 0; ni < 4; ni++)
#pragma unroll
            for (int r = 0; r < 4; r++) c[mi][ni][r] = 0.f;

    gemm_mainloop(g_attnout, W, 256, As, Bs, cx, c);

#pragma unroll
    for (int mi = 0; mi < 4; mi++) {
        int r0 = cx.rowBase + cx.wm + mi * 16 + cx.g;
        int r1 = r0 + 8;
#pragma unroll
        for (int ni = 0; ni < 4; ni++) {
            int col = cx.colBase + cx.wn + ni * 8 + 2 * cx.tg;
            float bx = bias[col], by = bias[col + 1];
            *(float2*)&Out[(size_t)r0 * 256 + col] =
                make_float2(c[mi][ni][0] + bx, c[mi][ni][1] + by);
            *(float2*)&Out[(size_t)r1 * 256 + col] =
                make_float2(c[mi][ni][2] + bx, c[mi][ni][3] + by);
        }
    }
}

// ---------------------------------------------------------------------------
// Attention: one block per (b,h,half). 128 threads = 4 warps, 16 rows each.
//   S[64x112] = q . k^T   (tf32 mma)   P = exp(S + bm) (reg-prefetched bm)
//   O[64x32]  = P . v     (tf32 mma), scaled by 1/rowsum at store
// smem words: q 64*36 | k 112*36 | vT 32*116 | P 64*116 | inv 64 = 17536 (70.1KB)
// 3 CTAs/SM, ~168 regs/thread budget.
// ---------------------------------------------------------------------------
#define LDQ 36
#define LDK 36
#define LDV 116
#define LDP 116
#define AOFF_K   (64 * LDQ)                 // 2304
#define AOFF_V   (AOFF_K + 112 * LDK)       // 6336
#define AOFF_P   (AOFF_V + 32 * LDV)        // 10048
#define AOFF_INV (AOFF_P + 64 * LDP)        // 17472
#define ATTN_SMEM_BYTES ((AOFF_INV + 64) * 4)   // 70144

__global__ __launch_bounds__(128, 3)
void attn_tc() {
    extern __shared__ uint32_t sm[];
    uint32_t* sq  = sm;
    uint32_t* sk  = sm + AOFF_K;
    uint32_t* sv  = sm + AOFF_V;
    uint32_t* sP  = sm + AOFF_P;
    float*    sInv = (float*)(sm + AOFF_INV);

    int tid  = threadIdx.x;
    int bid  = blockIdx.x;
    int bh   = bid >> 1;
    int rowOff = (bid & 1) * 64;
    int b = bh >> 3, h = bh & 7;
    const float* gq = g_qkv + (size_t)bh * HS;
    const float* gk = gq + QKV_ONE;
    const float* gv = gq + 2 * QKV_ONE;

    // ---- tile loads (float4 gmem, tf32 smem) ----
#pragma unroll
    for (int i = tid; i < 512; i += 128) {          // q: 64 rows x 32
        int r = i >> 3, d4 = (i & 7) * 4;
        int n = rowOff + r;
        float4 v = make_float4(0.f, 0.f, 0.f, 0.f);
        if (n < SEQ_N) v = *(const float4*)&gq[n * 32 + d4];
        uint4 u = make_uint4(f2tf(v.x * SCALE), f2tf(v.y * SCALE),
                             f2tf(v.z * SCALE), f2tf(v.w * SCALE));
        *(uint4*)&sq[r * LDQ + d4] = u;
    }
#pragma unroll
    for (int i = tid; i < 896; i += 128) {          // k: 112 rows x 32
        int r = i >> 3, d4 = (i & 7) * 4;
        float4 v = make_float4(0.f, 0.f, 0.f, 0.f);
        if (r < SEQ_N) v = *(const float4*)&gk[r * 32 + d4];
        uint4 u = make_uint4(f2tf(v.x), f2tf(v.y), f2tf(v.z), f2tf(v.w));
        *(uint4*)&sk[r * LDK + d4] = u;
    }
#pragma unroll
    for (int i = tid; i < 784; i += 128) {          // v -> vT[d][m]
        int m = i >> 3, d4 = (i & 7) * 4;
        float4 v = *(const float4*)&gv[m * 32 + d4];
        sv[(d4 + 0) * LDV + m] = f2tf(v.x);
        sv[(d4 + 1) * LDV + m] = f2tf(v.y);
        sv[(d4 + 2) * LDV + m] = f2tf(v.z);
        sv[(d4 + 3) * LDV + m] = f2tf(v.w);
    }
    for (int i = tid; i < 448; i += 128) {          // zero vT cols 98..111
        int d = i / 14, m = SEQ_N + i % 14;
        sv[d * LDV + m] = 0u;
    }
    __syncthreads();

    int lane = tid & 31, warp = tid >> 5;
    int g = lane >> 2, tg = lane & 3;
    int lr0 = warp * 16 + g, lr1 = lr0 + 8;
    int n0 = rowOff + lr0, n1 = n0 + 8;
    bool rv0 = (n0 < SEQ_N), rv1 = (n1 < SEQ_N);
    size_t bmbase = ((size_t)(b & (NW - 1)) * HEADS + h) * (SEQ_N * SEQ_N);
    const float* bmr0 = &g_bm[bmbase + (size_t)n0 * SEQ_N];
    const float* bmr1 = &g_bm[bmbase + (size_t)n1 * SEQ_N];

    // ---- S phase ----
    uint32_t aF[4][4];
#pragma unroll
    for (int kk = 0; kk < 4; kk++) {
        int base = lr0 * LDQ + kk * 8 + tg;
        aF[kk][0] = sq[base];
        aF[kk][1] = sq[base + 8 * LDQ];
        aF[kk][2] = sq[base + 4];
        aF[kk][3] = sq[base + 8 * LDQ + 4];
    }

    float sum0 = 0.f, sum1 = 0.f;
#pragma unroll
    for (int h2 = 0; h2 < 2; h2++) {
        // prefetch bias+mask for this half (7 ni's) into registers
        float2 pA[7], pB[7];
#pragma unroll
        for (int j = 0; j < 7; j++) {
            int c0 = (h2 * 7 + j) * 8 + 2 * tg;
            bool cvj = (c0 < SEQ_N);
            float2 t0 = make_float2(0.f, 0.f), t1 = make_float2(0.f, 0.f);
            if (rv0 && cvj) t0 = *(const float2*)&bmr0[c0];
            if (rv1 && cvj) t1 = *(const float2*)&bmr1[c0];
            pA[j] = t0; pB[j] = t1;
        }
#pragma unroll
        for (int j = 0; j < 7; j++) {
            int ni = h2 * 7 + j;
            float acc[4] = {0.f, 0.f, 0.f, 0.f};
#pragma unroll
            for (int kk = 0; kk < 4; kk++) {
                uint32_t bF[2];
                int nr = ni * 8 + g;
                bF[0] = sk[nr * LDK + kk * 8 + tg];
                bF[1] = sk[nr * LDK + kk * 8 + tg + 4];
                mma_tf32(acc, aF[kk], bF);
            }
            int c0 = ni * 8 + 2 * tg;
            bool cv = (c0 < SEQ_N);
            float e00 = 0.f, e01 = 0.f, e10 = 0.f, e11 = 0.f;
            if (cv && rv0) {
                e00 = fastexp(acc[0] + pA[j].x);
                e01 = fastexp(acc[1] + pA[j].y);
            }
            if (cv && rv1) {
                e10 = fastexp(acc[2] + pB[j].x);
                e11 = fastexp(acc[3] + pB[j].y);
            }
            uint32_t u00 = f2tf(e00), u01 = f2tf(e01);
            uint32_t u10 = f2tf(e10), u11 = f2tf(e11);
            sum0 += __uint_as_float(u00) + __uint_as_float(u01);
            sum1 += __uint_as_float(u10) + __uint_as_float(u11);
            *(uint2*)&sP[lr0 * LDP + c0] = make_uint2(u00, u01);
            *(uint2*)&sP[lr1 * LDP + c0] = make_uint2(u10, u11);
        }
    }
    // rowsum across the 4-lane quad
    sum0 += __shfl_xor_sync(0xffffffffu, sum0, 1);
    sum0 += __shfl_xor_sync(0xffffffffu, sum0, 2);
    sum1 += __shfl_xor_sync(0xffffffffu, sum1, 1);
    sum1 += __shfl_xor_sync(0xffffffffu, sum1, 2);
    if (tg == 0) {
        sInv[lr0] = rv0 ? (1.0f / sum0) : 0.f;
        sInv[lr1] = rv1 ? (1.0f / sum1) : 0.f;
    }
    __syncthreads();

    // ---- O phase: O = P . v ----
    float oacc[4][4];
#pragma unroll
    for (int ni = 0; ni < 4; ni++)
#pragma unroll
        for (int r = 0; r < 4; r++) oacc[ni][r] = 0.f;

#pragma unroll
    for (int kk = 0; kk < 14; kk++) {
        uint32_t aO[4];
        int base = lr0 * LDP + kk * 8 + tg;
        aO[0] = sP[base];
        aO[1] = sP[base + 8 * LDP];
        aO[2] = sP[base + 4];
        aO[3] = sP[base + 8 * LDP + 4];
#pragma unroll
        for (int ni = 0; ni < 4; ni++) {
            uint32_t bO[2];
            int vr = ni * 8 + g;
            bO[0] = sv[vr * LDV + kk * 8 + tg];
            bO[1] = sv[vr * LDV + kk * 8 + tg + 4];
            mma_tf32(oacc[ni], aO, bO);
        }
    }

    if (rv0) {
        float inv0 = sInv[lr0];
        size_t ob = ((size_t)b * SEQ_N + n0) * CH + h * DH;
#pragma unroll
        for (int ni = 0; ni < 4; ni++) {
            int d0 = ni * 8 + 2 * tg;
            *(float2*)&g_attnout[ob + d0] =
                make_float2(oacc[ni][0] * inv0, oacc[ni][1] * inv0);
        }
    }
    if (rv1) {
        float inv1 = sInv[lr1];
        size_t ob = ((size_t)b * SEQ_N + n1) * CH + h * DH;
#pragma unroll
        for (int ni = 0; ni < 4; ni++) {
            int d0 = ni * 8 + 2 * tg;
            *(float2*)&g_attnout[ob + d0] =
                make_float2(oacc[ni][2] * inv1, oacc[ni][3] * inv1);
        }
    }
}

// ---------------------------------------------------------------------------
// Launch
// ---------------------------------------------------------------------------
extern "C" void kernel_launch(void* const* d_in, const int* in_sizes, int n_in,
                              void* d_out, int out_size) {
    const float* x       = (const float*)d_in[0];
    const float* mask    = (const float*)d_in[1];
    const float* qkv_w   = (const float*)d_in[2];
    const float* proj_w  = (const float*)d_in[3];
    const float* proj_b  = (const float*)d_in[4];
    const float* table   = (const float*)d_in[5];
    float* out           = (float*)d_out;

    static bool attr_done = false;
    if (!attr_done) {
        cudaFuncSetAttribute(attn_tc, cudaFuncAttributeMaxDynamicSharedMemorySize,
                             ATTN_SMEM_BYTES);
        attr_done = true;
    }

    // 0) bias+mask precompute
    {
        int tot = NW * HEADS * SEQ_N * SEQ_N;
        bm_kernel<<<(tot + 255) / 256, 256>>>(mask, table);
    }
    // 1) qkv GEMM (tf32 tensor cores)
    gemm_qkv_tc<<<dim3(768 / 128, M_TOT / 128), 256>>>(x, qkv_w);
    // 2) attention: 2 half-blocks per (b,h)
    attn_tc<<<BH_TOT * 2, 128, ATTN_SMEM_BYTES>>>();
    // 3) proj GEMM + bias (tf32 tensor cores)
    gemm_proj_tc<<<dim3(256 / 128, M_TOT / 128), 256>>>(proj_w, proj_b, out);
}

// round 7
// speedup vs baseline: 2.9874x; 1.0117x over previous
#include <cuda_runtime.h>
#include <cuda_bf16.h>
#include <cstdint>
#include <cstddef>

// ---------------------------------------------------------------------------
// Problem constants
// ---------------------------------------------------------------------------
#define B_TOT   2048
#define SEQ_N   98
#define CH      256
#define HEADS   8
#define DH      32
#define NW      64
#define M_TOT   (B_TOT * SEQ_N)        // 200704
#define BH_TOT  (B_TOT * HEADS)        // 16384
#define HS      (SEQ_N * DH)           // 3136
#define QKV_ONE ((size_t)BH_TOT * HS)  // 51380224
#define SCALE   0.17677669529663687f   // 1/sqrt(32)

// ---------------------------------------------------------------------------
// Device-global scratch
// ---------------------------------------------------------------------------
__device__ float g_qkv[3ull * QKV_ONE];           // [which][b*H+h][n][d]
__device__ float g_attnout[(size_t)M_TOT * CH];   // [b][n][c] (tf32-rounded)
__device__ float g_bm[(size_t)NW * HEADS * SEQ_N * SEQ_N];  // bias+mask
__device__ float g_xr[(size_t)M_TOT * CH];        // tf32-rounded X
__device__ float g_wq[CH * 3 * CH];               // tf32-rounded qkv_w
__device__ float g_wp[CH * CH];                   // tf32-rounded proj_w

// ---------------------------------------------------------------------------
// tf32 helpers
// ---------------------------------------------------------------------------
__device__ __forceinline__ uint32_t f2tf(float v) {
    uint32_t r;
    asm("cvt.rna.tf32.f32 %0, %1;" : "=r"(r) : "f"(v));
    return r;
}
__device__ __forceinline__ float f2tff(float v) { return __uint_as_float(f2tf(v)); }

__device__ __forceinline__ void mma_tf32(float* c, const uint32_t* a, const uint32_t* b) {
    asm volatile(
        "mma.sync.aligned.m16n8k8.row.col.f32.tf32.tf32.f32 "
        "{%0,%1,%2,%3}, {%4,%5,%6,%7}, {%8,%9}, {%0,%1,%2,%3};\n"
        : "+f"(c[0]), "+f"(c[1]), "+f"(c[2]), "+f"(c[3])
        : "r"(a[0]), "r"(a[1]), "r"(a[2]), "r"(a[3]),
          "r"(b[0]), "r"(b[1]));
}

// fast exp on FMA pipe
__device__ __forceinline__ float fastexp(float s) {
    float t  = s * 1.4426950408889634f;
    float fr = t + 12582912.0f;            // 1.5 * 2^23
    float rn = fr - 12582912.0f;
    float f  = t - rn;
    float p  = 1.3333558146428443e-3f;
    p = fmaf(p, f, 9.618129107628477e-3f);
    p = fmaf(p, f, 5.550410866482158e-2f);
    p = fmaf(p, f, 2.402265069591007e-1f);
    p = fmaf(p, f, 6.931471805599453e-1f);
    p = fmaf(p, f, 1.0f);
    int ei = (int)((unsigned)__float_as_int(fr) << 23);
    return __int_as_float(__float_as_int(p) + ei);
}

// cp.async 16B
__device__ __forceinline__ void cpa16(uint32_t dst, const void* src) {
    asm volatile("cp.async.cg.shared.global [%0], [%1], 16;" :: "r"(dst), "l"(src));
}
__device__ __forceinline__ uint32_t smem_u32(const void* p) {
    return (uint32_t)__cvta_generic_to_shared(p);
}

// ---------------------------------------------------------------------------
// Kernel: tf32-round a float array (vectorized)
// ---------------------------------------------------------------------------
__global__ void tf32_round4(const float4* __restrict__ src, float4* __restrict__ dst,
                            int n4) {
    int i = blockIdx.x * 256 + threadIdx.x;
    if (i < n4) {
        float4 v = src[i];
        dst[i] = make_float4(f2tff(v.x), f2tff(v.y), f2tff(v.z), f2tff(v.w));
    }
}

// ---------------------------------------------------------------------------
// Kernel 0: precompute bias(rel-pos) + mask  ->  g_bm[wi][h][n][m]
// ---------------------------------------------------------------------------
__global__ void bm_kernel(const float* __restrict__ mask,
                          const float* __restrict__ table) {
    int i = blockIdx.x * 256 + threadIdx.x;
    const int TOT = NW * HEADS * SEQ_N * SEQ_N;
    if (i >= TOT) return;
    int m  = i % SEQ_N;
    int r  = i / SEQ_N;
    int n  = r % SEQ_N;  r /= SEQ_N;
    int h  = r & 7;
    int wi = r >> 3;
    int dn = n / 49, hn = (n % 49) / 7, wn = n % 7;
    int dm = m / 49, hm = (m % 49) / 7, wm = m % 7;
    int rid = (dn - dm + 1) * 169 + (hn - hm + 6) * 13 + (wn - wm + 6);
    g_bm[i] = table[rid * HEADS + h] + mask[(size_t)wi * SEQ_N * SEQ_N + n * SEQ_N + m];
}

// ---------------------------------------------------------------------------
// tf32 GEMM, cp.async 2-stage double buffer. Block 128x128, BK=32, 8 warps.
// Inputs MUST be pre-rounded to tf32 (raw bits used by mma).
// smem: 2 x (A 128*36 + B 32*136) u32 = 71680 B (dynamic)
// ---------------------------------------------------------------------------
#define TBK  32
#define LDA2 36
#define LDB2 136
#define AW   (128 * LDA2)      // 4608 words per A stage
#define BW   (TBK * LDB2)      // 4352 words per B stage
#define GEMM_SMEM_BYTES ((2 * AW + 2 * BW) * 4)   // 71680

struct GemmCtx {
    int rowBase, colBase;
    int g, tg, wm, wn;
};

__device__ __forceinline__ void gemm_mainloop_ca(
    const float* __restrict__ X, const float* __restrict__ W, int NLD,
    uint32_t* smem, const GemmCtx& cx, float c[4][4][4]) {
    int tid = threadIdx.x;
    int ar  = tid >> 3, ac4 = (tid & 7) * 4;
    int br  = tid >> 5, bc4 = (tid & 31) * 4;
    uint32_t base = smem_u32(smem);

    auto issue = [&](int s, int kt) {
        uint32_t ab = base + (s * AW) * 4;
#pragma unroll
        for (int i = 0; i < 4; i++) {
            int r = ar + 32 * i;
            cpa16(ab + (r * LDA2 + ac4) * 4,
                  X + (size_t)(cx.rowBase + r) * 256 + kt + ac4);
        }
        uint32_t bb = base + (2 * AW + s * BW) * 4;
#pragma unroll
        for (int i = 0; i < 4; i++) {
            int r = br + 8 * i;
            cpa16(bb + (r * LDB2 + bc4) * 4,
                  W + (size_t)(kt + r) * NLD + cx.colBase + bc4);
        }
        asm volatile("cp.async.commit_group;");
    };

    issue(0, 0);

#pragma unroll 1
    for (int it = 0; it < 8; it++) {
        if (it < 7) {
            issue((it + 1) & 1, (it + 1) * TBK);
            asm volatile("cp.async.wait_group 1;");
        } else {
            asm volatile("cp.async.wait_group 0;");
        }
        __syncthreads();

        uint32_t* As = smem + (it & 1) * AW;
        uint32_t* Bs = smem + 2 * AW + (it & 1) * BW;
#pragma unroll
        for (int kk = 0; kk < TBK; kk += 8) {
            uint32_t a[4][4], b[4][2];
#pragma unroll
            for (int mi = 0; mi < 4; mi++) {
                int r0 = (cx.wm + mi * 16 + cx.g) * LDA2 + kk + cx.tg;
                a[mi][0] = As[r0];
                a[mi][1] = As[r0 + 8 * LDA2];
                a[mi][2] = As[r0 + 4];
                a[mi][3] = As[r0 + 8 * LDA2 + 4];
            }
#pragma unroll
            for (int ni = 0; ni < 4; ni++) {
                int n = cx.wn + ni * 8 + cx.g;
                b[ni][0] = Bs[(kk + cx.tg) * LDB2 + n];
                b[ni][1] = Bs[(kk + cx.tg + 4) * LDB2 + n];
            }
#pragma unroll
            for (int mi = 0; mi < 4; mi++)
#pragma unroll
                for (int ni = 0; ni < 4; ni++)
                    mma_tf32(c[mi][ni], a[mi], b[ni]);
        }
        __syncthreads();
    }
}

// GEMM 1: qkv = Xr @ Wq[256,768], scatter into g_qkv[which][b*8+h][n][d]
__global__ __launch_bounds__(256, 2)
void gemm_qkv_tc(const float* __restrict__ X, const float* __restrict__ W) {
    extern __shared__ uint32_t smg[];
    int tid = threadIdx.x;
    GemmCtx cx;
    int lane = tid & 31, warp = tid >> 5;
    cx.g = lane >> 2; cx.tg = lane & 3;
    cx.wm = (warp >> 2) * 64; cx.wn = (warp & 3) * 32;
    cx.rowBase = blockIdx.y * 128; cx.colBase = blockIdx.x * 128;

    float c[4][4][4];
#pragma unroll
    for (int mi = 0; mi < 4; mi++)
#pragma unroll
        for (int ni = 0; ni < 4; ni++)
#pragma unroll
            for (int r = 0; r < 4; r++) c[mi][ni][r] = 0.f;

    gemm_mainloop_ca(X, W, 768, smg, cx, c);

#pragma unroll
    for (int mi = 0; mi < 4; mi++) {
        int r0 = cx.rowBase + cx.wm + mi * 16 + cx.g;
        int r1 = r0 + 8;
        int b0 = r0 / SEQ_N, n0 = r0 - b0 * SEQ_N;
        int b1 = r1 / SEQ_N, n1 = r1 - b1 * SEQ_N;
#pragma unroll
        for (int ni = 0; ni < 4; ni++) {
            int col   = cx.colBase + cx.wn + ni * 8 + 2 * cx.tg;
            int which = col >> 8;
            int h     = (col >> 5) & 7;
            int d0    = col & 31;
            size_t base0 = ((size_t)which * BH_TOT + b0 * HEADS + h) * HS + (size_t)n0 * DH + d0;
            size_t base1 = ((size_t)which * BH_TOT + b1 * HEADS + h) * HS + (size_t)n1 * DH + d0;
            *(float2*)&g_qkv[base0] = make_float2(c[mi][ni][0], c[mi][ni][1]);
            *(float2*)&g_qkv[base1] = make_float2(c[mi][ni][2], c[mi][ni][3]);
        }
    }
}

// GEMM 2: out = g_attnout @ Wp[256,256] + proj_b
__global__ __launch_bounds__(256, 2)
void gemm_proj_tc(const float* __restrict__ W, const float* __restrict__ bias,
                  float* __restrict__ Out) {
    extern __shared__ uint32_t smg[];
    int tid = threadIdx.x;
    GemmCtx cx;
    int lane = tid & 31, warp = tid >> 5;
    cx.g = lane >> 2; cx.tg = lane & 3;
    cx.wm = (warp >> 2) * 64; cx.wn = (warp & 3) * 32;
    cx.rowBase = blockIdx.y * 128; cx.colBase = blockIdx.x * 128;

    float c[4][4][4];
#pragma unroll
    for (int mi = 0; mi < 4; mi++)
#pragma unroll
        for (int ni = 0; ni < 4; ni++)
#pragma unroll
            for (int r = 0; r < 4; r++) c[mi][ni][r] = 0.f;

    gemm_mainloop_ca(g_attnout, W, 256, smg, cx, c);

#pragma unroll
    for (int mi = 0; mi < 4; mi++) {
        int r0 = cx.rowBase + cx.wm + mi * 16 + cx.g;
        int r1 = r0 + 8;
#pragma unroll
        for (int ni = 0; ni < 4; ni++) {
            int col = cx.colBase + cx.wn + ni * 8 + 2 * cx.tg;
            float bx = bias[col], by = bias[col + 1];
            *(float2*)&Out[(size_t)r0 * 256 + col] =
                make_float2(c[mi][ni][0] + bx, c[mi][ni][1] + by);
            *(float2*)&Out[(size_t)r1 * 256 + col] =
                make_float2(c[mi][ni][2] + bx, c[mi][ni][3] + by);
        }
    }
}

// ---------------------------------------------------------------------------
// Attention: one block per (b,h,half). 128 threads = 4 warps, 16 rows each.
// Output stores are tf32-rounded so proj GEMM can consume raw bits.
// ---------------------------------------------------------------------------
#define LDQ 36
#define LDK 36
#define LDV 116
#define LDP 116
#define AOFF_K   (64 * LDQ)                 // 2304
#define AOFF_V   (AOFF_K + 112 * LDK)       // 6336
#define AOFF_P   (AOFF_V + 32 * LDV)        // 10048
#define AOFF_INV (AOFF_P + 64 * LDP)        // 17472
#define ATTN_SMEM_BYTES ((AOFF_INV + 64) * 4)   // 70144

__global__ __launch_bounds__(128, 3)
void attn_tc() {
    extern __shared__ uint32_t sm[];
    uint32_t* sq  = sm;
    uint32_t* sk  = sm + AOFF_K;
    uint32_t* sv  = sm + AOFF_V;
    uint32_t* sP  = sm + AOFF_P;
    float*    sInv = (float*)(sm + AOFF_INV);

    int tid  = threadIdx.x;
    int bid  = blockIdx.x;
    int bh   = bid >> 1;
    int rowOff = (bid & 1) * 64;
    int b = bh >> 3, h = bh & 7;
    const float* gq = g_qkv + (size_t)bh * HS;
    const float* gk = gq + QKV_ONE;
    const float* gv = gq + 2 * QKV_ONE;

    // ---- tile loads (float4 gmem, tf32 smem) ----
#pragma unroll
    for (int i = tid; i < 512; i += 128) {          // q: 64 rows x 32
        int r = i >> 3, d4 = (i & 7) * 4;
        int n = rowOff + r;
        float4 v = make_float4(0.f, 0.f, 0.f, 0.f);
        if (n < SEQ_N) v = *(const float4*)&gq[n * 32 + d4];
        uint4 u = make_uint4(f2tf(v.x * SCALE), f2tf(v.y * SCALE),
                             f2tf(v.z * SCALE), f2tf(v.w * SCALE));
        *(uint4*)&sq[r * LDQ + d4] = u;
    }
#pragma unroll
    for (int i = tid; i < 896; i += 128) {          // k: 112 rows x 32
        int r = i >> 3, d4 = (i & 7) * 4;
        float4 v = make_float4(0.f, 0.f, 0.f, 0.f);
        if (r < SEQ_N) v = *(const float4*)&gk[r * 32 + d4];
        uint4 u = make_uint4(f2tf(v.x), f2tf(v.y), f2tf(v.z), f2tf(v.w));
        *(uint4*)&sk[r * LDK + d4] = u;
    }
#pragma unroll
    for (int i = tid; i < 784; i += 128) {          // v -> vT[d][m]
        int m = i >> 3, d4 = (i & 7) * 4;
        float4 v = *(const float4*)&gv[m * 32 + d4];
        sv[(d4 + 0) * LDV + m] = f2tf(v.x);
        sv[(d4 + 1) * LDV + m] = f2tf(v.y);
        sv[(d4 + 2) * LDV + m] = f2tf(v.z);
        sv[(d4 + 3) * LDV + m] = f2tf(v.w);
    }
    for (int i = tid; i < 448; i += 128) {          // zero vT cols 98..111
        int d = i / 14, m = SEQ_N + i % 14;
        sv[d * LDV + m] = 0u;
    }
    __syncthreads();

    int lane = tid & 31, warp = tid >> 5;
    int g = lane >> 2, tg = lane & 3;
    int lr0 = warp * 16 + g, lr1 = lr0 + 8;
    int n0 = rowOff + lr0, n1 = n0 + 8;
    bool rv0 = (n0 < SEQ_N), rv1 = (n1 < SEQ_N);
    size_t bmbase = ((size_t)(b & (NW - 1)) * HEADS + h) * (SEQ_N * SEQ_N);
    const float* bmr0 = &g_bm[bmbase + (size_t)n0 * SEQ_N];
    const float* bmr1 = &g_bm[bmbase + (size_t)n1 * SEQ_N];

    // ---- S phase ----
    uint32_t aF[4][4];
#pragma unroll
    for (int kk = 0; kk < 4; kk++) {
        int base = lr0 * LDQ + kk * 8 + tg;
        aF[kk][0] = sq[base];
        aF[kk][1] = sq[base + 8 * LDQ];
        aF[kk][2] = sq[base + 4];
        aF[kk][3] = sq[base + 8 * LDQ + 4];
    }

    float sum0 = 0.f, sum1 = 0.f;
#pragma unroll
    for (int h2 = 0; h2 < 2; h2++) {
        float2 pA[7], pB[7];
#pragma unroll
        for (int j = 0; j < 7; j++) {
            int c0 = (h2 * 7 + j) * 8 + 2 * tg;
            bool cvj = (c0 < SEQ_N);
            float2 t0 = make_float2(0.f, 0.f), t1 = make_float2(0.f, 0.f);
            if (rv0 && cvj) t0 = *(const float2*)&bmr0[c0];
            if (rv1 && cvj) t1 = *(const float2*)&bmr1[c0];
            pA[j] = t0; pB[j] = t1;
        }
#pragma unroll
        for (int j = 0; j < 7; j++) {
            int ni = h2 * 7 + j;
            float acc[4] = {0.f, 0.f, 0.f, 0.f};
#pragma unroll
            for (int kk = 0; kk < 4; kk++) {
                uint32_t bF[2];
                int nr = ni * 8 + g;
                bF[0] = sk[nr * LDK + kk * 8 + tg];
                bF[1] = sk[nr * LDK + kk * 8 + tg + 4];
                mma_tf32(acc, aF[kk], bF);
            }
            int c0 = ni * 8 + 2 * tg;
            bool cv = (c0 < SEQ_N);
            float e00 = 0.f, e01 = 0.f, e10 = 0.f, e11 = 0.f;
            if (cv && rv0) {
                e00 = fastexp(acc[0] + pA[j].x);
                e01 = fastexp(acc[1] + pA[j].y);
            }
            if (cv && rv1) {
                e10 = fastexp(acc[2] + pB[j].x);
                e11 = fastexp(acc[3] + pB[j].y);
            }
            uint32_t u00 = f2tf(e00), u01 = f2tf(e01);
            uint32_t u10 = f2tf(e10), u11 = f2tf(e11);
            sum0 += __uint_as_float(u00) + __uint_as_float(u01);
            sum1 += __uint_as_float(u10) + __uint_as_float(u11);
            *(uint2*)&sP[lr0 * LDP + c0] = make_uint2(u00, u01);
            *(uint2*)&sP[lr1 * LDP + c0] = make_uint2(u10, u11);
        }
    }
    sum0 += __shfl_xor_sync(0xffffffffu, sum0, 1);
    sum0 += __shfl_xor_sync(0xffffffffu, sum0, 2);
    sum1 += __shfl_xor_sync(0xffffffffu, sum1, 1);
    sum1 += __shfl_xor_sync(0xffffffffu, sum1, 2);
    if (tg == 0) {
        sInv[lr0] = rv0 ? (1.0f / sum0) : 0.f;
        sInv[lr1] = rv1 ? (1.0f / sum1) : 0.f;
    }
    __syncthreads();

    // ---- O phase: O = P . v ----
    float oacc[4][4];
#pragma unroll
    for (int ni = 0; ni < 4; ni++)
#pragma unroll
        for (int r = 0; r < 4; r++) oacc[ni][r] = 0.f;

#pragma unroll
    for (int kk = 0; kk < 14; kk++) {
        uint32_t aO[4];
        int base = lr0 * LDP + kk * 8 + tg;
        aO[0] = sP[base];
        aO[1] = sP[base + 8 * LDP];
        aO[2] = sP[base + 4];
        aO[3] = sP[base + 8 * LDP + 4];
#pragma unroll
        for (int ni = 0; ni < 4; ni++) {
            uint32_t bO[2];
            int vr = ni * 8 + g;
            bO[0] = sv[vr * LDV + kk * 8 + tg];
            bO[1] = sv[vr * LDV + kk * 8 + tg + 4];
            mma_tf32(oacc[ni], aO, bO);
        }
    }

    // stores tf32-rounded so proj GEMM can consume raw bits via cp.async
    if (rv0) {
        float inv0 = sInv[lr0];
        size_t ob = ((size_t)b * SEQ_N + n0) * CH + h * DH;
#pragma unroll
        for (int ni = 0; ni < 4; ni++) {
            int d0 = ni * 8 + 2 * tg;
            *(float2*)&g_attnout[ob + d0] =
                make_float2(f2tff(oacc[ni][0] * inv0), f2tff(oacc[ni][1] * inv0));
        }
    }
    if (rv1) {
        float inv1 = sInv[lr1];
        size_t ob = ((size_t)b * SEQ_N + n1) * CH + h * DH;
#pragma unroll
        for (int ni = 0; ni < 4; ni++) {
            int d0 = ni * 8 + 2 * tg;
            *(float2*)&g_attnout[ob + d0] =
                make_float2(f2tff(oacc[ni][2] * inv1), f2tff(oacc[ni][3] * inv1));
        }
    }
}

// ---------------------------------------------------------------------------
// Launch
// ---------------------------------------------------------------------------
extern "C" void kernel_launch(void* const* d_in, const int* in_sizes, int n_in,
                              void* d_out, int out_size) {
    const float* x       = (const float*)d_in[0];
    const float* mask    = (const float*)d_in[1];
    const float* qkv_w   = (const float*)d_in[2];
    const float* proj_w  = (const float*)d_in[3];
    const float* proj_b  = (const float*)d_in[4];
    const float* table   = (const float*)d_in[5];
    float* out           = (float*)d_out;

    static bool attr_done = false;
    if (!attr_done) {
        cudaFuncSetAttribute(attn_tc, cudaFuncAttributeMaxDynamicSharedMemorySize,
                             ATTN_SMEM_BYTES);
        cudaFuncSetAttribute(gemm_qkv_tc, cudaFuncAttributeMaxDynamicSharedMemorySize,
                             GEMM_SMEM_BYTES);
        cudaFuncSetAttribute(gemm_proj_tc, cudaFuncAttributeMaxDynamicSharedMemorySize,
                             GEMM_SMEM_BYTES);
        attr_done = true;
    }

    float* xr = nullptr; float* wq = nullptr; float* wp = nullptr;
    cudaGetSymbolAddress((void**)&xr, g_xr);
    cudaGetSymbolAddress((void**)&wq, g_wq);
    cudaGetSymbolAddress((void**)&wp, g_wp);

    // 0a) tf32-round GEMM inputs
    {
        int n4x = M_TOT * CH / 4;
        tf32_round4<<<(n4x + 255) / 256, 256>>>((const float4*)x, (float4*)xr, n4x);
        int n4q = CH * 3 * CH / 4;
        tf32_round4<<<(n4q + 255) / 256, 256>>>((const float4*)qkv_w, (float4*)wq, n4q);
        int n4p = CH * CH / 4;
        tf32_round4<<<(n4p + 255) / 256, 256>>>((const float4*)proj_w, (float4*)wp, n4p);
    }
    // 0b) bias+mask precompute
    {
        int tot = NW * HEADS * SEQ_N * SEQ_N;
        bm_kernel<<<(tot + 255) / 256, 256>>>(mask, table);
    }
    // 1) qkv GEMM (tf32 tensor cores, cp.async pipelined)
    gemm_qkv_tc<<<dim3(768 / 128, M_TOT / 128), 256, GEMM_SMEM_BYTES>>>(xr, wq);
    // 2) attention: 2 half-blocks per (b,h)
    attn_tc<<<BH_TOT * 2, 128, ATTN_SMEM_BYTES>>>();
    // 3) proj GEMM + bias (tf32 tensor cores, cp.async pipelined)
    gemm_proj_tc<<<dim3(256 / 128, M_TOT / 128), 256, GEMM_SMEM_BYTES>>>(wp, proj_b, out);
}

// round 11
// speedup vs baseline: 3.1936x; 1.0690x over previous
#include <cuda_runtime.h>
#include <cuda_bf16.h>
#include <cstdint>
#include <cstddef>

// ---------------------------------------------------------------------------
// Problem constants
// ---------------------------------------------------------------------------
#define B_TOT   2048
#define SEQ_N   98
#define CH      256
#define HEADS   8
#define DH      32
#define NW      64
#define M_TOT   (B_TOT * SEQ_N)        // 200704
#define BH_TOT  (B_TOT * HEADS)        // 16384
#define HS      (SEQ_N * DH)           // 3136
#define QKV_ONE ((size_t)BH_TOT * HS)  // 51380224
#define SCALE   0.17677669529663687f   // 1/sqrt(32)

// ---------------------------------------------------------------------------
// Device-global scratch
// ---------------------------------------------------------------------------
__device__ float g_qkv[3ull * QKV_ONE];           // [which][b*H+h][n][d] (tf32)
__device__ float g_attnout[(size_t)M_TOT * CH];   // [b][n][c] (tf32-rounded)
__device__ float g_bm[(size_t)NW * HEADS * SEQ_N * SEQ_N];  // bias+mask
__device__ float g_xr[(size_t)M_TOT * CH];        // tf32-rounded X
__device__ float g_wq[CH * 3 * CH];               // tf32-rounded qkv_w
__device__ float g_wp[CH * CH];                   // tf32-rounded proj_w

// ---------------------------------------------------------------------------
// tf32 helpers
// ---------------------------------------------------------------------------
__device__ __forceinline__ uint32_t f2tf(float v) {
    uint32_t r;
    asm("cvt.rna.tf32.f32 %0, %1;" : "=r"(r) : "f"(v));
    return r;
}
__device__ __forceinline__ float f2tff(float v) { return __uint_as_float(f2tf(v)); }

__device__ __forceinline__ void mma_tf32(float* c, const uint32_t* a, const uint32_t* b) {
    asm volatile(
        "mma.sync.aligned.m16n8k8.row.col.f32.tf32.tf32.f32 "
        "{%0,%1,%2,%3}, {%4,%5,%6,%7}, {%8,%9}, {%0,%1,%2,%3};\n"
        : "+f"(c[0]), "+f"(c[1]), "+f"(c[2]), "+f"(c[3])
        : "r"(a[0]), "r"(a[1]), "r"(a[2]), "r"(a[3]),
          "r"(b[0]), "r"(b[1]));
}

// fast exp on FMA pipe
__device__ __forceinline__ float fastexp(float s) {
    float t  = s * 1.4426950408889634f;
    float fr = t + 12582912.0f;            // 1.5 * 2^23
    float rn = fr - 12582912.0f;
    float f  = t - rn;
    float p  = 1.3333558146428443e-3f;
    p = fmaf(p, f, 9.618129107628477e-3f);
    p = fmaf(p, f, 5.550410866482158e-2f);
    p = fmaf(p, f, 2.402265069591007e-1f);
    p = fmaf(p, f, 6.931471805599453e-1f);
    p = fmaf(p, f, 1.0f);
    int ei = (int)((unsigned)__float_as_int(fr) << 23);
    return __int_as_float(__float_as_int(p) + ei);
}

// cp.async 16B
__device__ __forceinline__ void cpa16(uint32_t dst, const void* src) {
    asm volatile("cp.async.cg.shared.global [%0], [%1], 16;" :: "r"(dst), "l"(src));
}
__device__ __forceinline__ uint32_t smem_u32(const void* p) {
    return (uint32_t)__cvta_generic_to_shared(p);
}

// ---------------------------------------------------------------------------
// Kernel: tf32-round a float array (vectorized)
// ---------------------------------------------------------------------------
__global__ void tf32_round4(const float4* __restrict__ src, float4* __restrict__ dst,
                            int n4) {
    int i = blockIdx.x * 256 + threadIdx.x;
    if (i < n4) {
        float4 v = src[i];
        dst[i] = make_float4(f2tff(v.x), f2tff(v.y), f2tff(v.z), f2tff(v.w));
    }
}

// ---------------------------------------------------------------------------
// Kernel 0: precompute bias(rel-pos) + mask  ->  g_bm[wi][h][n][m]
// ---------------------------------------------------------------------------
__global__ void bm_kernel(const float* __restrict__ mask,
                          const float* __restrict__ table) {
    int i = blockIdx.x * 256 + threadIdx.x;
    const int TOT = NW * HEADS * SEQ_N * SEQ_N;
    if (i >= TOT) return;
    int m  = i % SEQ_N;
    int r  = i / SEQ_N;
    int n  = r % SEQ_N;  r /= SEQ_N;
    int h  = r & 7;
    int wi = r >> 3;
    int dn = n / 49, hn = (n % 49) / 7, wn = n % 7;
    int dm = m / 49, hm = (m % 49) / 7, wm = m % 7;
    int rid = (dn - dm + 1) * 169 + (hn - hm + 6) * 13 + (wn - wm + 6);
    g_bm[i] = table[rid * HEADS + h] + mask[(size_t)wi * SEQ_N * SEQ_N + n * SEQ_N + m];
}

// ---------------------------------------------------------------------------
// tf32 GEMM, cp.async 2-stage double buffer. Block 128x128, BK=32, 8 warps.
// Inputs MUST be pre-rounded to tf32 (raw bits used by mma).
// ---------------------------------------------------------------------------
#define TBK  32
#define LDA2 36
#define LDB2 136
#define AW   (128 * LDA2)      // 4608 words per A stage
#define BW   (TBK * LDB2)      // 4352 words per B stage
#define GEMM_SMEM_BYTES ((2 * AW + 2 * BW) * 4)   // 71680

struct GemmCtx {
    int rowBase, colBase;
    int g, tg, wm, wn;
};

__device__ __forceinline__ void gemm_mainloop_ca(
    const float* __restrict__ X, const float* __restrict__ W, int NLD,
    uint32_t* smem, const GemmCtx& cx, float c[4][4][4]) {
    int tid = threadIdx.x;
    int ar  = tid >> 3, ac4 = (tid & 7) * 4;
    int br  = tid >> 5, bc4 = (tid & 31) * 4;
    uint32_t base = smem_u32(smem);

    auto issue = [&](int s, int kt) {
        uint32_t ab = base + (s * AW) * 4;
#pragma unroll
        for (int i = 0; i < 4; i++) {
            int r = ar + 32 * i;
            cpa16(ab + (r * LDA2 + ac4) * 4,
                  X + (size_t)(cx.rowBase + r) * 256 + kt + ac4);
        }
        uint32_t bb = base + (2 * AW + s * BW) * 4;
#pragma unroll
        for (int i = 0; i < 4; i++) {
            int r = br + 8 * i;
            cpa16(bb + (r * LDB2 + bc4) * 4,
                  W + (size_t)(kt + r) * NLD + cx.colBase + bc4);
        }
        asm volatile("cp.async.commit_group;");
    };

    issue(0, 0);

#pragma unroll 1
    for (int it = 0; it < 8; it++) {
        if (it < 7) {
            issue((it + 1) & 1, (it + 1) * TBK);
            asm volatile("cp.async.wait_group 1;");
        } else {
            asm volatile("cp.async.wait_group 0;");
        }
        __syncthreads();

        uint32_t* As = smem + (it & 1) * AW;
        uint32_t* Bs = smem + 2 * AW + (it & 1) * BW;
#pragma unroll
        for (int kk = 0; kk < TBK; kk += 8) {
            uint32_t a[4][4], b[4][2];
#pragma unroll
            for (int mi = 0; mi < 4; mi++) {
                int r0 = (cx.wm + mi * 16 + cx.g) * LDA2 + kk + cx.tg;
                a[mi][0] = As[r0];
                a[mi][1] = As[r0 + 8 * LDA2];
                a[mi][2] = As[r0 + 4];
                a[mi][3] = As[r0 + 8 * LDA2 + 4];
            }
#pragma unroll
            for (int ni = 0; ni < 4; ni++) {
                int n = cx.wn + ni * 8 + cx.g;
                b[ni][0] = Bs[(kk + cx.tg) * LDB2 + n];
                b[ni][1] = Bs[(kk + cx.tg + 4) * LDB2 + n];
            }
#pragma unroll
            for (int mi = 0; mi < 4; mi++)
#pragma unroll
                for (int ni = 0; ni < 4; ni++)
                    mma_tf32(c[mi][ni], a[mi], b[ni]);
        }
        __syncthreads();
    }
}

// GEMM 1: qkv = Xr @ Wq[256,768], scatter into g_qkv (tf32-rounded stores)
__global__ __launch_bounds__(256, 2)
void gemm_qkv_tc(const float* __restrict__ X, const float* __restrict__ W) {
    extern __shared__ uint32_t smg[];
    int tid = threadIdx.x;
    GemmCtx cx;
    int lane = tid & 31, warp = tid >> 5;
    cx.g = lane >> 2; cx.tg = lane & 3;
    cx.wm = (warp >> 2) * 64; cx.wn = (warp & 3) * 32;
    cx.rowBase = blockIdx.y * 128; cx.colBase = blockIdx.x * 128;

    float c[4][4][4];
#pragma unroll
    for (int mi = 0; mi < 4; mi++)
#pragma unroll
        for (int ni = 0; ni < 4; ni++)
#pragma unroll
            for (int r = 0; r < 4; r++) c[mi][ni][r] = 0.f;

    gemm_mainloop_ca(X, W, 768, smg, cx, c);

#pragma unroll
    for (int mi = 0; mi < 4; mi++) {
        int r0 = cx.rowBase + cx.wm + mi * 16 + cx.g;
        int r1 = r0 + 8;
        int b0 = r0 / SEQ_N, n0 = r0 - b0 * SEQ_N;
        int b1 = r1 / SEQ_N, n1 = r1 - b1 * SEQ_N;
#pragma unroll
        for (int ni = 0; ni < 4; ni++) {
            int col   = cx.colBase + cx.wn + ni * 8 + 2 * cx.tg;
            int which = col >> 8;
            int h     = (col >> 5) & 7;
            int d0    = col & 31;
            size_t base0 = ((size_t)which * BH_TOT + b0 * HEADS + h) * HS + (size_t)n0 * DH + d0;
            size_t base1 = ((size_t)which * BH_TOT + b1 * HEADS + h) * HS + (size_t)n1 * DH + d0;
            // tf32-round so attention can cp.async raw bits
            *(float2*)&g_qkv[base0] = make_float2(f2tff(c[mi][ni][0]), f2tff(c[mi][ni][1]));
            *(float2*)&g_qkv[base1] = make_float2(f2tff(c[mi][ni][2]), f2tff(c[mi][ni][3]));
        }
    }
}

// GEMM 2: out = g_attnout @ Wp[256,256] + proj_b
__global__ __launch_bounds__(256, 2)
void gemm_proj_tc(const float* __restrict__ W, const float* __restrict__ bias,
                  float* __restrict__ Out) {
    extern __shared__ uint32_t smg[];
    int tid = threadIdx.x;
    GemmCtx cx;
    int lane = tid & 31, warp = tid >> 5;
    cx.g = lane >> 2; cx.tg = lane & 3;
    cx.wm = (warp >> 2) * 64; cx.wn = (warp & 3) * 32;
    cx.rowBase = blockIdx.y * 128; cx.colBase = blockIdx.x * 128;

    float c[4][4][4];
#pragma unroll
    for (int mi = 0; mi < 4; mi++)
#pragma unroll
        for (int ni = 0; ni < 4; ni++)
#pragma unroll
            for (int r = 0; r < 4; r++) c[mi][ni][r] = 0.f;

    gemm_mainloop_ca(g_attnout, W, 256, smg, cx, c);

#pragma unroll
    for (int mi = 0; mi < 4; mi++) {
        int r0 = cx.rowBase + cx.wm + mi * 16 + cx.g;
        int r1 = r0 + 8;
#pragma unroll
        for (int ni = 0; ni < 4; ni++) {
            int col = cx.colBase + cx.wn + ni * 8 + 2 * cx.tg;
            float bx = bias[col], by = bias[col + 1];
            *(float2*)&Out[(size_t)r0 * 256 + col] =
                make_float2(c[mi][ni][0] + bx, c[mi][ni][1] + by);
            *(float2*)&Out[(size_t)r1 * 256 + col] =
                make_float2(c[mi][ni][2] + bx, c[mi][ni][3] + by);
        }
    }
}

// ---------------------------------------------------------------------------
// Attention v3: one block per (b,h,half). 128 threads = 4 warps, 16 rows each.
//  - q A-fragments loaded straight from gmem (no smem stage)
//  - k, v loaded via cp.async (g_qkv is pre-rounded tf32 -> raw bits exact)
//  - v stored m-major [112][40] (cp.async friendly + conflict-free B-frags)
//  - no block barrier between S and O phases (sP is warp-private)
//  - odd-half warp 3 (rows 112-127, all invalid) exits early
// smem words: k 112*36 | v 112*40 | P 64*116 = 15936 (63.7KB) -> 3 CTAs/SM
// ---------------------------------------------------------------------------
#define LDK  36
#define LDVM 40
#define LDP  116
#define BOFF_V (112 * LDK)              // 4032
#define BOFF_P (BOFF_V + 112 * LDVM)    // 8512
#define ATTN_SMEM_BYTES ((BOFF_P + 64 * LDP) * 4)   // 63744

__global__ __launch_bounds__(128, 3)
void attn_tc() {
    extern __shared__ uint32_t sm[];
    uint32_t* sk = sm;
    uint32_t* sv = sm + BOFF_V;
    uint32_t* sP = sm + BOFF_P;

    int tid  = threadIdx.x;
    int bid  = blockIdx.x;
    int bh   = bid >> 1;
    int rowOff = (bid & 1) * 64;
    int b = bh >> 3, h = bh & 7;
    const float* gq = g_qkv + (size_t)bh * HS;
    const float* gk = gq + QKV_ONE;
    const float* gv = gq + 2 * QKV_ONE;
    uint32_t skb = smem_u32(sk), svb = smem_u32(sv);

    // ---- async k [98][32] -> sk[n][d], v [98][32] -> sv[m][d] ----
    for (int i = tid; i < 784; i += 128) {
        int r = i >> 3, c4 = (i & 7) * 4;
        cpa16(skb + (r * LDK + c4) * 4, gk + r * 32 + c4);
    }
    for (int i = tid; i < 784; i += 128) {
        int m = i >> 3, d4 = (i & 7) * 4;
        cpa16(svb + (m * LDVM + d4) * 4, gv + m * 32 + d4);
    }
    asm volatile("cp.async.commit_group;");

    int lane = tid & 31, warp = tid >> 5;
    int g = lane >> 2, tg = lane & 3;
    int lr0 = warp * 16 + g, lr1 = lr0 + 8;
    int n0 = rowOff + lr0, n1 = n0 + 8;
    bool rv0 = (n0 < SEQ_N), rv1 = (n1 < SEQ_N);

    // ---- q A-fragments straight from gmem (overlaps cp.async) ----
    uint32_t aF[4][4];
#pragma unroll
    for (int kk = 0; kk < 4; kk++) {
        int c = kk * 8 + tg;
        aF[kk][0] = rv0 ? f2tf(gq[n0 * 32 + c] * SCALE) : 0u;
        aF[kk][1] = rv1 ? f2tf(gq[n1 * 32 + c] * SCALE) : 0u;
        aF[kk][2] = rv0 ? f2tf(gq[n0 * 32 + c + 4] * SCALE) : 0u;
        aF[kk][3] = rv1 ? f2tf(gq[n1 * 32 + c + 4] * SCALE) : 0u;
    }

    // ---- zero pads (rows 98..111) ----
    for (int i = tid; i < 448; i += 128) {
        int r = 98 + (i >> 5), d = i & 31;
        sk[r * LDK + d] = 0u;
    }
    for (int i = tid; i < 448; i += 128) {
        int m = 98 + (i >> 5), d = i & 31;
        sv[m * LDVM + d] = 0u;
    }
    asm volatile("cp.async.wait_group 0;");
    __syncthreads();

    // odd-half warp 3 covers rows 112..127 -> entirely invalid
    if (rowOff != 0 && warp == 3) return;

    size_t bmbase = ((size_t)(b & (NW - 1)) * HEADS + h) * (SEQ_N * SEQ_N);
    const float* bmr0 = &g_bm[bmbase + (size_t)n0 * SEQ_N];
    const float* bmr1 = &g_bm[bmbase + (size_t)n1 * SEQ_N];

    // ---- S phase ----
    float sum0 = 0.f, sum1 = 0.f;
#pragma unroll
    for (int h2 = 0; h2 < 2; h2++) {
        float2 pA[7], pB[7];
#pragma unroll
        for (int j = 0; j < 7; j++) {
            int c0 = (h2 * 7 + j) * 8 + 2 * tg;
            bool cvj = (c0 < SEQ_N);
            float2 t0 = make_float2(0.f, 0.f), t1 = make_float2(0.f, 0.f);
            if (rv0 && cvj) t0 = *(const float2*)&bmr0[c0];
            if (rv1 && cvj) t1 = *(const float2*)&bmr1[c0];
            pA[j] = t0; pB[j] = t1;
        }
#pragma unroll
        for (int j = 0; j < 7; j++) {
            int ni = h2 * 7 + j;
            float acc[4] = {0.f, 0.f, 0.f, 0.f};
#pragma unroll
            for (int kk = 0; kk < 4; kk++) {
                uint32_t bF[2];
                int nr = ni * 8 + g;
                bF[0] = sk[nr * LDK + kk * 8 + tg];
                bF[1] = sk[nr * LDK + kk * 8 + tg + 4];
                mma_tf32(acc, aF[kk], bF);
            }
            int c0 = ni * 8 + 2 * tg;
            bool cv = (c0 < SEQ_N);
            float e00 = 0.f, e01 = 0.f, e10 = 0.f, e11 = 0.f;
            if (cv && rv0) {
                e00 = fastexp(acc[0] + pA[j].x);
                e01 = fastexp(acc[1] + pA[j].y);
            }
            if (cv && rv1) {
                e10 = fastexp(acc[2] + pB[j].x);
                e11 = fastexp(acc[3] + pB[j].y);
            }
            uint32_t u00 = f2tf(e00), u01 = f2tf(e01);
            uint32_t u10 = f2tf(e10), u11 = f2tf(e11);
            sum0 += __uint_as_float(u00) + __uint_as_float(u01);
            sum1 += __uint_as_float(u10) + __uint_as_float(u11);
            *(uint2*)&sP[lr0 * LDP + c0] = make_uint2(u00, u01);
            *(uint2*)&sP[lr1 * LDP + c0] = make_uint2(u10, u11);
        }
    }
    // rowsum across the 4-lane quad (result lands in all 4 lanes)
    sum0 += __shfl_xor_sync(0xffffffffu, sum0, 1);
    sum0 += __shfl_xor_sync(0xffffffffu, sum0, 2);
    sum1 += __shfl_xor_sync(0xffffffffu, sum1, 1);
    sum1 += __shfl_xor_sync(0xffffffffu, sum1, 2);
    float inv0 = rv0 ? (1.0f / sum0) : 0.f;
    float inv1 = rv1 ? (1.0f / sum1) : 0.f;

    // sP is warp-private (rows 16*warp..16*warp+15): warp-level sync suffices
    __syncwarp();

    // ---- O phase: O = P . v ----
    float oacc[4][4];
#pragma unroll
    for (int ni = 0; ni < 4; ni++)
#pragma unroll
        for (int r = 0; r < 4; r++) oacc[ni][r] = 0.f;

#pragma unroll
    for (int kk = 0; kk < 14; kk++) {
        uint32_t aO[4];
        int base = lr0 * LDP + kk * 8 + tg;
        aO[0] = sP[base];
        aO[1] = sP[base + 8 * LDP];
        aO[2] = sP[base + 4];
        aO[3] = sP[base + 8 * LDP + 4];
#pragma unroll
        for (int ni = 0; ni < 4; ni++) {
            uint32_t bO[2];
            int vr = ni * 8 + g;
            bO[0] = sv[(kk * 8 + tg) * LDVM + vr];
            bO[1] = sv[(kk * 8 + tg + 4) * LDVM + vr];
            mma_tf32(oacc[ni], aO, bO);
        }
    }

    // stores tf32-rounded so proj GEMM can consume raw bits via cp.async
    if (rv0) {
        size_t ob = ((size_t)b * SEQ_N + n0) * CH + h * DH;
#pragma unroll
        for (int ni = 0; ni < 4; ni++) {
            int d0 = ni * 8 + 2 * tg;
            *(float2*)&g_attnout[ob + d0] =
                make_float2(f2tff(oacc[ni][0] * inv0), f2tff(oacc[ni][1] * inv0));
        }
    }
    if (rv1) {
        size_t ob = ((size_t)b * SEQ_N + n1) * CH + h * DH;
#pragma unroll
        for (int ni = 0; ni < 4; ni++) {
            int d0 = ni * 8 + 2 * tg;
            *(float2*)&g_attnout[ob + d0] =
                make_float2(f2tff(oacc[ni][2] * inv1), f2tff(oacc[ni][3] * inv1));
        }
    }
}

// ---------------------------------------------------------------------------
// Launch
// ---------------------------------------------------------------------------
extern "C" void kernel_launch(void* const* d_in, const int* in_sizes, int n_in,
                              void* d_out, int out_size) {
    const float* x       = (const float*)d_in[0];
    const float* mask    = (const float*)d_in[1];
    const float* qkv_w   = (const float*)d_in[2];
    const float* proj_w  = (const float*)d_in[3];
    const float* proj_b  = (const float*)d_in[4];
    const float* table   = (const float*)d_in[5];
    float* out           = (float*)d_out;

    static bool attr_done = false;
    if (!attr_done) {
        cudaFuncSetAttribute(attn_tc, cudaFuncAttributeMaxDynamicSharedMemorySize,
                             ATTN_SMEM_BYTES);
        cudaFuncSetAttribute(gemm_qkv_tc, cudaFuncAttributeMaxDynamicSharedMemorySize,
                             GEMM_SMEM_BYTES);
        cudaFuncSetAttribute(gemm_proj_tc, cudaFuncAttributeMaxDynamicSharedMemorySize,
                             GEMM_SMEM_BYTES);
        attr_done = true;
    }

    float* xr = nullptr; float* wq = nullptr; float* wp = nullptr;
    cudaGetSymbolAddress((void**)&xr, g_xr);
    cudaGetSymbolAddress((void**)&wq, g_wq);
    cudaGetSymbolAddress((void**)&wp, g_wp);

    // 0a) tf32-round GEMM inputs
    {
        int n4x = M_TOT * CH / 4;
        tf32_round4<<<(n4x + 255) / 256, 256>>>((const float4*)x, (float4*)xr, n4x);
        int n4q = CH * 3 * CH / 4;
        tf32_round4<<<(n4q + 255) / 256, 256>>>((const float4*)qkv_w, (float4*)wq, n4q);
        int n4p = CH * CH / 4;
        tf32_round4<<<(n4p + 255) / 256, 256>>>((const float4*)proj_w, (float4*)wp, n4p);
    }
    // 0b) bias+mask precompute
    {
        int tot = NW * HEADS * SEQ_N * SEQ_N;
        bm_kernel<<<(tot + 255) / 256, 256>>>(mask, table);
    }
    // 1) qkv GEMM (tf32 tensor cores, cp.async pipelined, rounded stores)
    gemm_qkv_tc<<<dim3(768 / 128, M_TOT / 128), 256, GEMM_SMEM_BYTES>>>(xr, wq);
    // 2) attention: 2 half-blocks per (b,h)
    attn_tc<<<BH_TOT * 2, 128, ATTN_SMEM_BYTES>>>();
    // 3) proj GEMM + bias (tf32 tensor cores, cp.async pipelined)
    gemm_proj_tc<<<dim3(256 / 128, M_TOT / 128), 256, GEMM_SMEM_BYTES>>>(wp, proj_b, out);
}

// round 12
// speedup vs baseline: 3.5195x; 1.1021x over previous
#include <cuda_runtime.h>
#include <cuda_bf16.h>
#include <cstdint>
#include <cstddef>

// ---------------------------------------------------------------------------
// Problem constants
// ---------------------------------------------------------------------------
#define B_TOT   2048
#define SEQ_N   98
#define CH      256
#define HEADS   8
#define DH      32
#define NW      64
#define M_TOT   (B_TOT * SEQ_N)        // 200704
#define BH_TOT  (B_TOT * HEADS)        // 16384
#define HS      (SEQ_N * DH)           // 3136
#define QKV_ONE ((size_t)BH_TOT * HS)  // 51380224
#define SCALE   0.17677669529663687f   // 1/sqrt(32)

// ---------------------------------------------------------------------------
// Device-global scratch
// ---------------------------------------------------------------------------
__device__ float g_qkv[3ull * QKV_ONE];           // [which][b*H+h][n][d] (tf32)
__device__ float g_attnout[(size_t)M_TOT * CH];   // [b][n][c] (tf32-rounded)
__device__ float g_bm[(size_t)NW * HEADS * SEQ_N * SEQ_N];  // bias+mask
__device__ float g_xr[(size_t)M_TOT * CH];        // tf32-rounded X
__device__ float g_wq[CH * 3 * CH];               // tf32-rounded qkv_w
__device__ float g_wp[CH * CH];                   // tf32-rounded proj_w

// ---------------------------------------------------------------------------
// tf32 helpers
// ---------------------------------------------------------------------------
__device__ __forceinline__ uint32_t f2tf(float v) {
    uint32_t r;
    asm("cvt.rna.tf32.f32 %0, %1;" : "=r"(r) : "f"(v));
    return r;
}
__device__ __forceinline__ float f2tff(float v) { return __uint_as_float(f2tf(v)); }

__device__ __forceinline__ void mma_tf32(float* c, const uint32_t* a, const uint32_t* b) {
    asm volatile(
        "mma.sync.aligned.m16n8k8.row.col.f32.tf32.tf32.f32 "
        "{%0,%1,%2,%3}, {%4,%5,%6,%7}, {%8,%9}, {%0,%1,%2,%3};\n"
        : "+f"(c[0]), "+f"(c[1]), "+f"(c[2]), "+f"(c[3])
        : "r"(a[0]), "r"(a[1]), "r"(a[2]), "r"(a[3]),
          "r"(b[0]), "r"(b[1]));
}

// fast exp on FMA pipe
__device__ __forceinline__ float fastexp(float s) {
    float t  = s * 1.4426950408889634f;
    float fr = t + 12582912.0f;            // 1.5 * 2^23
    float rn = fr - 12582912.0f;
    float f  = t - rn;
    float p  = 1.3333558146428443e-3f;
    p = fmaf(p, f, 9.618129107628477e-3f);
    p = fmaf(p, f, 5.550410866482158e-2f);
    p = fmaf(p, f, 2.402265069591007e-1f);
    p = fmaf(p, f, 6.931471805599453e-1f);
    p = fmaf(p, f, 1.0f);
    int ei = (int)((unsigned)__float_as_int(fr) << 23);
    return __int_as_float(__float_as_int(p) + ei);
}

// cp.async 16B
__device__ __forceinline__ void cpa16(uint32_t dst, const void* src) {
    asm volatile("cp.async.cg.shared.global [%0], [%1], 16;" :: "r"(dst), "l"(src));
}
__device__ __forceinline__ uint32_t smem_u32(const void* p) {
    return (uint32_t)__cvta_generic_to_shared(p);
}

// ---------------------------------------------------------------------------
// Kernel: tf32-round a float array (vectorized)
// ---------------------------------------------------------------------------
__global__ void tf32_round4(const float4* __restrict__ src, float4* __restrict__ dst,
                            int n4) {
    int i = blockIdx.x * 256 + threadIdx.x;
    if (i < n4) {
        float4 v = src[i];
        dst[i] = make_float4(f2tff(v.x), f2tff(v.y), f2tff(v.z), f2tff(v.w));
    }
}

// ---------------------------------------------------------------------------
// Kernel 0: precompute bias(rel-pos) + mask  ->  g_bm[wi][h][n][m]
// ---------------------------------------------------------------------------
__global__ void bm_kernel(const float* __restrict__ mask,
                          const float* __restrict__ table) {
    int i = blockIdx.x * 256 + threadIdx.x;
    const int TOT = NW * HEADS * SEQ_N * SEQ_N;
    if (i >= TOT) return;
    int m  = i % SEQ_N;
    int r  = i / SEQ_N;
    int n  = r % SEQ_N;  r /= SEQ_N;
    int h  = r & 7;
    int wi = r >> 3;
    int dn = n / 49, hn = (n % 49) / 7, wn = n % 7;
    int dm = m / 49, hm = (m % 49) / 7, wm = m % 7;
    int rid = (dn - dm + 1) * 169 + (hn - hm + 6) * 13 + (wn - wm + 6);
    g_bm[i] = table[rid * HEADS + h] + mask[(size_t)wi * SEQ_N * SEQ_N + n * SEQ_N + m];
}

// ---------------------------------------------------------------------------
// tf32 GEMM, cp.async 2-stage double buffer. Block 128x128, BK=32, 8 warps.
// Inputs MUST be pre-rounded to tf32 (raw bits used by mma).
// ---------------------------------------------------------------------------
#define TBK  32
#define LDA2 36
#define LDB2 136
#define AW   (128 * LDA2)      // 4608 words per A stage
#define BW   (TBK * LDB2)      // 4352 words per B stage
#define GEMM_SMEM_BYTES ((2 * AW + 2 * BW) * 4)   // 71680

struct GemmCtx {
    int rowBase, colBase;
    int g, tg, wm, wn;
};

__device__ __forceinline__ void gemm_mainloop_ca(
    const float* __restrict__ X, const float* __restrict__ W, int NLD,
    uint32_t* smem, const GemmCtx& cx, float c[4][4][4]) {
    int tid = threadIdx.x;
    int ar  = tid >> 3, ac4 = (tid & 7) * 4;
    int br  = tid >> 5, bc4 = (tid & 31) * 4;
    uint32_t base = smem_u32(smem);

    auto issue = [&](int s, int kt) {
        uint32_t ab = base + (s * AW) * 4;
#pragma unroll
        for (int i = 0; i < 4; i++) {
            int r = ar + 32 * i;
            cpa16(ab + (r * LDA2 + ac4) * 4,
                  X + (size_t)(cx.rowBase + r) * 256 + kt + ac4);
        }
        uint32_t bb = base + (2 * AW + s * BW) * 4;
#pragma unroll
        for (int i = 0; i < 4; i++) {
            int r = br + 8 * i;
            cpa16(bb + (r * LDB2 + bc4) * 4,
                  W + (size_t)(kt + r) * NLD + cx.colBase + bc4);
        }
        asm volatile("cp.async.commit_group;");
    };

    issue(0, 0);

#pragma unroll 1
    for (int it = 0; it < 8; it++) {
        if (it < 7) {
            issue((it + 1) & 1, (it + 1) * TBK);
            asm volatile("cp.async.wait_group 1;");
        } else {
            asm volatile("cp.async.wait_group 0;");
        }
        __syncthreads();

        uint32_t* As = smem + (it & 1) * AW;
        uint32_t* Bs = smem + 2 * AW + (it & 1) * BW;
#pragma unroll
        for (int kk = 0; kk < TBK; kk += 8) {
            uint32_t a[4][4], b[4][2];
#pragma unroll
            for (int mi = 0; mi < 4; mi++) {
                int r0 = (cx.wm + mi * 16 + cx.g) * LDA2 + kk + cx.tg;
                a[mi][0] = As[r0];
                a[mi][1] = As[r0 + 8 * LDA2];
                a[mi][2] = As[r0 + 4];
                a[mi][3] = As[r0 + 8 * LDA2 + 4];
            }
#pragma unroll
            for (int ni = 0; ni < 4; ni++) {
                int n = cx.wn + ni * 8 + cx.g;
                b[ni][0] = Bs[(kk + cx.tg) * LDB2 + n];
                b[ni][1] = Bs[(kk + cx.tg + 4) * LDB2 + n];
            }
#pragma unroll
            for (int mi = 0; mi < 4; mi++)
#pragma unroll
                for (int ni = 0; ni < 4; ni++)
                    mma_tf32(c[mi][ni], a[mi], b[ni]);
        }
        __syncthreads();
    }
}

// GEMM 1: qkv = Xr @ Wq[256,768], scatter into g_qkv (tf32-rounded stores)
__global__ __launch_bounds__(256, 2)
void gemm_qkv_tc(const float* __restrict__ X, const float* __restrict__ W) {
    extern __shared__ uint32_t smg[];
    int tid = threadIdx.x;
    GemmCtx cx;
    int lane = tid & 31, warp = tid >> 5;
    cx.g = lane >> 2; cx.tg = lane & 3;
    cx.wm = (warp >> 2) * 64; cx.wn = (warp & 3) * 32;
    cx.rowBase = blockIdx.y * 128; cx.colBase = blockIdx.x * 128;

    float c[4][4][4];
#pragma unroll
    for (int mi = 0; mi < 4; mi++)
#pragma unroll
        for (int ni = 0; ni < 4; ni++)
#pragma unroll
            for (int r = 0; r < 4; r++) c[mi][ni][r] = 0.f;

    gemm_mainloop_ca(X, W, 768, smg, cx, c);

#pragma unroll
    for (int mi = 0; mi < 4; mi++) {
        int r0 = cx.rowBase + cx.wm + mi * 16 + cx.g;
        int r1 = r0 + 8;
        int b0 = r0 / SEQ_N, n0 = r0 - b0 * SEQ_N;
        int b1 = r1 / SEQ_N, n1 = r1 - b1 * SEQ_N;
#pragma unroll
        for (int ni = 0; ni < 4; ni++) {
            int col   = cx.colBase + cx.wn + ni * 8 + 2 * cx.tg;
            int which = col >> 8;
            int h     = (col >> 5) & 7;
            int d0    = col & 31;
            size_t base0 = ((size_t)which * BH_TOT + b0 * HEADS + h) * HS + (size_t)n0 * DH + d0;
            size_t base1 = ((size_t)which * BH_TOT + b1 * HEADS + h) * HS + (size_t)n1 * DH + d0;
            // tf32-round so attention can cp.async raw bits
            *(float2*)&g_qkv[base0] = make_float2(f2tff(c[mi][ni][0]), f2tff(c[mi][ni][1]));
            *(float2*)&g_qkv[base1] = make_float2(f2tff(c[mi][ni][2]), f2tff(c[mi][ni][3]));
        }
    }
}

// GEMM 2: out = g_attnout @ Wp[256,256] + proj_b
__global__ __launch_bounds__(256, 2)
void gemm_proj_tc(const float* __restrict__ W, const float* __restrict__ bias,
                  float* __restrict__ Out) {
    extern __shared__ uint32_t smg[];
    int tid = threadIdx.x;
    GemmCtx cx;
    int lane = tid & 31, warp = tid >> 5;
    cx.g = lane >> 2; cx.tg = lane & 3;
    cx.wm = (warp >> 2) * 64; cx.wn = (warp & 3) * 32;
    cx.rowBase = blockIdx.y * 128; cx.colBase = blockIdx.x * 128;

    float c[4][4][4];
#pragma unroll
    for (int mi = 0; mi < 4; mi++)
#pragma unroll
        for (int ni = 0; ni < 4; ni++)
#pragma unroll
            for (int r = 0; r < 4; r++) c[mi][ni][r] = 0.f;

    gemm_mainloop_ca(g_attnout, W, 256, smg, cx, c);

#pragma unroll
    for (int mi = 0; mi < 4; mi++) {
        int r0 = cx.rowBase + cx.wm + mi * 16 + cx.g;
        int r1 = r0 + 8;
#pragma unroll
        for (int ni = 0; ni < 4; ni++) {
            int col = cx.colBase + cx.wn + ni * 8 + 2 * cx.tg;
            float bx = bias[col], by = bias[col + 1];
            *(float2*)&Out[(size_t)r0 * 256 + col] =
                make_float2(c[mi][ni][0] + bx, c[mi][ni][1] + by);
            *(float2*)&Out[(size_t)r1 * 256 + col] =
                make_float2(c[mi][ni][2] + bx, c[mi][ni][3] + by);
        }
    }
}

// ---------------------------------------------------------------------------
// Attention v4: ONE block per (b,h), 256 threads = 8 warps, 16 rows each.
//  - k/v loaded ONCE per head (halves L2/DRAM traffic vs half-block scheme)
//  - q A-fragments straight from gmem; cp.async k/v (pre-rounded tf32 bits)
//  - warp 7 (rows 112-127, all invalid) exits right after the load barrier
//  - sP warp-private -> no block barrier between S and O phases
// smem words: k 112*36 | v 112*40 | P 112*116 = 21504 (86016 B) -> 2 CTAs/SM
// ---------------------------------------------------------------------------
#define LDK  36
#define LDVM 40
#define LDP  116
#define BOFF_V (112 * LDK)              // 4032
#define BOFF_P (BOFF_V + 112 * LDVM)    // 8512
#define ATTN_SMEM_BYTES ((BOFF_P + 112 * LDP) * 4)   // 86016

__global__ __launch_bounds__(256, 2)
void attn_tc() {
    extern __shared__ uint32_t sm[];
    uint32_t* sk = sm;
    uint32_t* sv = sm + BOFF_V;
    uint32_t* sP = sm + BOFF_P;

    int tid  = threadIdx.x;
    int bh   = blockIdx.x;
    int b = bh >> 3, h = bh & 7;
    const float* gq = g_qkv + (size_t)bh * HS;
    const float* gk = gq + QKV_ONE;
    const float* gv = gq + 2 * QKV_ONE;
    uint32_t skb = smem_u32(sk), svb = smem_u32(sv);

    // ---- async k [98][32] -> sk[n][d], v [98][32] -> sv[m][d] ----
    for (int i = tid; i < 784; i += 256) {
        int r = i >> 3, c4 = (i & 7) * 4;
        cpa16(skb + (r * LDK + c4) * 4, gk + r * 32 + c4);
    }
    for (int i = tid; i < 784; i += 256) {
        int m = i >> 3, d4 = (i & 7) * 4;
        cpa16(svb + (m * LDVM + d4) * 4, gv + m * 32 + d4);
    }
    asm volatile("cp.async.commit_group;");

    int lane = tid & 31, warp = tid >> 5;
    int g = lane >> 2, tg = lane & 3;
    int n0 = warp * 16 + g, n1 = n0 + 8;     // global row == local row
    bool rv0 = (n0 < SEQ_N), rv1 = (n1 < SEQ_N);

    // ---- q A-fragments straight from gmem (overlaps cp.async) ----
    uint32_t aF[4][4];
#pragma unroll
    for (int kk = 0; kk < 4; kk++) {
        int c = kk * 8 + tg;
        aF[kk][0] = rv0 ? f2tf(gq[n0 * 32 + c] * SCALE) : 0u;
        aF[kk][1] = rv1 ? f2tf(gq[n1 * 32 + c] * SCALE) : 0u;
        aF[kk][2] = rv0 ? f2tf(gq[n0 * 32 + c + 4] * SCALE) : 0u;
        aF[kk][3] = rv1 ? f2tf(gq[n1 * 32 + c + 4] * SCALE) : 0u;
    }

    // ---- zero pads (rows 98..111) ----
    for (int i = tid; i < 448; i += 256) {
        int r = 98 + (i >> 5), d = i & 31;
        sk[r * LDK + d] = 0u;
    }
    for (int i = tid; i < 448; i += 256) {
        int m = 98 + (i >> 5), d = i & 31;
        sv[m * LDVM + d] = 0u;
    }
    asm volatile("cp.async.wait_group 0;");
    __syncthreads();

    // warp 7 covers rows 112..127 -> entirely invalid
    if (warp == 7) return;

    size_t bmbase = ((size_t)(b & (NW - 1)) * HEADS + h) * (SEQ_N * SEQ_N);
    const float* bmr0 = &g_bm[bmbase + (size_t)n0 * SEQ_N];
    const float* bmr1 = &g_bm[bmbase + (size_t)n1 * SEQ_N];

    // ---- S phase ----
    float sum0 = 0.f, sum1 = 0.f;
#pragma unroll
    for (int h2 = 0; h2 < 2; h2++) {
        float2 pA[7], pB[7];
#pragma unroll
        for (int j = 0; j < 7; j++) {
            int c0 = (h2 * 7 + j) * 8 + 2 * tg;
            bool cvj = (c0 < SEQ_N);
            float2 t0 = make_float2(0.f, 0.f), t1 = make_float2(0.f, 0.f);
            if (rv0 && cvj) t0 = *(const float2*)&bmr0[c0];
            if (rv1 && cvj) t1 = *(const float2*)&bmr1[c0];
            pA[j] = t0; pB[j] = t1;
        }
#pragma unroll
        for (int j = 0; j < 7; j++) {
            int ni = h2 * 7 + j;
            float acc[4] = {0.f, 0.f, 0.f, 0.f};
#pragma unroll
            for (int kk = 0; kk < 4; kk++) {
                uint32_t bF[2];
                int nr = ni * 8 + g;
                bF[0] = sk[nr * LDK + kk * 8 + tg];
                bF[1] = sk[nr * LDK + kk * 8 + tg + 4];
                mma_tf32(acc, aF[kk], bF);
            }
            int c0 = ni * 8 + 2 * tg;
            bool cv = (c0 < SEQ_N);
            float e00 = 0.f, e01 = 0.f, e10 = 0.f, e11 = 0.f;
            if (cv && rv0) {
                e00 = fastexp(acc[0] + pA[j].x);
                e01 = fastexp(acc[1] + pA[j].y);
            }
            if (cv && rv1) {
                e10 = fastexp(acc[2] + pB[j].x);
                e11 = fastexp(acc[3] + pB[j].y);
            }
            uint32_t u00 = f2tf(e00), u01 = f2tf(e01);
            uint32_t u10 = f2tf(e10), u11 = f2tf(e11);
            sum0 += __uint_as_float(u00) + __uint_as_float(u01);
            sum1 += __uint_as_float(u10) + __uint_as_float(u11);
            *(uint2*)&sP[n0 * LDP + c0] = make_uint2(u00, u01);
            *(uint2*)&sP[n1 * LDP + c0] = make_uint2(u10, u11);
        }
    }
    // rowsum across the 4-lane quad (result lands in all 4 lanes)
    sum0 += __shfl_xor_sync(0xffffffffu, sum0, 1);
    sum0 += __shfl_xor_sync(0xffffffffu, sum0, 2);
    sum1 += __shfl_xor_sync(0xffffffffu, sum1, 1);
    sum1 += __shfl_xor_sync(0xffffffffu, sum1, 2);
    float inv0 = rv0 ? (1.0f / sum0) : 0.f;
    float inv1 = rv1 ? (1.0f / sum1) : 0.f;

    // sP is warp-private (rows 16*warp..16*warp+15): warp-level sync suffices
    __syncwarp();

    // ---- O phase: O = P . v ----
    float oacc[4][4];
#pragma unroll
    for (int ni = 0; ni < 4; ni++)
#pragma unroll
        for (int r = 0; r < 4; r++) oacc[ni][r] = 0.f;

#pragma unroll
    for (int kk = 0; kk < 14; kk++) {
        uint32_t aO[4];
        int base = n0 * LDP + kk * 8 + tg;
        aO[0] = sP[base];
        aO[1] = sP[base + 8 * LDP];
        aO[2] = sP[base + 4];
        aO[3] = sP[base + 8 * LDP + 4];
#pragma unroll
        for (int ni = 0; ni < 4; ni++) {
            uint32_t bO[2];
            int vr = ni * 8 + g;
            bO[0] = sv[(kk * 8 + tg) * LDVM + vr];
            bO[1] = sv[(kk * 8 + tg + 4) * LDVM + vr];
            mma_tf32(oacc[ni], aO, bO);
        }
    }

    // stores tf32-rounded so proj GEMM can consume raw bits via cp.async
    if (rv0) {
        size_t ob = ((size_t)b * SEQ_N + n0) * CH + h * DH;
#pragma unroll
        for (int ni = 0; ni < 4; ni++) {
            int d0 = ni * 8 + 2 * tg;
            *(float2*)&g_attnout[ob + d0] =
                make_float2(f2tff(oacc[ni][0] * inv0), f2tff(oacc[ni][1] * inv0));
        }
    }
    if (rv1) {
        size_t ob = ((size_t)b * SEQ_N + n1) * CH + h * DH;
#pragma unroll
        for (int ni = 0; ni < 4; ni++) {
            int d0 = ni * 8 + 2 * tg;
            *(float2*)&g_attnout[ob + d0] =
                make_float2(f2tff(oacc[ni][2] * inv1), f2tff(oacc[ni][3] * inv1));
        }
    }
}

// ---------------------------------------------------------------------------
// Launch
// ---------------------------------------------------------------------------
extern "C" void kernel_launch(void* const* d_in, const int* in_sizes, int n_in,
                              void* d_out, int out_size) {
    const float* x       = (const float*)d_in[0];
    const float* mask    = (const float*)d_in[1];
    const float* qkv_w   = (const float*)d_in[2];
    const float* proj_w  = (const float*)d_in[3];
    const float* proj_b  = (const float*)d_in[4];
    const float* table   = (const float*)d_in[5];
    float* out           = (float*)d_out;

    static bool attr_done = false;
    if (!attr_done) {
        cudaFuncSetAttribute(attn_tc, cudaFuncAttributeMaxDynamicSharedMemorySize,
                             ATTN_SMEM_BYTES);
        cudaFuncSetAttribute(gemm_qkv_tc, cudaFuncAttributeMaxDynamicSharedMemorySize,
                             GEMM_SMEM_BYTES);
        cudaFuncSetAttribute(gemm_proj_tc, cudaFuncAttributeMaxDynamicSharedMemorySize,
                             GEMM_SMEM_BYTES);
        attr_done = true;
    }

    float* xr = nullptr; float* wq = nullptr; float* wp = nullptr;
    cudaGetSymbolAddress((void**)&xr, g_xr);
    cudaGetSymbolAddress((void**)&wq, g_wq);
    cudaGetSymbolAddress((void**)&wp, g_wp);

    // 0a) tf32-round GEMM inputs
    {
        int n4x = M_TOT * CH / 4;
        tf32_round4<<<(n4x + 255) / 256, 256>>>((const float4*)x, (float4*)xr, n4x);
        int n4q = CH * 3 * CH / 4;
        tf32_round4<<<(n4q + 255) / 256, 256>>>((const float4*)qkv_w, (float4*)wq, n4q);
        int n4p = CH * CH / 4;
        tf32_round4<<<(n4p + 255) / 256, 256>>>((const float4*)proj_w, (float4*)wp, n4p);
    }
    // 0b) bias+mask precompute
    {
        int tot = NW * HEADS * SEQ_N * SEQ_N;
        bm_kernel<<<(tot + 255) / 256, 256>>>(mask, table);
    }
    // 1) qkv GEMM (tf32 tensor cores, cp.async pipelined, rounded stores)
    gemm_qkv_tc<<<dim3(768 / 128, M_TOT / 128), 256, GEMM_SMEM_BYTES>>>(xr, wq);
    // 2) attention: one block per (b,h)
    attn_tc<<<BH_TOT, 256, ATTN_SMEM_BYTES>>>();
    // 3) proj GEMM + bias (tf32 tensor cores, cp.async pipelined)
    gemm_proj_tc<<<dim3(256 / 128, M_TOT / 128), 256, GEMM_SMEM_BYTES>>>(wp, proj_b, out);
}

// round 13
// speedup vs baseline: 3.5973x; 1.0221x over previous
#include <cuda_runtime.h>
#include <cuda_bf16.h>
#include <cstdint>
#include <cstddef>

// ---------------------------------------------------------------------------
// Problem constants
// ---------------------------------------------------------------------------
#define B_TOT   2048
#define SEQ_N   98
#define CH      256
#define HEADS   8
#define DH      32
#define NW      64
#define M_TOT   (B_TOT * SEQ_N)        // 200704
#define BH_TOT  (B_TOT * HEADS)        // 16384
#define HS      (SEQ_N * DH)           // 3136
#define QKV_ONE ((size_t)BH_TOT * HS)  // 51380224
#define SCALE   0.17677669529663687f   // 1/sqrt(32)

// ---------------------------------------------------------------------------
// Device-global scratch
// ---------------------------------------------------------------------------
__device__ float g_qkv[3ull * QKV_ONE];           // [which][b*H+h][n][d] (tf32)
__device__ float g_attnout[(size_t)M_TOT * CH];   // [b][n][c] (tf32-rounded)
__device__ float g_bm[(size_t)NW * HEADS * SEQ_N * SEQ_N];  // bias+mask
__device__ float g_xr[(size_t)M_TOT * CH];        // tf32-rounded X
__device__ float g_wq[3 * CH * CH];               // tf32-rounded qkv_w, [N][K]
__device__ float g_wp[CH * CH];                   // tf32-rounded proj_w, [N][K]

// ---------------------------------------------------------------------------
// tf32 helpers
// ---------------------------------------------------------------------------
__device__ __forceinline__ uint32_t f2tf(float v) {
    uint32_t r;
    asm("cvt.rna.tf32.f32 %0, %1;" : "=r"(r) : "f"(v));
    return r;
}
__device__ __forceinline__ float f2tff(float v) { return __uint_as_float(f2tf(v)); }

__device__ __forceinline__ void mma_tf32(float* c, const uint32_t* a, const uint32_t* b) {
    asm volatile(
        "mma.sync.aligned.m16n8k8.row.col.f32.tf32.tf32.f32 "
        "{%0,%1,%2,%3}, {%4,%5,%6,%7}, {%8,%9}, {%0,%1,%2,%3};\n"
        : "+f"(c[0]), "+f"(c[1]), "+f"(c[2]), "+f"(c[3])
        : "r"(a[0]), "r"(a[1]), "r"(a[2]), "r"(a[3]),
          "r"(b[0]), "r"(b[1]));
}

// ldmatrix x4 (b16 view of tf32 data: lane -> 32-bit element (l/4, l%4))
__device__ __forceinline__ void ldsm4(uint32_t& d0, uint32_t& d1, uint32_t& d2,
                                      uint32_t& d3, uint32_t addr) {
    asm volatile("ldmatrix.sync.aligned.m8n8.x4.shared.b16 {%0,%1,%2,%3}, [%4];"
                 : "=r"(d0), "=r"(d1), "=r"(d2), "=r"(d3) : "r"(addr));
}

// fast exp on FMA pipe
__device__ __forceinline__ float fastexp(float s) {
    float t  = s * 1.4426950408889634f;
    float fr = t + 12582912.0f;            // 1.5 * 2^23
    float rn = fr - 12582912.0f;
    float f  = t - rn;
    float p  = 1.3333558146428443e-3f;
    p = fmaf(p, f, 9.618129107628477e-3f);
    p = fmaf(p, f, 5.550410866482158e-2f);
    p = fmaf(p, f, 2.402265069591007e-1f);
    p = fmaf(p, f, 6.931471805599453e-1f);
    p = fmaf(p, f, 1.0f);
    int ei = (int)((unsigned)__float_as_int(fr) << 23);
    return __int_as_float(__float_as_int(p) + ei);
}

// cp.async 16B
__device__ __forceinline__ void cpa16(uint32_t dst, const void* src) {
    asm volatile("cp.async.cg.shared.global [%0], [%1], 16;" :: "r"(dst), "l"(src));
}
__device__ __forceinline__ uint32_t smem_u32(const void* p) {
    return (uint32_t)__cvta_generic_to_shared(p);
}

// ---------------------------------------------------------------------------
// Kernel: tf32-round a float array (vectorized)
// ---------------------------------------------------------------------------
__global__ void tf32_round4(const float4* __restrict__ src, float4* __restrict__ dst,
                            int n4) {
    int i = blockIdx.x * 256 + threadIdx.x;
    if (i < n4) {
        float4 v = src[i];
        dst[i] = make_float4(f2tff(v.x), f2tff(v.y), f2tff(v.z), f2tff(v.w));
    }
}

// Kernel: tf32-round + transpose W [K][N] -> [N][K]
__global__ void round_transpose(const float* __restrict__ src, float* __restrict__ dst,
                                int K, int N) {
    int i = blockIdx.x * 256 + threadIdx.x;
    if (i < K * N) {
        int k = i / N, n = i % N;
        dst[n * K + k] = f2tff(src[i]);
    }
}

// ---------------------------------------------------------------------------
// Kernel 0: precompute bias(rel-pos) + mask  ->  g_bm[wi][h][n][m]
// ---------------------------------------------------------------------------
__global__ void bm_kernel(const float* __restrict__ mask,
                          const float* __restrict__ table) {
    int i = blockIdx.x * 256 + threadIdx.x;
    const int TOT = NW * HEADS * SEQ_N * SEQ_N;
    if (i >= TOT) return;
    int m  = i % SEQ_N;
    int r  = i / SEQ_N;
    int n  = r % SEQ_N;  r /= SEQ_N;
    int h  = r & 7;
    int wi = r >> 3;
    int dn = n / 49, hn = (n % 49) / 7, wn = n % 7;
    int dm = m / 49, hm = (m % 49) / 7, wm = m % 7;
    int rid = (dn - dm + 1) * 169 + (hn - hm + 6) * 13 + (wn - wm + 6);
    g_bm[i] = table[rid * HEADS + h] + mask[(size_t)wi * SEQ_N * SEQ_N + n * SEQ_N + m];
}

// ---------------------------------------------------------------------------
// tf32 GEMM, cp.async 2-stage, ldmatrix frag loads. Block 128x128, BK=32.
// A [M][K] row-major (pre-rounded), B = W^T [N][K] n-major (pre-rounded).
// Both smem tiles are 128 rows x 32 cols, stride LDA2=36 words.
// smem: 4 stages x 4608 words = 73728 B
// ---------------------------------------------------------------------------
#define TBK  32
#define LDA2 36
#define AW   (128 * LDA2)      // 4608 words per tile stage
#define GEMM_SMEM_BYTES (4 * AW * 4)   // 73728

struct GemmCtx {
    int rowBase, colBase;
    int wm, wn;
};

__device__ __forceinline__ void gemm_mainloop_ca(
    const float* __restrict__ X, const float* __restrict__ Wt,
    uint32_t* smem, const GemmCtx& cx, float c[4][4][4]) {
    int tid = threadIdx.x;
    int ar  = tid >> 3, ac4 = (tid & 7) * 4;
    uint32_t base = smem_u32(smem);

    int lane = tid & 31;
    int t = lane >> 3, r8 = lane & 7;
    // A-frag lane offset: m8n8 tiles (rows, k), (rows+8, k), (rows, k+4), (rows+8, k+4)
    int laneA = ((t & 1) * 8 + r8) * LDA2 + (t >> 1) * 4;
    // B-frag lane offset: tiles (n, k), (n, k+4), (n+8, k), (n+8, k+4)
    int laneB = ((t >> 1) * 8 + r8) * LDA2 + (t & 1) * 4;

    auto issue = [&](int s, int kt) {
        uint32_t ab = base + (s * AW) * 4;
#pragma unroll
        for (int i = 0; i < 4; i++) {
            int r = ar + 32 * i;
            cpa16(ab + (r * LDA2 + ac4) * 4,
                  X + (size_t)(cx.rowBase + r) * 256 + kt + ac4);
        }
        uint32_t bb = base + ((2 + s) * AW) * 4;
#pragma unroll
        for (int i = 0; i < 4; i++) {
            int r = ar + 32 * i;
            cpa16(bb + (r * LDA2 + ac4) * 4,
                  Wt + (size_t)(cx.colBase + r) * 256 + kt + ac4);
        }
        asm volatile("cp.async.commit_group;");
    };

    issue(0, 0);

#pragma unroll 1
    for (int it = 0; it < 8; it++) {
        if (it < 7) {
            issue((it + 1) & 1, (it + 1) * TBK);
            asm volatile("cp.async.wait_group 1;");
        } else {
            asm volatile("cp.async.wait_group 0;");
        }
        __syncthreads();

        uint32_t Ab = base + ((it & 1) * AW) * 4;
        uint32_t Bb = base + ((2 + (it & 1)) * AW) * 4;
#pragma unroll
        for (int kk = 0; kk < TBK; kk += 8) {
            uint32_t a[4][4], b[4][2];
#pragma unroll
            for (int mi = 0; mi < 4; mi++)
                ldsm4(a[mi][0], a[mi][1], a[mi][2], a[mi][3],
                      Ab + (((cx.wm + mi * 16) * LDA2 + kk) + laneA) * 4);
            ldsm4(b[0][0], b[0][1], b[1][0], b[1][1],
                  Bb + ((cx.wn * LDA2 + kk) + laneB) * 4);
            ldsm4(b[2][0], b[2][1], b[3][0], b[3][1],
                  Bb + (((cx.wn + 16) * LDA2 + kk) + laneB) * 4);
#pragma unroll
            for (int mi = 0; mi < 4; mi++)
#pragma unroll
                for (int ni = 0; ni < 4; ni++)
                    mma_tf32(c[mi][ni], a[mi], b[ni]);
        }
        __syncthreads();
    }
}

// GEMM 1: qkv = Xr @ Wq^T-view, scatter into g_qkv (tf32-rounded stores)
__global__ __launch_bounds__(256, 2)
void gemm_qkv_tc(const float* __restrict__ X, const float* __restrict__ Wt) {
    extern __shared__ uint32_t smg[];
    int tid = threadIdx.x;
    int lane = tid & 31, warp = tid >> 5;
    int g = lane >> 2, tg = lane & 3;
    GemmCtx cx;
    cx.wm = (warp >> 2) * 64; cx.wn = (warp & 3) * 32;
    cx.rowBase = blockIdx.y * 128; cx.colBase = blockIdx.x * 128;

    float c[4][4][4];
#pragma unroll
    for (int mi = 0; mi < 4; mi++)
#pragma unroll
        for (int ni = 0; ni < 4; ni++)
#pragma unroll
            for (int r = 0; r < 4; r++) c[mi][ni][r] = 0.f;

    gemm_mainloop_ca(X, Wt, smg, cx, c);

#pragma unroll
    for (int mi = 0; mi < 4; mi++) {
        int r0 = cx.rowBase + cx.wm + mi * 16 + g;
        int r1 = r0 + 8;
        int b0 = r0 / SEQ_N, n0 = r0 - b0 * SEQ_N;
        int b1 = r1 / SEQ_N, n1 = r1 - b1 * SEQ_N;
#pragma unroll
        for (int ni = 0; ni < 4; ni++) {
            int col   = cx.colBase + cx.wn + ni * 8 + 2 * tg;
            int which = col >> 8;
            int h     = (col >> 5) & 7;
            int d0    = col & 31;
            size_t base0 = ((size_t)which * BH_TOT + b0 * HEADS + h) * HS + (size_t)n0 * DH + d0;
            size_t base1 = ((size_t)which * BH_TOT + b1 * HEADS + h) * HS + (size_t)n1 * DH + d0;
            // tf32-round so attention can cp.async raw bits
            *(float2*)&g_qkv[base0] = make_float2(f2tff(c[mi][ni][0]), f2tff(c[mi][ni][1]));
            *(float2*)&g_qkv[base1] = make_float2(f2tff(c[mi][ni][2]), f2tff(c[mi][ni][3]));
        }
    }
}

// GEMM 2: out = g_attnout @ Wp^T-view + proj_b
__global__ __launch_bounds__(256, 2)
void gemm_proj_tc(const float* __restrict__ Wt, const float* __restrict__ bias,
                  float* __restrict__ Out) {
    extern __shared__ uint32_t smg[];
    int tid = threadIdx.x;
    int lane = tid & 31, warp = tid >> 5;
    int g = lane >> 2, tg = lane & 3;
    GemmCtx cx;
    cx.wm = (warp >> 2) * 64; cx.wn = (warp & 3) * 32;
    cx.rowBase = blockIdx.y * 128; cx.colBase = blockIdx.x * 128;

    float c[4][4][4];
#pragma unroll
    for (int mi = 0; mi < 4; mi++)
#pragma unroll
        for (int ni = 0; ni < 4; ni++)
#pragma unroll
            for (int r = 0; r < 4; r++) c[mi][ni][r] = 0.f;

    gemm_mainloop_ca(g_attnout, Wt, smg, cx, c);

#pragma unroll
    for (int mi = 0; mi < 4; mi++) {
        int r0 = cx.rowBase + cx.wm + mi * 16 + g;
        int r1 = r0 + 8;
#pragma unroll
        for (int ni = 0; ni < 4; ni++) {
            int col = cx.colBase + cx.wn + ni * 8 + 2 * tg;
            float bx = bias[col], by = bias[col + 1];
            *(float2*)&Out[(size_t)r0 * 256 + col] =
                make_float2(c[mi][ni][0] + bx, c[mi][ni][1] + by);
            *(float2*)&Out[(size_t)r1 * 256 + col] =
                make_float2(c[mi][ni][2] + bx, c[mi][ni][3] + by);
        }
    }
}

// ---------------------------------------------------------------------------
// Attention v5: ONE block per (b,h), 256 threads = 8 warps, 16 rows each.
//  - k/v loaded once per head via cp.async (pre-rounded tf32 bits)
//  - q A-fragments straight from gmem
//  - S-phase k-frags and O-phase P-frags via ldmatrix (2 / 1 LDSM per group)
//  - warp 7 (rows 112-127, invalid) exits after the load barrier
// smem words: k 112*36 | v 112*40 | P 112*116 = 21504 (86016 B) -> 2 CTAs/SM
// ---------------------------------------------------------------------------
#define LDK  36
#define LDVM 40
#define LDP  116
#define BOFF_V (112 * LDK)              // 4032
#define BOFF_P (BOFF_V + 112 * LDVM)    // 8512
#define ATTN_SMEM_BYTES ((BOFF_P + 112 * LDP) * 4)   // 86016

__global__ __launch_bounds__(256, 2)
void attn_tc() {
    extern __shared__ uint32_t sm[];
    uint32_t* sk = sm;
    uint32_t* sv = sm + BOFF_V;
    uint32_t* sP = sm + BOFF_P;

    int tid  = threadIdx.x;
    int bh   = blockIdx.x;
    int b = bh >> 3, h = bh & 7;
    const float* gq = g_qkv + (size_t)bh * HS;
    const float* gk = gq + QKV_ONE;
    const float* gv = gq + 2 * QKV_ONE;
    uint32_t skb = smem_u32(sk), svb = smem_u32(sv);
    uint32_t sPb = smem_u32(sP);

    // ---- async k [98][32] -> sk[n][d], v [98][32] -> sv[m][d] ----
    for (int i = tid; i < 784; i += 256) {
        int r = i >> 3, c4 = (i & 7) * 4;
        cpa16(skb + (r * LDK + c4) * 4, gk + r * 32 + c4);
    }
    for (int i = tid; i < 784; i += 256) {
        int m = i >> 3, d4 = (i & 7) * 4;
        cpa16(svb + (m * LDVM + d4) * 4, gv + m * 32 + d4);
    }
    asm volatile("cp.async.commit_group;");

    int lane = tid & 31, warp = tid >> 5;
    int g = lane >> 2, tg = lane & 3;
    int t8 = lane >> 3, r8 = lane & 7;
    int n0 = warp * 16 + g, n1 = n0 + 8;
    bool rv0 = (n0 < SEQ_N), rv1 = (n1 < SEQ_N);

    // ---- q A-fragments straight from gmem (overlaps cp.async) ----
    uint32_t aF[4][4];
#pragma unroll
    for (int kk = 0; kk < 4; kk++) {
        int c = kk * 8 + tg;
        aF[kk][0] = rv0 ? f2tf(gq[n0 * 32 + c] * SCALE) : 0u;
        aF[kk][1] = rv1 ? f2tf(gq[n1 * 32 + c] * SCALE) : 0u;
        aF[kk][2] = rv0 ? f2tf(gq[n0 * 32 + c + 4] * SCALE) : 0u;
        aF[kk][3] = rv1 ? f2tf(gq[n1 * 32 + c + 4] * SCALE) : 0u;
    }

    // ---- zero pads (rows 98..111) ----
    for (int i = tid; i < 448; i += 256) {
        int r = 98 + (i >> 5), d = i & 31;
        sk[r * LDK + d] = 0u;
    }
    for (int i = tid; i < 448; i += 256) {
        int m = 98 + (i >> 5), d = i & 31;
        sv[m * LDVM + d] = 0u;
    }
    asm volatile("cp.async.wait_group 0;");
    __syncthreads();

    // warp 7 covers rows 112..127 -> entirely invalid
    if (warp == 7) return;

    size_t bmbase = ((size_t)(b & (NW - 1)) * HEADS + h) * (SEQ_N * SEQ_N);
    const float* bmr0 = &g_bm[bmbase + (size_t)n0 * SEQ_N];
    const float* bmr1 = &g_bm[bmbase + (size_t)n1 * SEQ_N];

    // ldmatrix lane offsets (words)
    int laneS = r8 * LDK + t8 * 4;                       // k-frags: tiles k=0,4,8,12
    int laneO = ((t8 & 1) * 8 + r8) * LDP + (t8 >> 1) * 4;  // P A-frags

    // ---- S phase ----
    float sum0 = 0.f, sum1 = 0.f;
#pragma unroll
    for (int h2 = 0; h2 < 2; h2++) {
        float2 pA[7], pB[7];
#pragma unroll
        for (int j = 0; j < 7; j++) {
            int c0 = (h2 * 7 + j) * 8 + 2 * tg;
            bool cvj = (c0 < SEQ_N);
            float2 t0 = make_float2(0.f, 0.f), t1 = make_float2(0.f, 0.f);
            if (rv0 && cvj) t0 = *(const float2*)&bmr0[c0];
            if (rv1 && cvj) t1 = *(const float2*)&bmr1[c0];
            pA[j] = t0; pB[j] = t1;
        }
#pragma unroll
        for (int j = 0; j < 7; j++) {
            int ni = h2 * 7 + j;
            uint32_t bF[4][2];
            uint32_t sbase = skb + (ni * 8 * LDK + laneS) * 4;
            ldsm4(bF[0][0], bF[0][1], bF[1][0], bF[1][1], sbase);        // k 0..15
            ldsm4(bF[2][0], bF[2][1], bF[3][0], bF[3][1], sbase + 64);   // k 16..31
            float acc[4] = {0.f, 0.f, 0.f, 0.f};
#pragma unroll
            for (int kk = 0; kk < 4; kk++)
                mma_tf32(acc, aF[kk], bF[kk]);
            int c0 = ni * 8 + 2 * tg;
            bool cv = (c0 < SEQ_N);
            float e00 = 0.f, e01 = 0.f, e10 = 0.f, e11 = 0.f;
            if (cv && rv0) {
                e00 = fastexp(acc[0] + pA[j].x);
                e01 = fastexp(acc[1] + pA[j].y);
            }
            if (cv && rv1) {
                e10 = fastexp(acc[2] + pB[j].x);
                e11 = fastexp(acc[3] + pB[j].y);
            }
            uint32_t u00 = f2tf(e00), u01 = f2tf(e01);
            uint32_t u10 = f2tf(e10), u11 = f2tf(e11);
            sum0 += __uint_as_float(u00) + __uint_as_float(u01);
            sum1 += __uint_as_float(u10) + __uint_as_float(u11);
            *(uint2*)&sP[n0 * LDP + c0] = make_uint2(u00, u01);
            *(uint2*)&sP[n1 * LDP + c0] = make_uint2(u10, u11);
        }
    }
    // rowsum across the 4-lane quad (result lands in all 4 lanes)
    sum0 += __shfl_xor_sync(0xffffffffu, sum0, 1);
    sum0 += __shfl_xor_sync(0xffffffffu, sum0, 2);
    sum1 += __shfl_xor_sync(0xffffffffu, sum1, 1);
    sum1 += __shfl_xor_sync(0xffffffffu, sum1, 2);
    float inv0 = rv0 ? (1.0f / sum0) : 0.f;
    float inv1 = rv1 ? (1.0f / sum1) : 0.f;

    // sP is warp-private (rows 16*warp..16*warp+15): warp-level sync suffices
    __syncwarp();

    // ---- O phase: O = P . v ----
    float oacc[4][4];
#pragma unroll
    for (int ni = 0; ni < 4; ni++)
#pragma unroll
        for (int r = 0; r < 4; r++) oacc[ni][r] = 0.f;

    uint32_t pbase = sPb + (warp * 16 * LDP + laneO) * 4;
#pragma unroll
    for (int kk = 0; kk < 14; kk++) {
        uint32_t aO[4];
        ldsm4(aO[0], aO[1], aO[2], aO[3], pbase + kk * 32);
#pragma unroll
        for (int ni = 0; ni < 4; ni++) {
            uint32_t bO[2];
            int vr = ni * 8 + g;
            bO[0] = sv[(kk * 8 + tg) * LDVM + vr];
            bO[1] = sv[(kk * 8 + tg + 4) * LDVM + vr];
            mma_tf32(oacc[ni], aO, bO);
        }
    }

    // stores tf32-rounded so proj GEMM can consume raw bits via cp.async
    if (rv0) {
        size_t ob = ((size_t)b * SEQ_N + n0) * CH + h * DH;
#pragma unroll
        for (int ni = 0; ni < 4; ni++) {
            int d0 = ni * 8 + 2 * tg;
            *(float2*)&g_attnout[ob + d0] =
                make_float2(f2tff(oacc[ni][0] * inv0), f2tff(oacc[ni][1] * inv0));
        }
    }
    if (rv1) {
        size_t ob = ((size_t)b * SEQ_N + n1) * CH + h * DH;
#pragma unroll
        for (int ni = 0; ni < 4; ni++) {
            int d0 = ni * 8 + 2 * tg;
            *(float2*)&g_attnout[ob + d0] =
                make_float2(f2tff(oacc[ni][2] * inv1), f2tff(oacc[ni][3] * inv1));
        }
    }
}

// ---------------------------------------------------------------------------
// Launch
// ---------------------------------------------------------------------------
extern "C" void kernel_launch(void* const* d_in, const int* in_sizes, int n_in,
                              void* d_out, int out_size) {
    const float* x       = (const float*)d_in[0];
    const float* mask    = (const float*)d_in[1];
    const float* qkv_w   = (const float*)d_in[2];
    const float* proj_w  = (const float*)d_in[3];
    const float* proj_b  = (const float*)d_in[4];
    const float* table   = (const float*)d_in[5];
    float* out           = (float*)d_out;

    static bool attr_done = false;
    if (!attr_done) {
        cudaFuncSetAttribute(attn_tc, cudaFuncAttributeMaxDynamicSharedMemorySize,
                             ATTN_SMEM_BYTES);
        cudaFuncSetAttribute(gemm_qkv_tc, cudaFuncAttributeMaxDynamicSharedMemorySize,
                             GEMM_SMEM_BYTES);
        cudaFuncSetAttribute(gemm_proj_tc, cudaFuncAttributeMaxDynamicSharedMemorySize,
                             GEMM_SMEM_BYTES);
        attr_done = true;
    }

    float* xr = nullptr; float* wq = nullptr; float* wp = nullptr;
    cudaGetSymbolAddress((void**)&xr, g_xr);
    cudaGetSymbolAddress((void**)&wq, g_wq);
    cudaGetSymbolAddress((void**)&wp, g_wp);

    // 0a) tf32-round X; round+transpose weights to [N][K]
    {
        int n4x = M_TOT * CH / 4;
        tf32_round4<<<(n4x + 255) / 256, 256>>>((const float4*)x, (float4*)xr, n4x);
        int nq = CH * 3 * CH;
        round_transpose<<<(nq + 255) / 256, 256>>>(qkv_w, wq, CH, 3 * CH);
        int np = CH * CH;
        round_transpose<<<(np + 255) / 256, 256>>>(proj_w, wp, CH, CH);
    }
    // 0b) bias+mask precompute
    {
        int tot = NW * HEADS * SEQ_N * SEQ_N;
        bm_kernel<<<(tot + 255) / 256, 256>>>(mask, table);
    }
    // 1) qkv GEMM (tf32 mma + ldmatrix + cp.async)
    gemm_qkv_tc<<<dim3(768 / 128, M_TOT / 128), 256, GEMM_SMEM_BYTES>>>(xr, wq);
    // 2) attention: one block per (b,h)
    attn_tc<<<BH_TOT, 256, ATTN_SMEM_BYTES>>>();
    // 3) proj GEMM + bias (tf32 mma + ldmatrix + cp.async)
    gemm_proj_tc<<<dim3(256 / 128, M_TOT / 128), 256, GEMM_SMEM_BYTES>>>(wp, proj_b, out);
}

// round 14
// speedup vs baseline: 3.7156x; 1.0329x over previous
#include <cuda_runtime.h>
#include <cuda_bf16.h>
#include <cstdint>
#include <cstddef>

// ---------------------------------------------------------------------------
// Problem constants
// ---------------------------------------------------------------------------
#define B_TOT   2048
#define SEQ_N   98
#define CH      256
#define HEADS   8
#define DH      32
#define NW      64
#define M_TOT   (B_TOT * SEQ_N)        // 200704
#define BH_TOT  (B_TOT * HEADS)        // 16384
#define HS      (SEQ_N * DH)           // 3136
#define QKV_ONE ((size_t)BH_TOT * HS)  // 51380224
#define SCALE   0.17677669529663687f   // 1/sqrt(32)

// ---------------------------------------------------------------------------
// Device-global scratch
// ---------------------------------------------------------------------------
__device__ float g_qkv[3ull * QKV_ONE];           // [which][b*H+h][n][d] (tf32)
__device__ float g_attnout[(size_t)M_TOT * CH];   // [b][n][c] (tf32-rounded)
__device__ float g_bm[(size_t)NW * HEADS * SEQ_N * SEQ_N];  // bias+mask
__device__ float g_xr[(size_t)M_TOT * CH];        // tf32-rounded X
__device__ float g_wq[3 * CH * CH];               // tf32-rounded qkv_w, [N][K]
__device__ float g_wp[CH * CH];                   // tf32-rounded proj_w, [N][K]

// ---------------------------------------------------------------------------
// tf32 helpers
// ---------------------------------------------------------------------------
__device__ __forceinline__ uint32_t f2tf(float v) {
    uint32_t r;
    asm("cvt.rna.tf32.f32 %0, %1;" : "=r"(r) : "f"(v));
    return r;
}
__device__ __forceinline__ float f2tff(float v) { return __uint_as_float(f2tf(v)); }

__device__ __forceinline__ void mma_tf32(float* c, const uint32_t* a, const uint32_t* b) {
    asm volatile(
        "mma.sync.aligned.m16n8k8.row.col.f32.tf32.tf32.f32 "
        "{%0,%1,%2,%3}, {%4,%5,%6,%7}, {%8,%9}, {%0,%1,%2,%3};\n"
        : "+f"(c[0]), "+f"(c[1]), "+f"(c[2]), "+f"(c[3])
        : "r"(a[0]), "r"(a[1]), "r"(a[2]), "r"(a[3]),
          "r"(b[0]), "r"(b[1]));
}

// ldmatrix x4 (b16 view of tf32 data: lane -> 32-bit element (l/4, l%4))
__device__ __forceinline__ void ldsm4(uint32_t& d0, uint32_t& d1, uint32_t& d2,
                                      uint32_t& d3, uint32_t addr) {
    asm volatile("ldmatrix.sync.aligned.m8n8.x4.shared.b16 {%0,%1,%2,%3}, [%4];"
                 : "=r"(d0), "=r"(d1), "=r"(d2), "=r"(d3) : "r"(addr));
}

// fast exp on FMA pipe
__device__ __forceinline__ float fastexp(float s) {
    float t  = s * 1.4426950408889634f;
    float fr = t + 12582912.0f;            // 1.5 * 2^23
    float rn = fr - 12582912.0f;
    float f  = t - rn;
    float p  = 1.3333558146428443e-3f;
    p = fmaf(p, f, 9.618129107628477e-3f);
    p = fmaf(p, f, 5.550410866482158e-2f);
    p = fmaf(p, f, 2.402265069591007e-1f);
    p = fmaf(p, f, 6.931471805599453e-1f);
    p = fmaf(p, f, 1.0f);
    int ei = (int)((unsigned)__float_as_int(fr) << 23);
    return __int_as_float(__float_as_int(p) + ei);
}

// cp.async 16B
__device__ __forceinline__ void cpa16(uint32_t dst, const void* src) {
    asm volatile("cp.async.cg.shared.global [%0], [%1], 16;" :: "r"(dst), "l"(src));
}
__device__ __forceinline__ uint32_t smem_u32(const void* p) {
    return (uint32_t)__cvta_generic_to_shared(p);
}

// ---------------------------------------------------------------------------
// Kernel: tf32-round a float array (vectorized)
// ---------------------------------------------------------------------------
__global__ void tf32_round4(const float4* __restrict__ src, float4* __restrict__ dst,
                            int n4) {
    int i = blockIdx.x * 256 + threadIdx.x;
    if (i < n4) {
        float4 v = src[i];
        dst[i] = make_float4(f2tff(v.x), f2tff(v.y), f2tff(v.z), f2tff(v.w));
    }
}

// Kernel: tf32-round + transpose W [K][N] -> [N][K]
__global__ void round_transpose(const float* __restrict__ src, float* __restrict__ dst,
                                int K, int N) {
    int i = blockIdx.x * 256 + threadIdx.x;
    if (i < K * N) {
        int k = i / N, n = i % N;
        dst[n * K + k] = f2tff(src[i]);
    }
}

// ---------------------------------------------------------------------------
// Kernel 0: precompute bias(rel-pos) + mask  ->  g_bm[wi][h][n][m]
// ---------------------------------------------------------------------------
__global__ void bm_kernel(const float* __restrict__ mask,
                          const float* __restrict__ table) {
    int i = blockIdx.x * 256 + threadIdx.x;
    const int TOT = NW * HEADS * SEQ_N * SEQ_N;
    if (i >= TOT) return;
    int m  = i % SEQ_N;
    int r  = i / SEQ_N;
    int n  = r % SEQ_N;  r /= SEQ_N;
    int h  = r & 7;
    int wi = r >> 3;
    int dn = n / 49, hn = (n % 49) / 7, wn = n % 7;
    int dm = m / 49, hm = (m % 49) / 7, wm = m % 7;
    int rid = (dn - dm + 1) * 169 + (hn - hm + 6) * 13 + (wn - wm + 6);
    g_bm[i] = table[rid * HEADS + h] + mask[(size_t)wi * SEQ_N * SEQ_N + n * SEQ_N + m];
}

// ---------------------------------------------------------------------------
// tf32 GEMM, cp.async 2-stage, ldmatrix frag loads. Block 128x128, BK=32.
// A [M][K] row-major (pre-rounded), B = W^T [N][K] n-major (pre-rounded).
// ---------------------------------------------------------------------------
#define TBK  32
#define LDA2 36
#define AW   (128 * LDA2)      // 4608 words per tile stage
#define GEMM_SMEM_BYTES (4 * AW * 4)   // 73728

struct GemmCtx {
    int rowBase, colBase;
    int wm, wn;
};

__device__ __forceinline__ void gemm_mainloop_ca(
    const float* __restrict__ X, const float* __restrict__ Wt,
    uint32_t* smem, const GemmCtx& cx, float c[4][4][4]) {
    int tid = threadIdx.x;
    int ar  = tid >> 3, ac4 = (tid & 7) * 4;
    uint32_t base = smem_u32(smem);

    int lane = tid & 31;
    int t = lane >> 3, r8 = lane & 7;
    int laneA = ((t & 1) * 8 + r8) * LDA2 + (t >> 1) * 4;
    int laneB = ((t >> 1) * 8 + r8) * LDA2 + (t & 1) * 4;

    auto issue = [&](int s, int kt) {
        uint32_t ab = base + (s * AW) * 4;
#pragma unroll
        for (int i = 0; i < 4; i++) {
            int r = ar + 32 * i;
            cpa16(ab + (r * LDA2 + ac4) * 4,
                  X + (size_t)(cx.rowBase + r) * 256 + kt + ac4);
        }
        uint32_t bb = base + ((2 + s) * AW) * 4;
#pragma unroll
        for (int i = 0; i < 4; i++) {
            int r = ar + 32 * i;
            cpa16(bb + (r * LDA2 + ac4) * 4,
                  Wt + (size_t)(cx.colBase + r) * 256 + kt + ac4);
        }
        asm volatile("cp.async.commit_group;");
    };

    issue(0, 0);

#pragma unroll 1
    for (int it = 0; it < 8; it++) {
        if (it < 7) {
            issue((it + 1) & 1, (it + 1) * TBK);
            asm volatile("cp.async.wait_group 1;");
        } else {
            asm volatile("cp.async.wait_group 0;");
        }
        __syncthreads();

        uint32_t Ab = base + ((it & 1) * AW) * 4;
        uint32_t Bb = base + ((2 + (it & 1)) * AW) * 4;
#pragma unroll
        for (int kk = 0; kk < TBK; kk += 8) {
            uint32_t a[4][4], b[4][2];
#pragma unroll
            for (int mi = 0; mi < 4; mi++)
                ldsm4(a[mi][0], a[mi][1], a[mi][2], a[mi][3],
                      Ab + (((cx.wm + mi * 16) * LDA2 + kk) + laneA) * 4);
            ldsm4(b[0][0], b[0][1], b[1][0], b[1][1],
                  Bb + ((cx.wn * LDA2 + kk) + laneB) * 4);
            ldsm4(b[2][0], b[2][1], b[3][0], b[3][1],
                  Bb + (((cx.wn + 16) * LDA2 + kk) + laneB) * 4);
#pragma unroll
            for (int mi = 0; mi < 4; mi++)
#pragma unroll
                for (int ni = 0; ni < 4; ni++)
                    mma_tf32(c[mi][ni], a[mi], b[ni]);
        }
        __syncthreads();
    }
}

// GEMM 1: qkv = Xr @ Wq^T-view, scatter into g_qkv (tf32-rounded stores)
__global__ __launch_bounds__(256, 2)
void gemm_qkv_tc(const float* __restrict__ X, const float* __restrict__ Wt) {
    extern __shared__ uint32_t smg[];
    int tid = threadIdx.x;
    int lane = tid & 31, warp = tid >> 5;
    int g = lane >> 2, tg = lane & 3;
    GemmCtx cx;
    cx.wm = (warp >> 2) * 64; cx.wn = (warp & 3) * 32;
    cx.rowBase = blockIdx.y * 128; cx.colBase = blockIdx.x * 128;

    float c[4][4][4];
#pragma unroll
    for (int mi = 0; mi < 4; mi++)
#pragma unroll
        for (int ni = 0; ni < 4; ni++)
#pragma unroll
            for (int r = 0; r < 4; r++) c[mi][ni][r] = 0.f;

    gemm_mainloop_ca(X, Wt, smg, cx, c);

#pragma unroll
    for (int mi = 0; mi < 4; mi++) {
        int r0 = cx.rowBase + cx.wm + mi * 16 + g;
        int r1 = r0 + 8;
        int b0 = r0 / SEQ_N, n0 = r0 - b0 * SEQ_N;
        int b1 = r1 / SEQ_N, n1 = r1 - b1 * SEQ_N;
#pragma unroll
        for (int ni = 0; ni < 4; ni++) {
            int col   = cx.colBase + cx.wn + ni * 8 + 2 * tg;
            int which = col >> 8;
            int h     = (col >> 5) & 7;
            int d0    = col & 31;
            size_t base0 = ((size_t)which * BH_TOT + b0 * HEADS + h) * HS + (size_t)n0 * DH + d0;
            size_t base1 = ((size_t)which * BH_TOT + b1 * HEADS + h) * HS + (size_t)n1 * DH + d0;
            // tf32-round so attention can cp.async raw bits
            *(float2*)&g_qkv[base0] = make_float2(f2tff(c[mi][ni][0]), f2tff(c[mi][ni][1]));
            *(float2*)&g_qkv[base1] = make_float2(f2tff(c[mi][ni][2]), f2tff(c[mi][ni][3]));
        }
    }
}

// GEMM 2: out = g_attnout @ Wp^T-view + proj_b
__global__ __launch_bounds__(256, 2)
void gemm_proj_tc(const float* __restrict__ Wt, const float* __restrict__ bias,
                  float* __restrict__ Out) {
    extern __shared__ uint32_t smg[];
    int tid = threadIdx.x;
    int lane = tid & 31, warp = tid >> 5;
    int g = lane >> 2, tg = lane & 3;
    GemmCtx cx;
    cx.wm = (warp >> 2) * 64; cx.wn = (warp & 3) * 32;
    cx.rowBase = blockIdx.y * 128; cx.colBase = blockIdx.x * 128;

    float c[4][4][4];
#pragma unroll
    for (int mi = 0; mi < 4; mi++)
#pragma unroll
        for (int ni = 0; ni < 4; ni++)
#pragma unroll
            for (int r = 0; r < 4; r++) c[mi][ni][r] = 0.f;

    gemm_mainloop_ca(g_attnout, Wt, smg, cx, c);

#pragma unroll
    for (int mi = 0; mi < 4; mi++) {
        int r0 = cx.rowBase + cx.wm + mi * 16 + g;
        int r1 = r0 + 8;
#pragma unroll
        for (int ni = 0; ni < 4; ni++) {
            int col = cx.colBase + cx.wn + ni * 8 + 2 * tg;
            float bx = bias[col], by = bias[col + 1];
            *(float2*)&Out[(size_t)r0 * 256 + col] =
                make_float2(c[mi][ni][0] + bx, c[mi][ni][1] + by);
            *(float2*)&Out[(size_t)r1 * 256 + col] =
                make_float2(c[mi][ni][2] + bx, c[mi][ni][3] + by);
        }
    }
}

// ---------------------------------------------------------------------------
// Attention v6: one block per (b,h), 256 threads = 8 warps, 16 rows each.
//  v5 + ILP restructuring (pure scheduling, bit-identical numerics):
//   - S-phase processes ni in PAIRS: two independent mma chains interleaved
//   - bm float2s software-pipelined one pair ahead (double-buffered regs)
//   - O-phase v-frags software-pipelined one kk ahead
// smem words: k 112*36 | v 112*40 | P 112*116 = 21504 (86016 B) -> 2 CTAs/SM
// ---------------------------------------------------------------------------
#define LDK  36
#define LDVM 40
#define LDP  116
#define BOFF_V (112 * LDK)              // 4032
#define BOFF_P (BOFF_V + 112 * LDVM)    // 8512
#define ATTN_SMEM_BYTES ((BOFF_P + 112 * LDP) * 4)   // 86016

__global__ __launch_bounds__(256, 2)
void attn_tc() {
    extern __shared__ uint32_t sm[];
    uint32_t* sk = sm;
    uint32_t* sv = sm + BOFF_V;
    uint32_t* sP = sm + BOFF_P;

    int tid  = threadIdx.x;
    int bh   = blockIdx.x;
    int b = bh >> 3, h = bh & 7;
    const float* gq = g_qkv + (size_t)bh * HS;
    const float* gk = gq + QKV_ONE;
    const float* gv = gq + 2 * QKV_ONE;
    uint32_t skb = smem_u32(sk), svb = smem_u32(sv);
    uint32_t sPb = smem_u32(sP);

    // ---- async k [98][32] -> sk[n][d], v [98][32] -> sv[m][d] ----
    for (int i = tid; i < 784; i += 256) {
        int r = i >> 3, c4 = (i & 7) * 4;
        cpa16(skb + (r * LDK + c4) * 4, gk + r * 32 + c4);
    }
    for (int i = tid; i < 784; i += 256) {
        int m = i >> 3, d4 = (i & 7) * 4;
        cpa16(svb + (m * LDVM + d4) * 4, gv + m * 32 + d4);
    }
    asm volatile("cp.async.commit_group;");

    int lane = tid & 31, warp = tid >> 5;
    int g = lane >> 2, tg = lane & 3;
    int t8 = lane >> 3, r8 = lane & 7;
    int n0 = warp * 16 + g, n1 = n0 + 8;
    bool rv0 = (n0 < SEQ_N), rv1 = (n1 < SEQ_N);

    // ---- q A-fragments straight from gmem (overlaps cp.async) ----
    uint32_t aF[4][4];
#pragma unroll
    for (int kk = 0; kk < 4; kk++) {
        int c = kk * 8 + tg;
        aF[kk][0] = rv0 ? f2tf(gq[n0 * 32 + c] * SCALE) : 0u;
        aF[kk][1] = rv1 ? f2tf(gq[n1 * 32 + c] * SCALE) : 0u;
        aF[kk][2] = rv0 ? f2tf(gq[n0 * 32 + c + 4] * SCALE) : 0u;
        aF[kk][3] = rv1 ? f2tf(gq[n1 * 32 + c + 4] * SCALE) : 0u;
    }

    // ---- zero pads (rows 98..111) ----
    for (int i = tid; i < 448; i += 256) {
        int r = 98 + (i >> 5), d = i & 31;
        sk[r * LDK + d] = 0u;
    }
    for (int i = tid; i < 448; i += 256) {
        int m = 98 + (i >> 5), d = i & 31;
        sv[m * LDVM + d] = 0u;
    }
    asm volatile("cp.async.wait_group 0;");
    __syncthreads();

    // warp 7 covers rows 112..127 -> entirely invalid
    if (warp == 7) return;

    size_t bmbase = ((size_t)(b & (NW - 1)) * HEADS + h) * (SEQ_N * SEQ_N);
    const float* bmr0 = &g_bm[bmbase + (size_t)n0 * SEQ_N];
    const float* bmr1 = &g_bm[bmbase + (size_t)n1 * SEQ_N];

    // ldmatrix lane offsets (words)
    int laneS = r8 * LDK + t8 * 4;                         // k-frags
    int laneO = ((t8 & 1) * 8 + r8) * LDP + (t8 >> 1) * 4; // P A-frags

    // bm pair fetch helper: pair p covers ni = 2p, 2p+1
    auto bm_fetch = [&](int p, float2* A, float2* B) {
#pragma unroll
        for (int e = 0; e < 2; e++) {
            int c0 = (2 * p + e) * 8 + 2 * tg;
            bool cvj = (c0 < SEQ_N);
            float2 t0 = make_float2(0.f, 0.f), t1 = make_float2(0.f, 0.f);
            if (rv0 && cvj) t0 = *(const float2*)&bmr0[c0];
            if (rv1 && cvj) t1 = *(const float2*)&bmr1[c0];
            A[e] = t0; B[e] = t1;
        }
    };

    // ---- S phase: 7 pairs of ni, two interleaved mma chains per pair ----
    float sum0 = 0.f, sum1 = 0.f;
    float2 pA[2][2], pB[2][2];
    bm_fetch(0, pA[0], pB[0]);
#pragma unroll
    for (int p = 0; p < 7; p++) {
        int ni0 = 2 * p, ni1 = 2 * p + 1;
        // k-fragments for both ni (4 LDSM)
        uint32_t bF0[4][2], bF1[4][2];
        uint32_t sb0 = skb + (ni0 * 8 * LDK + laneS) * 4;
        uint32_t sb1 = skb + (ni1 * 8 * LDK + laneS) * 4;
        ldsm4(bF0[0][0], bF0[0][1], bF0[1][0], bF0[1][1], sb0);
        ldsm4(bF0[2][0], bF0[2][1], bF0[3][0], bF0[3][1], sb0 + 64);
        ldsm4(bF1[0][0], bF1[0][1], bF1[1][0], bF1[1][1], sb1);
        ldsm4(bF1[2][0], bF1[2][1], bF1[3][0], bF1[3][1], sb1 + 64);

        // prefetch next pair's bm while mma runs
        if (p < 6) bm_fetch(p + 1, pA[(p + 1) & 1], pB[(p + 1) & 1]);

        float acc0[4] = {0.f, 0.f, 0.f, 0.f};
        float acc1[4] = {0.f, 0.f, 0.f, 0.f};
#pragma unroll
        for (int kk = 0; kk < 4; kk++) {
            mma_tf32(acc0, aF[kk], bF0[kk]);
            mma_tf32(acc1, aF[kk], bF1[kk]);
        }

        float2* cA = pA[p & 1];
        float2* cB = pB[p & 1];
        // epilogue ni0 then ni1 (same order as before -> bit-identical sums)
#pragma unroll
        for (int e = 0; e < 2; e++) {
            int ni = (e == 0) ? ni0 : ni1;
            float* acc = (e == 0) ? acc0 : acc1;
            int c0 = ni * 8 + 2 * tg;
            bool cv = (c0 < SEQ_N);
            float e00 = 0.f, e01 = 0.f, e10 = 0.f, e11 = 0.f;
            if (cv && rv0) {
                e00 = fastexp(acc[0] + cA[e].x);
                e01 = fastexp(acc[1] + cA[e].y);
            }
            if (cv && rv1) {
                e10 = fastexp(acc[2] + cB[e].x);
                e11 = fastexp(acc[3] + cB[e].y);
            }
            uint32_t u00 = f2tf(e00), u01 = f2tf(e01);
            uint32_t u10 = f2tf(e10), u11 = f2tf(e11);
            sum0 += __uint_as_float(u00) + __uint_as_float(u01);
            sum1 += __uint_as_float(u10) + __uint_as_float(u11);
            *(uint2*)&sP[n0 * LDP + c0] = make_uint2(u00, u01);
            *(uint2*)&sP[n1 * LDP + c0] = make_uint2(u10, u11);
        }
    }
    // rowsum across the 4-lane quad (result lands in all 4 lanes)
    sum0 += __shfl_xor_sync(0xffffffffu, sum0, 1);
    sum0 += __shfl_xor_sync(0xffffffffu, sum0, 2);
    sum1 += __shfl_xor_sync(0xffffffffu, sum1, 1);
    sum1 += __shfl_xor_sync(0xffffffffu, sum1, 2);
    float inv0 = rv0 ? (1.0f / sum0) : 0.f;
    float inv1 = rv1 ? (1.0f / sum1) : 0.f;

    // sP is warp-private (rows 16*warp..16*warp+15): warp-level sync suffices
    __syncwarp();

    // ---- O phase: O = P . v, v-frags pipelined one kk ahead ----
    float oacc[4][4];
#pragma unroll
    for (int ni = 0; ni < 4; ni++)
#pragma unroll
        for (int r = 0; r < 4; r++) oacc[ni][r] = 0.f;

    uint32_t pbase = sPb + (warp * 16 * LDP + laneO) * 4;

    auto v_fetch = [&](int kk, uint32_t bO[4][2]) {
#pragma unroll
        for (int ni = 0; ni < 4; ni++) {
            int vr = ni * 8 + g;
            bO[ni][0] = sv[(kk * 8 + tg) * LDVM + vr];
            bO[ni][1] = sv[(kk * 8 + tg + 4) * LDVM + vr];
        }
    };

    uint32_t bOv[2][4][2];
    v_fetch(0, bOv[0]);
#pragma unroll
    for (int kk = 0; kk < 14; kk++) {
        uint32_t aO[4];
        ldsm4(aO[0], aO[1], aO[2], aO[3], pbase + kk * 32);
        if (kk < 13) v_fetch(kk + 1, bOv[(kk + 1) & 1]);
#pragma unroll
        for (int ni = 0; ni < 4; ni++)
            mma_tf32(oacc[ni], aO, bOv[kk & 1][ni]);
    }

    // stores tf32-rounded so proj GEMM can consume raw bits via cp.async
    if (rv0) {
        size_t ob = ((size_t)b * SEQ_N + n0) * CH + h * DH;
#pragma unroll
        for (int ni = 0; ni < 4; ni++) {
            int d0 = ni * 8 + 2 * tg;
            *(float2*)&g_attnout[ob + d0] =
                make_float2(f2tff(oacc[ni][0] * inv0), f2tff(oacc[ni][1] * inv0));
        }
    }
    if (rv1) {
        size_t ob = ((size_t)b * SEQ_N + n1) * CH + h * DH;
#pragma unroll
        for (int ni = 0; ni < 4; ni++) {
            int d0 = ni * 8 + 2 * tg;
            *(float2*)&g_attnout[ob + d0] =
                make_float2(f2tff(oacc[ni][2] * inv1), f2tff(oacc[ni][3] * inv1));
        }
    }
}

// ---------------------------------------------------------------------------
// Launch
// ---------------------------------------------------------------------------
extern "C" void kernel_launch(void* const* d_in, const int* in_sizes, int n_in,
                              void* d_out, int out_size) {
    const float* x       = (const float*)d_in[0];
    const float* mask    = (const float*)d_in[1];
    const float* qkv_w   = (const float*)d_in[2];
    const float* proj_w  = (const float*)d_in[3];
    const float* proj_b  = (const float*)d_in[4];
    const float* table   = (const float*)d_in[5];
    float* out           = (float*)d_out;

    static bool attr_done = false;
    if (!attr_done) {
        cudaFuncSetAttribute(attn_tc, cudaFuncAttributeMaxDynamicSharedMemorySize,
                             ATTN_SMEM_BYTES);
        cudaFuncSetAttribute(gemm_qkv_tc, cudaFuncAttributeMaxDynamicSharedMemorySize,
                             GEMM_SMEM_BYTES);
        cudaFuncSetAttribute(gemm_proj_tc, cudaFuncAttributeMaxDynamicSharedMemorySize,
                             GEMM_SMEM_BYTES);
        attr_done = true;
    }

    float* xr = nullptr; float* wq = nullptr; float* wp = nullptr;
    cudaGetSymbolAddress((void**)&xr, g_xr);
    cudaGetSymbolAddress((void**)&wq, g_wq);
    cudaGetSymbolAddress((void**)&wp, g_wp);

    // 0a) tf32-round X; round+transpose weights to [N][K]
    {
        int n4x = M_TOT * CH / 4;
        tf32_round4<<<(n4x + 255) / 256, 256>>>((const float4*)x, (float4*)xr, n4x);
        int nq = CH * 3 * CH;
        round_transpose<<<(nq + 255) / 256, 256>>>(qkv_w, wq, CH, 3 * CH);
        int np = CH * CH;
        round_transpose<<<(np + 255) / 256, 256>>>(proj_w, wp, CH, CH);
    }
    // 0b) bias+mask precompute
    {
        int tot = NW * HEADS * SEQ_N * SEQ_N;
        bm_kernel<<<(tot + 255) / 256, 256>>>(mask, table);
    }
    // 1) qkv GEMM (tf32 mma + ldmatrix + cp.async)
    gemm_qkv_tc<<<dim3(768 / 128, M_TOT / 128), 256, GEMM_SMEM_BYTES>>>(xr, wq);
    // 2) attention: one block per (b,h)
    attn_tc<<<BH_TOT, 256, ATTN_SMEM_BYTES>>>();
    // 3) proj GEMM + bias (tf32 mma + ldmatrix + cp.async)
    gemm_proj_tc<<<dim3(256 / 128, M_TOT / 128), 256, GEMM_SMEM_BYTES>>>(wp, proj_b, out);
}

// round 15
// speedup vs baseline: 3.9005x; 1.0498x over previous
#include <cuda_runtime.h>
#include <cuda_bf16.h>
#include <cstdint>
#include <cstddef>

// ---------------------------------------------------------------------------
// Problem constants
// ---------------------------------------------------------------------------
#define B_TOT   2048
#define SEQ_N   98
#define CH      256
#define HEADS   8
#define DH      32
#define NW      64
#define M_TOT   (B_TOT * SEQ_N)        // 200704
#define BH_TOT  (B_TOT * HEADS)        // 16384
#define HS      (SEQ_N * DH)           // 3136
#define QKV_ONE ((size_t)BH_TOT * HS)  // 51380224
#define SCALE   0.17677669529663687f   // 1/sqrt(32)

// ---------------------------------------------------------------------------
// Device-global scratch
// ---------------------------------------------------------------------------
__device__ float g_qkv[3ull * QKV_ONE];           // [which][b*H+h][n][d] (tf32)
__device__ float g_attnout[(size_t)M_TOT * CH];   // [b][n][c] (tf32-rounded)
__device__ float g_bm[(size_t)NW * HEADS * SEQ_N * SEQ_N];  // bias+mask
__device__ float g_wq[3 * CH * CH];               // tf32-rounded qkv_w, [N][K]
__device__ float g_wp[CH * CH];                   // tf32-rounded proj_w, [N][K]

// ---------------------------------------------------------------------------
// tf32 helpers
// ---------------------------------------------------------------------------
__device__ __forceinline__ uint32_t f2tf(float v) {
    uint32_t r;
    asm("cvt.rna.tf32.f32 %0, %1;" : "=r"(r) : "f"(v));
    return r;
}
__device__ __forceinline__ float f2tff(float v) { return __uint_as_float(f2tf(v)); }

__device__ __forceinline__ void mma_tf32(float* c, const uint32_t* a, const uint32_t* b) {
    asm volatile(
        "mma.sync.aligned.m16n8k8.row.col.f32.tf32.tf32.f32 "
        "{%0,%1,%2,%3}, {%4,%5,%6,%7}, {%8,%9}, {%0,%1,%2,%3};\n"
        : "+f"(c[0]), "+f"(c[1]), "+f"(c[2]), "+f"(c[3])
        : "r"(a[0]), "r"(a[1]), "r"(a[2]), "r"(a[3]),
          "r"(b[0]), "r"(b[1]));
}

// ldmatrix x4 (b16 view of tf32 data: lane -> 32-bit element (l/4, l%4))
__device__ __forceinline__ void ldsm4(uint32_t& d0, uint32_t& d1, uint32_t& d2,
                                      uint32_t& d3, uint32_t addr) {
    asm volatile("ldmatrix.sync.aligned.m8n8.x4.shared.b16 {%0,%1,%2,%3}, [%4];"
                 : "=r"(d0), "=r"(d1), "=r"(d2), "=r"(d3) : "r"(addr));
}

// fast exp on FMA pipe
__device__ __forceinline__ float fastexp(float s) {
    float t  = s * 1.4426950408889634f;
    float fr = t + 12582912.0f;            // 1.5 * 2^23
    float rn = fr - 12582912.0f;
    float f  = t - rn;
    float p  = 1.3333558146428443e-3f;
    p = fmaf(p, f, 9.618129107628477e-3f);
    p = fmaf(p, f, 5.550410866482158e-2f);
    p = fmaf(p, f, 2.402265069591007e-1f);
    p = fmaf(p, f, 6.931471805599453e-1f);
    p = fmaf(p, f, 1.0f);
    int ei = (int)((unsigned)__float_as_int(fr) << 23);
    return __int_as_float(__float_as_int(p) + ei);
}

// cp.async 16B
__device__ __forceinline__ void cpa16(uint32_t dst, const void* src) {
    asm volatile("cp.async.cg.shared.global [%0], [%1], 16;" :: "r"(dst), "l"(src));
}
__device__ __forceinline__ uint32_t smem_u32(const void* p) {
    return (uint32_t)__cvta_generic_to_shared(p);
}

// Kernel: tf32-round + transpose W [K][N] -> [N][K]
__global__ void round_transpose(const float* __restrict__ src, float* __restrict__ dst,
                                int K, int N) {
    int i = blockIdx.x * 256 + threadIdx.x;
    if (i < K * N) {
        int k = i / N, n = i % N;
        dst[n * K + k] = f2tff(src[i]);
    }
}

// ---------------------------------------------------------------------------
// Kernel 0: precompute bias(rel-pos) + mask  ->  g_bm[wi][h][n][m]
// ---------------------------------------------------------------------------
__global__ void bm_kernel(const float* __restrict__ mask,
                          const float* __restrict__ table) {
    int i = blockIdx.x * 256 + threadIdx.x;
    const int TOT = NW * HEADS * SEQ_N * SEQ_N;
    if (i >= TOT) return;
    int m  = i % SEQ_N;
    int r  = i / SEQ_N;
    int n  = r % SEQ_N;  r /= SEQ_N;
    int h  = r & 7;
    int wi = r >> 3;
    int dn = n / 49, hn = (n % 49) / 7, wn = n % 7;
    int dm = m / 49, hm = (m % 49) / 7, wm = m % 7;
    int rid = (dn - dm + 1) * 169 + (hn - hm + 6) * 13 + (wn - wm + 6);
    g_bm[i] = table[rid * HEADS + h] + mask[(size_t)wi * SEQ_N * SEQ_N + n * SEQ_N + m];
}

// ---------------------------------------------------------------------------
// tf32 GEMM, cp.async 2-stage, ldmatrix frag loads. Block 128x128, BK=32.
// A [M][K] row-major, B = W^T [N][K] n-major (pre-rounded tf32).
// A may be raw fp32: mma truncates to tf32 (deterministic, ~1.6e-4 rel bias).
// ---------------------------------------------------------------------------
#define TBK  32
#define LDA2 36
#define AW   (128 * LDA2)      // 4608 words per tile stage
#define GEMM_SMEM_BYTES (4 * AW * 4)   // 73728

struct GemmCtx {
    int rowBase, colBase;
    int wm, wn;
};

__device__ __forceinline__ void gemm_mainloop_ca(
    const float* __restrict__ X, const float* __restrict__ Wt,
    uint32_t* smem, const GemmCtx& cx, float c[4][4][4]) {
    int tid = threadIdx.x;
    int ar  = tid >> 3, ac4 = (tid & 7) * 4;
    uint32_t base = smem_u32(smem);

    int lane = tid & 31;
    int t = lane >> 3, r8 = lane & 7;
    int laneA = ((t & 1) * 8 + r8) * LDA2 + (t >> 1) * 4;
    int laneB = ((t >> 1) * 8 + r8) * LDA2 + (t & 1) * 4;

    auto issue = [&](int s, int kt) {
        uint32_t ab = base + (s * AW) * 4;
#pragma unroll
        for (int i = 0; i < 4; i++) {
            int r = ar + 32 * i;
            cpa16(ab + (r * LDA2 + ac4) * 4,
                  X + (size_t)(cx.rowBase + r) * 256 + kt + ac4);
        }
        uint32_t bb = base + ((2 + s) * AW) * 4;
#pragma unroll
        for (int i = 0; i < 4; i++) {
            int r = ar + 32 * i;
            cpa16(bb + (r * LDA2 + ac4) * 4,
                  Wt + (size_t)(cx.colBase + r) * 256 + kt + ac4);
        }
        asm volatile("cp.async.commit_group;");
    };

    issue(0, 0);

#pragma unroll 1
    for (int it = 0; it < 8; it++) {
        if (it < 7) {
            issue((it + 1) & 1, (it + 1) * TBK);
            asm volatile("cp.async.wait_group 1;");
        } else {
            asm volatile("cp.async.wait_group 0;");
        }
        __syncthreads();

        uint32_t Ab = base + ((it & 1) * AW) * 4;
        uint32_t Bb = base + ((2 + (it & 1)) * AW) * 4;
#pragma unroll
        for (int kk = 0; kk < TBK; kk += 8) {
            uint32_t a[4][4], b[4][2];
#pragma unroll
            for (int mi = 0; mi < 4; mi++)
                ldsm4(a[mi][0], a[mi][1], a[mi][2], a[mi][3],
                      Ab + (((cx.wm + mi * 16) * LDA2 + kk) + laneA) * 4);
            ldsm4(b[0][0], b[0][1], b[1][0], b[1][1],
                  Bb + ((cx.wn * LDA2 + kk) + laneB) * 4);
            ldsm4(b[2][0], b[2][1], b[3][0], b[3][1],
                  Bb + (((cx.wn + 16) * LDA2 + kk) + laneB) * 4);
#pragma unroll
            for (int mi = 0; mi < 4; mi++)
#pragma unroll
                for (int ni = 0; ni < 4; ni++)
                    mma_tf32(c[mi][ni], a[mi], b[ni]);
        }
        __syncthreads();
    }
}

// GEMM 1: qkv = X(raw) @ Wq^T-view, scatter into g_qkv (tf32-rounded stores)
__global__ __launch_bounds__(256, 2)
void gemm_qkv_tc(const float* __restrict__ X, const float* __restrict__ Wt) {
    extern __shared__ uint32_t smg[];
    int tid = threadIdx.x;
    int lane = tid & 31, warp = tid >> 5;
    int g = lane >> 2, tg = lane & 3;
    GemmCtx cx;
    cx.wm = (warp >> 2) * 64; cx.wn = (warp & 3) * 32;
    cx.rowBase = blockIdx.y * 128; cx.colBase = blockIdx.x * 128;

    float c[4][4][4];
#pragma unroll
    for (int mi = 0; mi < 4; mi++)
#pragma unroll
        for (int ni = 0; ni < 4; ni++)
#pragma unroll
            for (int r = 0; r < 4; r++) c[mi][ni][r] = 0.f;

    gemm_mainloop_ca(X, Wt, smg, cx, c);

#pragma unroll
    for (int mi = 0; mi < 4; mi++) {
        int r0 = cx.rowBase + cx.wm + mi * 16 + g;
        int r1 = r0 + 8;
        int b0 = r0 / SEQ_N, n0 = r0 - b0 * SEQ_N;
        int b1 = r1 / SEQ_N, n1 = r1 - b1 * SEQ_N;
#pragma unroll
        for (int ni = 0; ni < 4; ni++) {
            int col   = cx.colBase + cx.wn + ni * 8 + 2 * tg;
            int which = col >> 8;
            int h     = (col >> 5) & 7;
            int d0    = col & 31;
            size_t base0 = ((size_t)which * BH_TOT + b0 * HEADS + h) * HS + (size_t)n0 * DH + d0;
            size_t base1 = ((size_t)which * BH_TOT + b1 * HEADS + h) * HS + (size_t)n1 * DH + d0;
            // tf32-round so attention can cp.async raw bits
            *(float2*)&g_qkv[base0] = make_float2(f2tff(c[mi][ni][0]), f2tff(c[mi][ni][1]));
            *(float2*)&g_qkv[base1] = make_float2(f2tff(c[mi][ni][2]), f2tff(c[mi][ni][3]));
        }
    }
}

// GEMM 2: out = g_attnout @ Wp^T-view + proj_b
__global__ __launch_bounds__(256, 2)
void gemm_proj_tc(const float* __restrict__ Wt, const float* __restrict__ bias,
                  float* __restrict__ Out) {
    extern __shared__ uint32_t smg[];
    int tid = threadIdx.x;
    int lane = tid & 31, warp = tid >> 5;
    int g = lane >> 2, tg = lane & 3;
    GemmCtx cx;
    cx.wm = (warp >> 2) * 64; cx.wn = (warp & 3) * 32;
    cx.rowBase = blockIdx.y * 128; cx.colBase = blockIdx.x * 128;

    float c[4][4][4];
#pragma unroll
    for (int mi = 0; mi < 4; mi++)
#pragma unroll
        for (int ni = 0; ni < 4; ni++)
#pragma unroll
            for (int r = 0; r < 4; r++) c[mi][ni][r] = 0.f;

    gemm_mainloop_ca(g_attnout, Wt, smg, cx, c);

#pragma unroll
    for (int mi = 0; mi < 4; mi++) {
        int r0 = cx.rowBase + cx.wm + mi * 16 + g;
        int r1 = r0 + 8;
#pragma unroll
        for (int ni = 0; ni < 4; ni++) {
            int col = cx.colBase + cx.wn + ni * 8 + 2 * tg;
            float bx = bias[col], by = bias[col + 1];
            *(float2*)&Out[(size_t)r0 * 256 + col] =
                make_float2(c[mi][ni][0] + bx, c[mi][ni][1] + by);
            *(float2*)&Out[(size_t)r1 * 256 + col] =
                make_float2(c[mi][ni][2] + bx, c[mi][ni][3] + by);
        }
    }
}

// ---------------------------------------------------------------------------
// Attention v6: one block per (b,h), 256 threads = 8 warps, 16 rows each.
//   - S-phase in ni-pairs with interleaved mma chains; bm double-buffered
//   - O-phase v-frags pipelined one kk ahead
// smem words: k 112*36 | v 112*40 | P 112*116 = 21504 (86016 B) -> 2 CTAs/SM
// ---------------------------------------------------------------------------
#define LDK  36
#define LDVM 40
#define LDP  116
#define BOFF_V (112 * LDK)              // 4032
#define BOFF_P (BOFF_V + 112 * LDVM)    // 8512
#define ATTN_SMEM_BYTES ((BOFF_P + 112 * LDP) * 4)   // 86016

__global__ __launch_bounds__(256, 2)
void attn_tc() {
    extern __shared__ uint32_t sm[];
    uint32_t* sk = sm;
    uint32_t* sv = sm + BOFF_V;
    uint32_t* sP = sm + BOFF_P;

    int tid  = threadIdx.x;
    int bh   = blockIdx.x;
    int b = bh >> 3, h = bh & 7;
    const float* gq = g_qkv + (size_t)bh * HS;
    const float* gk = gq + QKV_ONE;
    const float* gv = gq + 2 * QKV_ONE;
    uint32_t skb = smem_u32(sk), svb = smem_u32(sv);
    uint32_t sPb = smem_u32(sP);

    // ---- async k [98][32] -> sk[n][d], v [98][32] -> sv[m][d] ----
    for (int i = tid; i < 784; i += 256) {
        int r = i >> 3, c4 = (i & 7) * 4;
        cpa16(skb + (r * LDK + c4) * 4, gk + r * 32 + c4);
    }
    for (int i = tid; i < 784; i += 256) {
        int m = i >> 3, d4 = (i & 7) * 4;
        cpa16(svb + (m * LDVM + d4) * 4, gv + m * 32 + d4);
    }
    asm volatile("cp.async.commit_group;");

    int lane = tid & 31, warp = tid >> 5;
    int g = lane >> 2, tg = lane & 3;
    int t8 = lane >> 3, r8 = lane & 7;
    int n0 = warp * 16 + g, n1 = n0 + 8;
    bool rv0 = (n0 < SEQ_N), rv1 = (n1 < SEQ_N);

    // ---- q A-fragments straight from gmem (overlaps cp.async) ----
    uint32_t aF[4][4];
#pragma unroll
    for (int kk = 0; kk < 4; kk++) {
        int c = kk * 8 + tg;
        aF[kk][0] = rv0 ? f2tf(gq[n0 * 32 + c] * SCALE) : 0u;
        aF[kk][1] = rv1 ? f2tf(gq[n1 * 32 + c] * SCALE) : 0u;
        aF[kk][2] = rv0 ? f2tf(gq[n0 * 32 + c + 4] * SCALE) : 0u;
        aF[kk][3] = rv1 ? f2tf(gq[n1 * 32 + c + 4] * SCALE) : 0u;
    }

    // ---- zero pads (rows 98..111) ----
    for (int i = tid; i < 448; i += 256) {
        int r = 98 + (i >> 5), d = i & 31;
        sk[r * LDK + d] = 0u;
    }
    for (int i = tid; i < 448; i += 256) {
        int m = 98 + (i >> 5), d = i & 31;
        sv[m * LDVM + d] = 0u;
    }
    asm volatile("cp.async.wait_group 0;");
    __syncthreads();

    // warp 7 covers rows 112..127 -> entirely invalid
    if (warp == 7) return;

    size_t bmbase = ((size_t)(b & (NW - 1)) * HEADS + h) * (SEQ_N * SEQ_N);
    const float* bmr0 = &g_bm[bmbase + (size_t)n0 * SEQ_N];
    const float* bmr1 = &g_bm[bmbase + (size_t)n1 * SEQ_N];

    // ldmatrix lane offsets (words)
    int laneS = r8 * LDK + t8 * 4;                         // k-frags
    int laneO = ((t8 & 1) * 8 + r8) * LDP + (t8 >> 1) * 4; // P A-frags

    // bm pair fetch helper: pair p covers ni = 2p, 2p+1
    auto bm_fetch = [&](int p, float2* A, float2* B) {
#pragma unroll
        for (int e = 0; e < 2; e++) {
            int c0 = (2 * p + e) * 8 + 2 * tg;
            bool cvj = (c0 < SEQ_N);
            float2 t0 = make_float2(0.f, 0.f), t1 = make_float2(0.f, 0.f);
            if (rv0 && cvj) t0 = *(const float2*)&bmr0[c0];
            if (rv1 && cvj) t1 = *(const float2*)&bmr1[c0];
            A[e] = t0; B[e] = t1;
        }
    };

    // ---- S phase: 7 pairs of ni, two interleaved mma chains per pair ----
    float sum0 = 0.f, sum1 = 0.f;
    float2 pA[2][2], pB[2][2];
    bm_fetch(0, pA[0], pB[0]);
#pragma unroll
    for (int p = 0; p < 7; p++) {
        int ni0 = 2 * p, ni1 = 2 * p + 1;
        uint32_t bF0[4][2], bF1[4][2];
        uint32_t sb0 = skb + (ni0 * 8 * LDK + laneS) * 4;
        uint32_t sb1 = skb + (ni1 * 8 * LDK + laneS) * 4;
        ldsm4(bF0[0][0], bF0[0][1], bF0[1][0], bF0[1][1], sb0);
        ldsm4(bF0[2][0], bF0[2][1], bF0[3][0], bF0[3][1], sb0 + 64);
        ldsm4(bF1[0][0], bF1[0][1], bF1[1][0], bF1[1][1], sb1);
        ldsm4(bF1[2][0], bF1[2][1], bF1[3][0], bF1[3][1], sb1 + 64);

        if (p < 6) bm_fetch(p + 1, pA[(p + 1) & 1], pB[(p + 1) & 1]);

        float acc0[4] = {0.f, 0.f, 0.f, 0.f};
        float acc1[4] = {0.f, 0.f, 0.f, 0.f};
#pragma unroll
        for (int kk = 0; kk < 4; kk++) {
            mma_tf32(acc0, aF[kk], bF0[kk]);
            mma_tf32(acc1, aF[kk], bF1[kk]);
        }

        float2* cA = pA[p & 1];
        float2* cB = pB[p & 1];
#pragma unroll
        for (int e = 0; e < 2; e++) {
            int ni = (e == 0) ? ni0 : ni1;
            float* acc = (e == 0) ? acc0 : acc1;
            int c0 = ni * 8 + 2 * tg;
            bool cv = (c0 < SEQ_N);
            float e00 = 0.f, e01 = 0.f, e10 = 0.f, e11 = 0.f;
            if (cv && rv0) {
                e00 = fastexp(acc[0] + cA[e].x);
                e01 = fastexp(acc[1] + cA[e].y);
            }
            if (cv && rv1) {
                e10 = fastexp(acc[2] + cB[e].x);
                e11 = fastexp(acc[3] + cB[e].y);
            }
            uint32_t u00 = f2tf(e00), u01 = f2tf(e01);
            uint32_t u10 = f2tf(e10), u11 = f2tf(e11);
            sum0 += __uint_as_float(u00) + __uint_as_float(u01);
            sum1 += __uint_as_float(u10) + __uint_as_float(u11);
            *(uint2*)&sP[n0 * LDP + c0] = make_uint2(u00, u01);
            *(uint2*)&sP[n1 * LDP + c0] = make_uint2(u10, u11);
        }
    }
    // rowsum across the 4-lane quad (result lands in all 4 lanes)
    sum0 += __shfl_xor_sync(0xffffffffu, sum0, 1);
    sum0 += __shfl_xor_sync(0xffffffffu, sum0, 2);
    sum1 += __shfl_xor_sync(0xffffffffu, sum1, 1);
    sum1 += __shfl_xor_sync(0xffffffffu, sum1, 2);
    float inv0 = rv0 ? (1.0f / sum0) : 0.f;
    float inv1 = rv1 ? (1.0f / sum1) : 0.f;

    // sP is warp-private (rows 16*warp..16*warp+15): warp-level sync suffices
    __syncwarp();

    // ---- O phase: O = P . v, v-frags pipelined one kk ahead ----
    float oacc[4][4];
#pragma unroll
    for (int ni = 0; ni < 4; ni++)
#pragma unroll
        for (int r = 0; r < 4; r++) oacc[ni][r] = 0.f;

    uint32_t pbase = sPb + (warp * 16 * LDP + laneO) * 4;

    auto v_fetch = [&](int kk, uint32_t bO[4][2]) {
#pragma unroll
        for (int ni = 0; ni < 4; ni++) {
            int vr = ni * 8 + g;
            bO[ni][0] = sv[(kk * 8 + tg) * LDVM + vr];
            bO[ni][1] = sv[(kk * 8 + tg + 4) * LDVM + vr];
        }
    };

    uint32_t bOv[2][4][2];
    v_fetch(0, bOv[0]);
#pragma unroll
    for (int kk = 0; kk < 14; kk++) {
        uint32_t aO[4];
        ldsm4(aO[0], aO[1], aO[2], aO[3], pbase + kk * 32);
        if (kk < 13) v_fetch(kk + 1, bOv[(kk + 1) & 1]);
#pragma unroll
        for (int ni = 0; ni < 4; ni++)
            mma_tf32(oacc[ni], aO, bOv[kk & 1][ni]);
    }

    // stores tf32-rounded so proj GEMM can consume raw bits via cp.async
    if (rv0) {
        size_t ob = ((size_t)b * SEQ_N + n0) * CH + h * DH;
#pragma unroll
        for (int ni = 0; ni < 4; ni++) {
            int d0 = ni * 8 + 2 * tg;
            *(float2*)&g_attnout[ob + d0] =
                make_float2(f2tff(oacc[ni][0] * inv0), f2tff(oacc[ni][1] * inv0));
        }
    }
    if (rv1) {
        size_t ob = ((size_t)b * SEQ_N + n1) * CH + h * DH;
#pragma unroll
        for (int ni = 0; ni < 4; ni++) {
            int d0 = ni * 8 + 2 * tg;
            *(float2*)&g_attnout[ob + d0] =
                make_float2(f2tff(oacc[ni][2] * inv1), f2tff(oacc[ni][3] * inv1));
        }
    }
}

// ---------------------------------------------------------------------------
// Launch
// ---------------------------------------------------------------------------
extern "C" void kernel_launch(void* const* d_in, const int* in_sizes, int n_in,
                              void* d_out, int out_size) {
    const float* x       = (const float*)d_in[0];
    const float* mask    = (const float*)d_in[1];
    const float* qkv_w   = (const float*)d_in[2];
    const float* proj_w  = (const float*)d_in[3];
    const float* proj_b  = (const float*)d_in[4];
    const float* table   = (const float*)d_in[5];
    float* out           = (float*)d_out;

    static bool attr_done = false;
    if (!attr_done) {
        cudaFuncSetAttribute(attn_tc, cudaFuncAttributeMaxDynamicSharedMemorySize,
                             ATTN_SMEM_BYTES);
        cudaFuncSetAttribute(gemm_qkv_tc, cudaFuncAttributeMaxDynamicSharedMemorySize,
                             GEMM_SMEM_BYTES);
        cudaFuncSetAttribute(gemm_proj_tc, cudaFuncAttributeMaxDynamicSharedMemorySize,
                             GEMM_SMEM_BYTES);
        attr_done = true;
    }

    float* wq = nullptr; float* wp = nullptr;
    cudaGetSymbolAddress((void**)&wq, g_wq);
    cudaGetSymbolAddress((void**)&wp, g_wp);

    // 0a) round+transpose weights to [N][K]  (X stays raw: mma truncates A)
    {
        int nq = CH * 3 * CH;
        round_transpose<<<(nq + 255) / 256, 256>>>(qkv_w, wq, CH, 3 * CH);
        int np = CH * CH;
        round_transpose<<<(np + 255) / 256, 256>>>(proj_w, wp, CH, CH);
    }
    // 0b) bias+mask precompute
    {
        int tot = NW * HEADS * SEQ_N * SEQ_N;
        bm_kernel<<<(tot + 255) / 256, 256>>>(mask, table);
    }
    // 1) qkv GEMM (tf32 mma + ldmatrix + cp.async, raw-X A operand)
    gemm_qkv_tc<<<dim3(768 / 128, M_TOT / 128), 256, GEMM_SMEM_BYTES>>>(x, wq);
    // 2) attention: one block per (b,h)
    attn_tc<<<BH_TOT, 256, ATTN_SMEM_BYTES>>>();
    // 3) proj GEMM + bias (tf32 mma + ldmatrix + cp.async)
    gemm_proj_tc<<<dim3(256 / 128, M_TOT / 128), 256, GEMM_SMEM_BYTES>>>(wp, proj_b, out);
}

// round 16
// speedup vs baseline: 4.5217x; 1.1593x over previous
#include <cuda_runtime.h>
#include <cuda_fp16.h>
#include <cstdint>
#include <cstddef>

// ---------------------------------------------------------------------------
// Problem constants
// ---------------------------------------------------------------------------
#define B_TOT   2048
#define SEQ_N   98
#define CH      256
#define HEADS   8
#define DH      32
#define NW      64
#define M_TOT   (B_TOT * SEQ_N)        // 200704
#define BH_TOT  (B_TOT * HEADS)        // 16384
#define HS      (SEQ_N * DH)           // 3136
#define QKV_ONE ((size_t)BH_TOT * HS)  // 51380224
#define SCALE   0.17677669529663687f   // 1/sqrt(32)

// ---------------------------------------------------------------------------
// Device-global scratch
// ---------------------------------------------------------------------------
__device__ float  g_qkv[3ull * QKV_ONE];           // [which][b*H+h][n][d] (tf32)
__device__ __half g_attnout[(size_t)M_TOT * CH];   // [b][n][c] fp16
__device__ float  g_bm[(size_t)NW * HEADS * SEQ_N * SEQ_N];  // bias+mask
__device__ __half g_xh[(size_t)M_TOT * CH];        // fp16 X
__device__ __half g_wq[3 * CH * CH];               // fp16 qkv_w, [N][K]
__device__ __half g_wp[CH * CH];                   // fp16 proj_w, [N][K]

// ---------------------------------------------------------------------------
// helpers
// ---------------------------------------------------------------------------
__device__ __forceinline__ uint32_t f2tf(float v) {
    uint32_t r;
    asm("cvt.rna.tf32.f32 %0, %1;" : "=r"(r) : "f"(v));
    return r;
}
__device__ __forceinline__ float f2tff(float v) { return __uint_as_float(f2tf(v)); }

__device__ __forceinline__ void mma_tf32(float* c, const uint32_t* a, const uint32_t* b) {
    asm volatile(
        "mma.sync.aligned.m16n8k8.row.col.f32.tf32.tf32.f32 "
        "{%0,%1,%2,%3}, {%4,%5,%6,%7}, {%8,%9}, {%0,%1,%2,%3};\n"
        : "+f"(c[0]), "+f"(c[1]), "+f"(c[2]), "+f"(c[3])
        : "r"(a[0]), "r"(a[1]), "r"(a[2]), "r"(a[3]),
          "r"(b[0]), "r"(b[1]));
}

__device__ __forceinline__ void mma_f16(float* c, const uint32_t* a, const uint32_t* b) {
    asm volatile(
        "mma.sync.aligned.m16n8k16.row.col.f32.f16.f16.f32 "
        "{%0,%1,%2,%3}, {%4,%5,%6,%7}, {%8,%9}, {%0,%1,%2,%3};\n"
        : "+f"(c[0]), "+f"(c[1]), "+f"(c[2]), "+f"(c[3])
        : "r"(a[0]), "r"(a[1]), "r"(a[2]), "r"(a[3]),
          "r"(b[0]), "r"(b[1]));
}

__device__ __forceinline__ void ldsm4(uint32_t& d0, uint32_t& d1, uint32_t& d2,
                                      uint32_t& d3, uint32_t addr) {
    asm volatile("ldmatrix.sync.aligned.m8n8.x4.shared.b16 {%0,%1,%2,%3}, [%4];"
                 : "=r"(d0), "=r"(d1), "=r"(d2), "=r"(d3) : "r"(addr));
}

// fast exp on FMA pipe
__device__ __forceinline__ float fastexp(float s) {
    float t  = s * 1.4426950408889634f;
    float fr = t + 12582912.0f;            // 1.5 * 2^23
    float rn = fr - 12582912.0f;
    float f  = t - rn;
    float p  = 1.3333558146428443e-3f;
    p = fmaf(p, f, 9.618129107628477e-3f);
    p = fmaf(p, f, 5.550410866482158e-2f);
    p = fmaf(p, f, 2.402265069591007e-1f);
    p = fmaf(p, f, 6.931471805599453e-1f);
    p = fmaf(p, f, 1.0f);
    int ei = (int)((unsigned)__float_as_int(fr) << 23);
    return __int_as_float(__float_as_int(p) + ei);
}

// cp.async 16B
__device__ __forceinline__ void cpa16(uint32_t dst, const void* src) {
    asm volatile("cp.async.cg.shared.global [%0], [%1], 16;" :: "r"(dst), "l"(src));
}
__device__ __forceinline__ uint32_t smem_u32(const void* p) {
    return (uint32_t)__cvta_generic_to_shared(p);
}

// ---------------------------------------------------------------------------
// Prepass kernels
// ---------------------------------------------------------------------------
__global__ void f2h4(const float4* __restrict__ src, __half2* __restrict__ dst,
                     int n4) {
    int i = blockIdx.x * 256 + threadIdx.x;
    if (i < n4) {
        float4 v = src[i];
        dst[2 * i]     = __floats2half2_rn(v.x, v.y);
        dst[2 * i + 1] = __floats2half2_rn(v.z, v.w);
    }
}

// fp16-round + transpose W [K][N] -> [N][K]
__global__ void round_transpose_h(const float* __restrict__ src, __half* __restrict__ dst,
                                  int K, int N) {
    int i = blockIdx.x * 256 + threadIdx.x;
    if (i < K * N) {
        int k = i / N, n = i % N;
        dst[n * K + k] = __float2half_rn(src[i]);
    }
}

// ---------------------------------------------------------------------------
// Kernel 0: precompute bias(rel-pos) + mask  ->  g_bm[wi][h][n][m]
// ---------------------------------------------------------------------------
__global__ void bm_kernel(const float* __restrict__ mask,
                          const float* __restrict__ table) {
    int i = blockIdx.x * 256 + threadIdx.x;
    const int TOT = NW * HEADS * SEQ_N * SEQ_N;
    if (i >= TOT) return;
    int m  = i % SEQ_N;
    int r  = i / SEQ_N;
    int n  = r % SEQ_N;  r /= SEQ_N;
    int h  = r & 7;
    int wi = r >> 3;
    int dn = n / 49, hn = (n % 49) / 7, wn = n % 7;
    int dm = m / 49, hm = (m % 49) / 7, wm = m % 7;
    int rid = (dn - dm + 1) * 169 + (hn - hm + 6) * 13 + (wn - wm + 6);
    g_bm[i] = table[rid * HEADS + h] + mask[(size_t)wi * SEQ_N * SEQ_N + n * SEQ_N + m];
}

// ---------------------------------------------------------------------------
// fp16 GEMM, cp.async 2-stage, ldmatrix, m16n8k16. Block 128x128, BK=32.
// A [M][K] fp16 row-major, B = W^T [N][K] fp16 n-major.
// Tiles 128 x 32 halves, stride LDH=40 halves (80 B rows -> LDSM conflict-free).
// smem: 4 x 5120 halves = 40960 B
// ---------------------------------------------------------------------------
#define TBK  32
#define LDH  40
#define AWH  (128 * LDH)       // 5120 halves per tile stage
#define GEMM_SMEM_BYTES (4 * AWH * 2)   // 40960

struct GemmCtx {
    int rowBase, colBase;
    int wm, wn;
};

__device__ __forceinline__ void gemm_mainloop_h(
    const __half* __restrict__ X, const __half* __restrict__ Wt,
    __half* smem, const GemmCtx& cx, float c[4][4][4]) {
    int tid = threadIdx.x;
    int ar   = tid >> 2, aseg = (tid & 3) * 8;   // 64 rows/pass x 4 16B segs
    uint32_t base = smem_u32(smem);

    int lane = tid & 31;
    int t = lane >> 3, r8 = lane & 7;
    // A frags: m0(r,k) m1(r+8,k) m2(r,k+8) m3(r+8,k+8)
    int laneA = ((t & 1) * 8 + r8) * LDH + (t >> 1) * 8;
    // B frags: m0(n,k) m1(n,k+8) m2(n+8,k) m3(n+8,k+8)
    int laneB = ((t >> 1) * 8 + r8) * LDH + (t & 1) * 8;

    auto issue = [&](int s, int kt) {
        uint32_t ab = base + (s * AWH) * 2;
#pragma unroll
        for (int i = 0; i < 2; i++) {
            int r = ar + 64 * i;
            cpa16(ab + (r * LDH + aseg) * 2,
                  X + (size_t)(cx.rowBase + r) * 256 + kt + aseg);
        }
        uint32_t bb = base + ((2 + s) * AWH) * 2;
#pragma unroll
        for (int i = 0; i < 2; i++) {
            int r = ar + 64 * i;
            cpa16(bb + (r * LDH + aseg) * 2,
                  Wt + (size_t)(cx.colBase + r) * 256 + kt + aseg);
        }
        asm volatile("cp.async.commit_group;");
    };

    issue(0, 0);

#pragma unroll 1
    for (int it = 0; it < 8; it++) {
        if (it < 7) {
            issue((it + 1) & 1, (it + 1) * TBK);
            asm volatile("cp.async.wait_group 1;");
        } else {
            asm volatile("cp.async.wait_group 0;");
        }
        __syncthreads();

        uint32_t Ab = base + ((it & 1) * AWH) * 2;
        uint32_t Bb = base + ((2 + (it & 1)) * AWH) * 2;
#pragma unroll
        for (int kk = 0; kk < TBK; kk += 16) {
            uint32_t a[4][4], b[4][2];
#pragma unroll
            for (int mi = 0; mi < 4; mi++)
                ldsm4(a[mi][0], a[mi][1], a[mi][2], a[mi][3],
                      Ab + (((cx.wm + mi * 16) * LDH + kk) + laneA) * 2);
            ldsm4(b[0][0], b[0][1], b[1][0], b[1][1],
                  Bb + ((cx.wn * LDH + kk) + laneB) * 2);
            ldsm4(b[2][0], b[2][1], b[3][0], b[3][1],
                  Bb + (((cx.wn + 16) * LDH + kk) + laneB) * 2);
#pragma unroll
            for (int mi = 0; mi < 4; mi++)
#pragma unroll
                for (int ni = 0; ni < 4; ni++)
                    mma_f16(c[mi][ni], a[mi], b[ni]);
        }
        __syncthreads();
    }
}

// GEMM 1: qkv = Xh @ Wq^T-view, scatter into g_qkv (tf32-rounded fp32 stores)
__global__ __launch_bounds__(256, 2)
void gemm_qkv_tc(const __half* __restrict__ X, const __half* __restrict__ Wt) {
    extern __shared__ __half smgh[];
    int tid = threadIdx.x;
    int lane = tid & 31, warp = tid >> 5;
    int g = lane >> 2, tg = lane & 3;
    GemmCtx cx;
    cx.wm = (warp >> 2) * 64; cx.wn = (warp & 3) * 32;
    cx.rowBase = blockIdx.y * 128; cx.colBase = blockIdx.x * 128;

    float c[4][4][4];
#pragma unroll
    for (int mi = 0; mi < 4; mi++)
#pragma unroll
        for (int ni = 0; ni < 4; ni++)
#pragma unroll
            for (int r = 0; r < 4; r++) c[mi][ni][r] = 0.f;

    gemm_mainloop_h(X, Wt, smgh, cx, c);

#pragma unroll
    for (int mi = 0; mi < 4; mi++) {
        int r0 = cx.rowBase + cx.wm + mi * 16 + g;
        int r1 = r0 + 8;
        int b0 = r0 / SEQ_N, n0 = r0 - b0 * SEQ_N;
        int b1 = r1 / SEQ_N, n1 = r1 - b1 * SEQ_N;
#pragma unroll
        for (int ni = 0; ni < 4; ni++) {
            int col   = cx.colBase + cx.wn + ni * 8 + 2 * tg;
            int which = col >> 8;
            int h     = (col >> 5) & 7;
            int d0    = col & 31;
            size_t base0 = ((size_t)which * BH_TOT + b0 * HEADS + h) * HS + (size_t)n0 * DH + d0;
            size_t base1 = ((size_t)which * BH_TOT + b1 * HEADS + h) * HS + (size_t)n1 * DH + d0;
            // tf32-round so attention can cp.async raw bits
            *(float2*)&g_qkv[base0] = make_float2(f2tff(c[mi][ni][0]), f2tff(c[mi][ni][1]));
            *(float2*)&g_qkv[base1] = make_float2(f2tff(c[mi][ni][2]), f2tff(c[mi][ni][3]));
        }
    }
}

// GEMM 2: out = g_attnout(fp16) @ Wp^T-view + proj_b
__global__ __launch_bounds__(256, 2)
void gemm_proj_tc(const __half* __restrict__ Wt, const float* __restrict__ bias,
                  float* __restrict__ Out) {
    extern __shared__ __half smgh[];
    int tid = threadIdx.x;
    int lane = tid & 31, warp = tid >> 5;
    int g = lane >> 2, tg = lane & 3;
    GemmCtx cx;
    cx.wm = (warp >> 2) * 64; cx.wn = (warp & 3) * 32;
    cx.rowBase = blockIdx.y * 128; cx.colBase = blockIdx.x * 128;

    float c[4][4][4];
#pragma unroll
    for (int mi = 0; mi < 4; mi++)
#pragma unroll
        for (int ni = 0; ni < 4; ni++)
#pragma unroll
            for (int r = 0; r < 4; r++) c[mi][ni][r] = 0.f;

    gemm_mainloop_h(g_attnout, Wt, smgh, cx, c);

#pragma unroll
    for (int mi = 0; mi < 4; mi++) {
        int r0 = cx.rowBase + cx.wm + mi * 16 + g;
        int r1 = r0 + 8;
#pragma unroll
        for (int ni = 0; ni < 4; ni++) {
            int col = cx.colBase + cx.wn + ni * 8 + 2 * tg;
            float bx = bias[col], by = bias[col + 1];
            *(float2*)&Out[(size_t)r0 * 256 + col] =
                make_float2(c[mi][ni][0] + bx, c[mi][ni][1] + by);
            *(float2*)&Out[(size_t)r1 * 256 + col] =
                make_float2(c[mi][ni][2] + bx, c[mi][ni][3] + by);
        }
    }
}

// ---------------------------------------------------------------------------
// Attention v6 (unchanged internals, fp16 output stores):
// one block per (b,h), 256 threads = 8 warps, 16 rows each.
// smem words: k 112*36 | v 112*40 | P 112*116 = 21504 (86016 B) -> 2 CTAs/SM
// ---------------------------------------------------------------------------
#define LDK  36
#define LDVM 40
#define LDP  116
#define BOFF_V (112 * LDK)              // 4032
#define BOFF_P (BOFF_V + 112 * LDVM)    // 8512
#define ATTN_SMEM_BYTES ((BOFF_P + 112 * LDP) * 4)   // 86016

__global__ __launch_bounds__(256, 2)
void attn_tc() {
    extern __shared__ uint32_t sm[];
    uint32_t* sk = sm;
    uint32_t* sv = sm + BOFF_V;
    uint32_t* sP = sm + BOFF_P;

    int tid  = threadIdx.x;
    int bh   = blockIdx.x;
    int b = bh >> 3, h = bh & 7;
    const float* gq = g_qkv + (size_t)bh * HS;
    const float* gk = gq + QKV_ONE;
    const float* gv = gq + 2 * QKV_ONE;
    uint32_t skb = smem_u32(sk), svb = smem_u32(sv);
    uint32_t sPb = smem_u32(sP);

    // ---- async k [98][32] -> sk[n][d], v [98][32] -> sv[m][d] ----
    for (int i = tid; i < 784; i += 256) {
        int r = i >> 3, c4 = (i & 7) * 4;
        cpa16(skb + (r * LDK + c4) * 4, gk + r * 32 + c4);
    }
    for (int i = tid; i < 784; i += 256) {
        int m = i >> 3, d4 = (i & 7) * 4;
        cpa16(svb + (m * LDVM + d4) * 4, gv + m * 32 + d4);
    }
    asm volatile("cp.async.commit_group;");

    int lane = tid & 31, warp = tid >> 5;
    int g = lane >> 2, tg = lane & 3;
    int t8 = lane >> 3, r8 = lane & 7;
    int n0 = warp * 16 + g, n1 = n0 + 8;
    bool rv0 = (n0 < SEQ_N), rv1 = (n1 < SEQ_N);

    // ---- q A-fragments straight from gmem (overlaps cp.async) ----
    uint32_t aF[4][4];
#pragma unroll
    for (int kk = 0; kk < 4; kk++) {
        int c = kk * 8 + tg;
        aF[kk][0] = rv0 ? f2tf(gq[n0 * 32 + c] * SCALE) : 0u;
        aF[kk][1] = rv1 ? f2tf(gq[n1 * 32 + c] * SCALE) : 0u;
        aF[kk][2] = rv0 ? f2tf(gq[n0 * 32 + c + 4] * SCALE) : 0u;
        aF[kk][3] = rv1 ? f2tf(gq[n1 * 32 + c + 4] * SCALE) : 0u;
    }

    // ---- zero pads (rows 98..111) ----
    for (int i = tid; i < 448; i += 256) {
        int r = 98 + (i >> 5), d = i & 31;
        sk[r * LDK + d] = 0u;
    }
    for (int i = tid; i < 448; i += 256) {
        int m = 98 + (i >> 5), d = i & 31;
        sv[m * LDVM + d] = 0u;
    }
    asm volatile("cp.async.wait_group 0;");
    __syncthreads();

    // warp 7 covers rows 112..127 -> entirely invalid
    if (warp == 7) return;

    size_t bmbase = ((size_t)(b & (NW - 1)) * HEADS + h) * (SEQ_N * SEQ_N);
    const float* bmr0 = &g_bm[bmbase + (size_t)n0 * SEQ_N];
    const float* bmr1 = &g_bm[bmbase + (size_t)n1 * SEQ_N];

    // ldmatrix lane offsets (words)
    int laneS = r8 * LDK + t8 * 4;                         // k-frags
    int laneO = ((t8 & 1) * 8 + r8) * LDP + (t8 >> 1) * 4; // P A-frags

    // bm pair fetch helper: pair p covers ni = 2p, 2p+1
    auto bm_fetch = [&](int p, float2* A, float2* B) {
#pragma unroll
        for (int e = 0; e < 2; e++) {
            int c0 = (2 * p + e) * 8 + 2 * tg;
            bool cvj = (c0 < SEQ_N);
            float2 t0 = make_float2(0.f, 0.f), t1 = make_float2(0.f, 0.f);
            if (rv0 && cvj) t0 = *(const float2*)&bmr0[c0];
            if (rv1 && cvj) t1 = *(const float2*)&bmr1[c0];
            A[e] = t0; B[e] = t1;
        }
    };

    // ---- S phase: 7 pairs of ni, two interleaved mma chains per pair ----
    float sum0 = 0.f, sum1 = 0.f;
    float2 pA[2][2], pB[2][2];
    bm_fetch(0, pA[0], pB[0]);
#pragma unroll
    for (int p = 0; p < 7; p++) {
        int ni0 = 2 * p, ni1 = 2 * p + 1;
        uint32_t bF0[4][2], bF1[4][2];
        uint32_t sb0 = skb + (ni0 * 8 * LDK + laneS) * 4;
        uint32_t sb1 = skb + (ni1 * 8 * LDK + laneS) * 4;
        ldsm4(bF0[0][0], bF0[0][1], bF0[1][0], bF0[1][1], sb0);
        ldsm4(bF0[2][0], bF0[2][1], bF0[3][0], bF0[3][1], sb0 + 64);
        ldsm4(bF1[0][0], bF1[0][1], bF1[1][0], bF1[1][1], sb1);
        ldsm4(bF1[2][0], bF1[2][1], bF1[3][0], bF1[3][1], sb1 + 64);

        if (p < 6) bm_fetch(p + 1, pA[(p + 1) & 1], pB[(p + 1) & 1]);

        float acc0[4] = {0.f, 0.f, 0.f, 0.f};
        float acc1[4] = {0.f, 0.f, 0.f, 0.f};
#pragma unroll
        for (int kk = 0; kk < 4; kk++) {
            mma_tf32(acc0, aF[kk], bF0[kk]);
            mma_tf32(acc1, aF[kk], bF1[kk]);
        }

        float2* cA = pA[p & 1];
        float2* cB = pB[p & 1];
#pragma unroll
        for (int e = 0; e < 2; e++) {
            int ni = (e == 0) ? ni0 : ni1;
            float* acc = (e == 0) ? acc0 : acc1;
            int c0 = ni * 8 + 2 * tg;
            bool cv = (c0 < SEQ_N);
            float e00 = 0.f, e01 = 0.f, e10 = 0.f, e11 = 0.f;
            if (cv && rv0) {
                e00 = fastexp(acc[0] + cA[e].x);
                e01 = fastexp(acc[1] + cA[e].y);
            }
            if (cv && rv1) {
                e10 = fastexp(acc[2] + cB[e].x);
                e11 = fastexp(acc[3] + cB[e].y);
            }
            uint32_t u00 = f2tf(e00), u01 = f2tf(e01);
            uint32_t u10 = f2tf(e10), u11 = f2tf(e11);
            sum0 += __uint_as_float(u00) + __uint_as_float(u01);
            sum1 += __uint_as_float(u10) + __uint_as_float(u11);
            *(uint2*)&sP[n0 * LDP + c0] = make_uint2(u00, u01);
            *(uint2*)&sP[n1 * LDP + c0] = make_uint2(u10, u11);
        }
    }
    // rowsum across the 4-lane quad (result lands in all 4 lanes)
    sum0 += __shfl_xor_sync(0xffffffffu, sum0, 1);
    sum0 += __shfl_xor_sync(0xffffffffu, sum0, 2);
    sum1 += __shfl_xor_sync(0xffffffffu, sum1, 1);
    sum1 += __shfl_xor_sync(0xffffffffu, sum1, 2);
    float inv0 = rv0 ? (1.0f / sum0) : 0.f;
    float inv1 = rv1 ? (1.0f / sum1) : 0.f;

    // sP is warp-private (rows 16*warp..16*warp+15): warp-level sync suffices
    __syncwarp();

    // ---- O phase: O = P . v, v-frags pipelined one kk ahead ----
    float oacc[4][4];
#pragma unroll
    for (int ni = 0; ni < 4; ni++)
#pragma unroll
        for (int r = 0; r < 4; r++) oacc[ni][r] = 0.f;

    uint32_t pbase = sPb + (warp * 16 * LDP + laneO) * 4;

    auto v_fetch = [&](int kk, uint32_t bO[4][2]) {
#pragma unroll
        for (int ni = 0; ni < 4; ni++) {
            int vr = ni * 8 + g;
            bO[ni][0] = sv[(kk * 8 + tg) * LDVM + vr];
            bO[ni][1] = sv[(kk * 8 + tg + 4) * LDVM + vr];
        }
    };

    uint32_t bOv[2][4][2];
    v_fetch(0, bOv[0]);
#pragma unroll
    for (int kk = 0; kk < 14; kk++) {
        uint32_t aO[4];
        ldsm4(aO[0], aO[1], aO[2], aO[3], pbase + kk * 32);
        if (kk < 13) v_fetch(kk + 1, bOv[(kk + 1) & 1]);
#pragma unroll
        for (int ni = 0; ni < 4; ni++)
            mma_tf32(oacc[ni], aO, bOv[kk & 1][ni]);
    }

    // fp16 stores: proj GEMM consumes g_attnout as its fp16 A operand
    if (rv0) {
        size_t ob = ((size_t)b * SEQ_N + n0) * CH + h * DH;
#pragma unroll
        for (int ni = 0; ni < 4; ni++) {
            int d0 = ni * 8 + 2 * tg;
            *(__half2*)&g_attnout[ob + d0] =
                __floats2half2_rn(oacc[ni][0] * inv0, oacc[ni][1] * inv0);
        }
    }
    if (rv1) {
        size_t ob = ((size_t)b * SEQ_N + n1) * CH + h * DH;
#pragma unroll
        for (int ni = 0; ni < 4; ni++) {
            int d0 = ni * 8 + 2 * tg;
            *(__half2*)&g_attnout[ob + d0] =
                __floats2half2_rn(oacc[ni][2] * inv1, oacc[ni][3] * inv1);
        }
    }
}

// ---------------------------------------------------------------------------
// Launch
// ---------------------------------------------------------------------------
extern "C" void kernel_launch(void* const* d_in, const int* in_sizes, int n_in,
                              void* d_out, int out_size) {
    const float* x       = (const float*)d_in[0];
    const float* mask    = (const float*)d_in[1];
    const float* qkv_w   = (const float*)d_in[2];
    const float* proj_w  = (const float*)d_in[3];
    const float* proj_b  = (const float*)d_in[4];
    const float* table   = (const float*)d_in[5];
    float* out           = (float*)d_out;

    static bool attr_done = false;
    if (!attr_done) {
        cudaFuncSetAttribute(attn_tc, cudaFuncAttributeMaxDynamicSharedMemorySize,
                             ATTN_SMEM_BYTES);
        cudaFuncSetAttribute(gemm_qkv_tc, cudaFuncAttributeMaxDynamicSharedMemorySize,
                             GEMM_SMEM_BYTES);
        cudaFuncSetAttribute(gemm_proj_tc, cudaFuncAttributeMaxDynamicSharedMemorySize,
                             GEMM_SMEM_BYTES);
        attr_done = true;
    }

    __half* xh = nullptr; __half* wq = nullptr; __half* wp = nullptr;
    cudaGetSymbolAddress((void**)&xh, g_xh);
    cudaGetSymbolAddress((void**)&wq, g_wq);
    cudaGetSymbolAddress((void**)&wp, g_wp);

    // 0a) X -> fp16; weights round+transpose -> fp16 [N][K]
    {
        int n4x = M_TOT * CH / 4;
        f2h4<<<(n4x + 255) / 256, 256>>>((const float4*)x, (__half2*)xh, n4x);
        int nq = CH * 3 * CH;
        round_transpose_h<<<(nq + 255) / 256, 256>>>(qkv_w, wq, CH, 3 * CH);
        int np = CH * CH;
        round_transpose_h<<<(np + 255) / 256, 256>>>(proj_w, wp, CH, CH);
    }
    // 0b) bias+mask precompute
    {
        int tot = NW * HEADS * SEQ_N * SEQ_N;
        bm_kernel<<<(tot + 255) / 256, 256>>>(mask, table);
    }
    // 1) qkv GEMM (fp16 m16n8k16 + ldmatrix + cp.async)
    gemm_qkv_tc<<<dim3(768 / 128, M_TOT / 128), 256, GEMM_SMEM_BYTES>>>(xh, wq);
    // 2) attention: one block per (b,h)
    attn_tc<<<BH_TOT, 256, ATTN_SMEM_BYTES>>>();
    // 3) proj GEMM + bias (fp16 m16n8k16 + ldmatrix + cp.async)
    gemm_proj_tc<<<dim3(256 / 128, M_TOT / 128), 256, GEMM_SMEM_BYTES>>>(wp, proj_b, out);
}